// round 1
// baseline (speedup 1.0000x reference)
#include <cuda_runtime.h>
#include <cuda_bf16.h>
#include <math.h>

// Problem constants
#define B 8
#define C 512
#define L 4096
#define HEADS 8
#define DHEAD 64
#define HIDDEN 512           // HEADS*DHEAD
#define QKV_CH 1536          // 3*HIDDEN
#define SQRT_C 22.627416998f // sqrt(512)
#define ATTN_SCALE 0.125f    // 64^-0.5

// Scratch buffers (static device allocations; no cudaMalloc allowed)
__device__ float g_xn[(size_t)B * C * L];        // 64 MB
__device__ float g_qkv[(size_t)B * QKV_CH * L];  // 192 MB
__device__ float g_ctx[(size_t)B * HEADS * DHEAD * DHEAD];
__device__ float g_attn[(size_t)B * HIDDEN * L]; // 64 MB
__device__ float g_o[(size_t)B * C * L];         // 64 MB

// ---------------------------------------------------------------------------
// Kernel 1: channel RMSNorm  (x[b,c,l] -> xn = x/||x||_c * g[c] * sqrt(C))
// one thread per (b,l) column; strided loop over c is coalesced across threads
// ---------------------------------------------------------------------------
__global__ void rmsnorm_ch_kernel(const float* __restrict__ x,
                                  const float* __restrict__ g,
                                  float* __restrict__ out) {
    size_t idx = (size_t)blockIdx.x * blockDim.x + threadIdx.x; // over B*L
    int b = (int)(idx >> 12);
    int l = (int)(idx & (L - 1));
    const float* xp = x + ((size_t)b * C) * L + l;
    float ss = 0.f;
#pragma unroll 8
    for (int c = 0; c < C; c++) {
        float v = xp[(size_t)c * L];
        ss += v * v;
    }
    float n = fmaxf(sqrtf(ss), 1e-12f);
    float scale = SQRT_C / n;
    float* op = out + ((size_t)b * C) * L + l;
#pragma unroll 8
    for (int c = 0; c < C; c++) {
        op[(size_t)c * L] = xp[(size_t)c * L] * scale * g[c];
    }
}

// ---------------------------------------------------------------------------
// Kernel 7: final RMSNorm + residual
// ---------------------------------------------------------------------------
__global__ void rmsnorm_res_kernel(const float* __restrict__ o,
                                   const float* __restrict__ g,
                                   const float* __restrict__ x,
                                   float* __restrict__ out) {
    size_t idx = (size_t)blockIdx.x * blockDim.x + threadIdx.x;
    int b = (int)(idx >> 12);
    int l = (int)(idx & (L - 1));
    size_t base = ((size_t)b * C) * L + l;
    const float* op = o + base;
    float ss = 0.f;
#pragma unroll 8
    for (int c = 0; c < C; c++) {
        float v = op[(size_t)c * L];
        ss += v * v;
    }
    float n = fmaxf(sqrtf(ss), 1e-12f);
    float scale = SQRT_C / n;
    const float* xp = x + base;
    float* dp = out + base;
#pragma unroll 8
    for (int c = 0; c < C; c++) {
        dp[(size_t)c * L] = op[(size_t)c * L] * scale * g[c] + xp[(size_t)c * L];
    }
}

// ---------------------------------------------------------------------------
// Batched SGEMM: C[bz] = A @ B[bz] (+ bias), row-major.
// A is shared across batch [M,K]; B[bz] = Bbase + bz*strideB, [K,N];
// C[bz] = Cbase + bz*strideC, [M,N]. M%128==0, N%128==0, K%8==0.
// 128x128 block tile, 8x8 per thread, 256 threads, BK=8.
// ---------------------------------------------------------------------------
__global__ __launch_bounds__(256) void sgemm128(
    const float* __restrict__ A, const float* __restrict__ Bb,
    float* __restrict__ Cb, const float* __restrict__ bias,
    int M, int N, int K, size_t strideB, size_t strideC) {
    const int BM = 128, BN = 128, BK = 8;
    __shared__ float As[BK][BM];
    __shared__ float Bs[BK][BN];

    int tid = threadIdx.x;
    const float* Ap = A + (size_t)blockIdx.y * BM * K;
    const float* Bp = Bb + (size_t)blockIdx.z * strideB + (size_t)blockIdx.x * BN;
    float* Cp = Cb + (size_t)blockIdx.z * strideC +
                (size_t)blockIdx.y * BM * N + (size_t)blockIdx.x * BN;

    // A loads: 128 rows x 8 cols = 1024 floats = 256 x float4
    int aRow = tid >> 1;
    int aCol = (tid & 1) * 4;
    // B loads: 8 rows x 128 cols
    int bRow = tid >> 5;
    int bCol = (tid & 31) * 4;

    int trow = (tid >> 4) * 8;
    int tcol = (tid & 15) * 8;

    float acc[8][8];
#pragma unroll
    for (int i = 0; i < 8; i++)
#pragma unroll
        for (int j = 0; j < 8; j++) acc[i][j] = 0.f;

    for (int k0 = 0; k0 < K; k0 += BK) {
        float4 a4 = *reinterpret_cast<const float4*>(Ap + (size_t)aRow * K + k0 + aCol);
        As[aCol + 0][aRow] = a4.x;
        As[aCol + 1][aRow] = a4.y;
        As[aCol + 2][aRow] = a4.z;
        As[aCol + 3][aRow] = a4.w;
        float4 b4 = *reinterpret_cast<const float4*>(Bp + (size_t)(k0 + bRow) * N + bCol);
        *reinterpret_cast<float4*>(&Bs[bRow][bCol]) = b4;
        __syncthreads();

#pragma unroll
        for (int kk = 0; kk < BK; kk++) {
            float4 ra0 = *reinterpret_cast<float4*>(&As[kk][trow]);
            float4 ra1 = *reinterpret_cast<float4*>(&As[kk][trow + 4]);
            float4 rb0 = *reinterpret_cast<float4*>(&Bs[kk][tcol]);
            float4 rb1 = *reinterpret_cast<float4*>(&Bs[kk][tcol + 4]);
            float ra[8] = {ra0.x, ra0.y, ra0.z, ra0.w, ra1.x, ra1.y, ra1.z, ra1.w};
            float rb[8] = {rb0.x, rb0.y, rb0.z, rb0.w, rb1.x, rb1.y, rb1.z, rb1.w};
#pragma unroll
            for (int i = 0; i < 8; i++)
#pragma unroll
                for (int j = 0; j < 8; j++) acc[i][j] = fmaf(ra[i], rb[j], acc[i][j]);
        }
        __syncthreads();
    }

#pragma unroll
    for (int i = 0; i < 8; i++) {
        int row = trow + i;
        float bv = bias ? bias[blockIdx.y * BM + row] : 0.f;
#pragma unroll
        for (int j = 0; j < 8; j += 4) {
            float4 r;
            r.x = acc[i][j + 0] + bv;
            r.y = acc[i][j + 1] + bv;
            r.z = acc[i][j + 2] + bv;
            r.w = acc[i][j + 3] + bv;
            *reinterpret_cast<float4*>(&Cp[(size_t)row * N + tcol + j]) = r;
        }
    }
}

// ---------------------------------------------------------------------------
// Kernel 3: softmax over L for the k channels (qkv channels [512, 1024)),
// in place. One block per (b, channel) row of 4096.
// ---------------------------------------------------------------------------
__global__ void ksoftmax_kernel(float* __restrict__ qkv) {
    int row = blockIdx.x;           // 0..B*HIDDEN-1
    int b = row >> 9;
    int ch = row & (HIDDEN - 1);
    float* p = qkv + ((size_t)b * QKV_CH + HIDDEN + ch) * L;
    int tid = threadIdx.x;          // 256 threads, 16 elems each
    float v[16];
    float m = -INFINITY;
#pragma unroll
    for (int i = 0; i < 16; i++) {
        v[i] = p[tid + i * 256];
        m = fmaxf(m, v[i]);
    }
    __shared__ float red[256];
    red[tid] = m;
    __syncthreads();
    for (int s = 128; s > 0; s >>= 1) {
        if (tid < s) red[tid] = fmaxf(red[tid], red[tid + s]);
        __syncthreads();
    }
    m = red[0];
    __syncthreads();
    float sum = 0.f;
#pragma unroll
    for (int i = 0; i < 16; i++) {
        v[i] = expf(v[i] - m);
        sum += v[i];
    }
    red[tid] = sum;
    __syncthreads();
    for (int s = 128; s > 0; s >>= 1) {
        if (tid < s) red[tid] += red[tid + s];
        __syncthreads();
    }
    float inv = 1.f / red[0];
#pragma unroll
    for (int i = 0; i < 16; i++) p[tid + i * 256] = v[i] * inv;
}

// ---------------------------------------------------------------------------
// Kernel 4: context[b,h,d,e] = sum_n k[d,n] * v[e,n].  One block per (b,h).
// 256 threads, 4x4 per thread, n-chunks of 64 staged through smem.
// ---------------------------------------------------------------------------
__global__ __launch_bounds__(256) void ctx_kernel(const float* __restrict__ qkv,
                                                  float* __restrict__ ctx) {
    int bh = blockIdx.x;
    int b = bh >> 3, h = bh & 7;
    const float* kp = qkv + ((size_t)b * QKV_CH + HIDDEN + h * DHEAD) * L;
    const float* vp = qkv + ((size_t)b * QKV_CH + 2 * HIDDEN + h * DHEAD) * L;
    __shared__ float ks[64][65];
    __shared__ float vs[64][65];
    int tid = threadIdx.x;
    int d0 = (tid >> 4) * 4;
    int e0 = (tid & 15) * 4;
    float acc[4][4];
#pragma unroll
    for (int i = 0; i < 4; i++)
#pragma unroll
        for (int j = 0; j < 4; j++) acc[i][j] = 0.f;

    for (int n0 = 0; n0 < L; n0 += 64) {
        for (int idx = tid; idx < 64 * 64; idx += 256) {
            int r = idx >> 6, c2 = idx & 63;
            ks[r][c2] = kp[(size_t)r * L + n0 + c2];
            vs[r][c2] = vp[(size_t)r * L + n0 + c2];
        }
        __syncthreads();
#pragma unroll 4
        for (int nn = 0; nn < 64; nn++) {
            float rk[4], rv[4];
#pragma unroll
            for (int i = 0; i < 4; i++) rk[i] = ks[d0 + i][nn];
#pragma unroll
            for (int j = 0; j < 4; j++) rv[j] = vs[e0 + j][nn];
#pragma unroll
            for (int i = 0; i < 4; i++)
#pragma unroll
                for (int j = 0; j < 4; j++) acc[i][j] = fmaf(rk[i], rv[j], acc[i][j]);
        }
        __syncthreads();
    }
    float* cp = ctx + (size_t)bh * DHEAD * DHEAD;
#pragma unroll
    for (int i = 0; i < 4; i++)
#pragma unroll
        for (int j = 0; j < 4; j++) cp[(d0 + i) * DHEAD + e0 + j] = acc[i][j];
}

// ---------------------------------------------------------------------------
// Kernel 5: q-softmax (over d) fused with out[e,n] = sum_d ctx[d,e]*qs[d,n].
// One thread per n. ctx tile in smem (broadcast reads, float4).
// q is re-read 3x from global (L2-hot) to keep 64 fp32 accumulators in regs.
// ---------------------------------------------------------------------------
__global__ __launch_bounds__(128) void attn_apply_kernel(const float* __restrict__ qkv,
                                                         const float* __restrict__ ctx,
                                                         float* __restrict__ attn) {
    int n = blockIdx.x * 128 + threadIdx.x;
    int bh = blockIdx.y;
    int b = bh >> 3, h = bh & 7;

    __shared__ float4 cs[64][16];
    const float4* cp4 = reinterpret_cast<const float4*>(ctx + (size_t)bh * DHEAD * DHEAD);
    for (int idx = threadIdx.x; idx < 64 * 16; idx += 128)
        cs[idx >> 4][idx & 15] = cp4[idx];
    __syncthreads();

    const float* qp = qkv + ((size_t)b * QKV_CH + h * DHEAD) * L + n;
    float m = -INFINITY;
#pragma unroll 8
    for (int d = 0; d < DHEAD; d++) m = fmaxf(m, qp[(size_t)d * L]);
    float sum = 0.f;
#pragma unroll 8
    for (int d = 0; d < DHEAD; d++) sum += expf(qp[(size_t)d * L] - m);
    float inv = ATTN_SCALE / sum;

    float4 acc[16];
#pragma unroll
    for (int e = 0; e < 16; e++) acc[e] = make_float4(0.f, 0.f, 0.f, 0.f);

#pragma unroll 4
    for (int d = 0; d < DHEAD; d++) {
        float qs = expf(qp[(size_t)d * L] - m) * inv;
#pragma unroll
        for (int e = 0; e < 16; e++) {
            float4 c4 = cs[d][e];
            acc[e].x = fmaf(c4.x, qs, acc[e].x);
            acc[e].y = fmaf(c4.y, qs, acc[e].y);
            acc[e].z = fmaf(c4.z, qs, acc[e].z);
            acc[e].w = fmaf(c4.w, qs, acc[e].w);
        }
    }

    float* op = attn + ((size_t)b * HIDDEN + h * DHEAD) * L + n;
#pragma unroll
    for (int e = 0; e < 16; e++) {
        op[(size_t)(e * 4 + 0) * L] = acc[e].x;
        op[(size_t)(e * 4 + 1) * L] = acc[e].y;
        op[(size_t)(e * 4 + 2) * L] = acc[e].z;
        op[(size_t)(e * 4 + 3) * L] = acc[e].w;
    }
}

// ---------------------------------------------------------------------------
extern "C" void kernel_launch(void* const* d_in, const int* in_sizes, int n_in,
                              void* d_out, int out_size) {
    const float* x     = (const float*)d_in[0];
    const float* g_in  = (const float*)d_in[1];
    const float* w_qkv = (const float*)d_in[2];
    const float* w_out = (const float*)d_in[3];
    const float* b_out = (const float*)d_in[4];
    const float* g_out = (const float*)d_in[5];
    float* out = (float*)d_out;

    float *xn, *qkv, *ctx, *attn, *o;
    cudaGetSymbolAddress((void**)&xn, g_xn);
    cudaGetSymbolAddress((void**)&qkv, g_qkv);
    cudaGetSymbolAddress((void**)&ctx, g_ctx);
    cudaGetSymbolAddress((void**)&attn, g_attn);
    cudaGetSymbolAddress((void**)&o, g_o);

    // 1. RMSNorm(x) -> xn
    rmsnorm_ch_kernel<<<(B * L) / 256, 256>>>(x, g_in, xn);

    // 2. qkv = w_qkv @ xn   [1536,512]x[512,4096] x8
    sgemm128<<<dim3(L / 128, QKV_CH / 128, B), 256>>>(
        w_qkv, xn, qkv, nullptr, QKV_CH, L, C,
        (size_t)C * L, (size_t)QKV_CH * L);

    // 3. k softmax over L (in place)
    ksoftmax_kernel<<<B * HIDDEN, 256>>>(qkv);

    // 4. context = k @ v^T per (b,h)
    ctx_kernel<<<B * HEADS, 256>>>(qkv, ctx);

    // 5. attn = ctx^T @ softmax_d(q)*scale
    attn_apply_kernel<<<dim3(L / 128, B * HEADS), 128>>>(qkv, ctx, attn);

    // 6. o = w_out @ attn + b_out   [512,512]x[512,4096] x8
    sgemm128<<<dim3(L / 128, C / 128, B), 256>>>(
        w_out, attn, o, b_out, C, L, HIDDEN,
        (size_t)HIDDEN * L, (size_t)C * L);

    // 7. RMSNorm(o) + residual -> out
    rmsnorm_res_kernel<<<(B * L) / 256, 256>>>(o, g_out, x, out);
}

// round 2
// speedup vs baseline: 2.2674x; 2.2674x over previous
#include <cuda_runtime.h>
#include <cuda_bf16.h>
#include <math.h>
#include <stdint.h>

// Problem constants
#define B 8
#define C 512
#define L 4096
#define HEADS 8
#define DHEAD 64
#define HIDDEN 512           // HEADS*DHEAD
#define QKV_CH 1536          // 3*HIDDEN
#define SQRT_C 22.627416998f // sqrt(512)
#define ATTN_SCALE 0.125f    // 64^-0.5
#define NCHUNK 16            // ctx split factor over L

// Scratch buffers (static device allocations; no cudaMalloc allowed)
__device__ float g_xn[(size_t)B * C * L];        // 64 MB
__device__ float g_qkv[(size_t)B * QKV_CH * L];  // 192 MB
__device__ float g_ctxp[(size_t)NCHUNK * B * HEADS * DHEAD * DHEAD]; // 16 MB
__device__ float g_ctx[(size_t)B * HEADS * DHEAD * DHEAD];           // 1 MB
__device__ float g_attn[(size_t)B * HIDDEN * L]; // 64 MB
__device__ float g_o[(size_t)B * C * L];         // 64 MB

// ---------------------------------------------------------------------------
// tf32 helpers
// ---------------------------------------------------------------------------
__device__ __forceinline__ uint32_t f2tf32(float x) {
    uint32_t r;
    asm("cvt.rna.tf32.f32 %0, %1;" : "=r"(r) : "f"(x));
    return r;
}

__device__ __forceinline__ void mma_tf32(float d[4], const uint32_t a[4],
                                         const uint32_t b[2]) {
    asm volatile(
        "mma.sync.aligned.m16n8k8.row.col.f32.tf32.tf32.f32 "
        "{%0,%1,%2,%3}, {%4,%5,%6,%7}, {%8,%9}, {%0,%1,%2,%3};"
        : "+f"(d[0]), "+f"(d[1]), "+f"(d[2]), "+f"(d[3])
        : "r"(a[0]), "r"(a[1]), "r"(a[2]), "r"(a[3]),
          "r"(b[0]), "r"(b[1]));
}

// ---------------------------------------------------------------------------
// Kernel 1: channel RMSNorm  (x[b,c,l] -> xn = x/||x||_c * g[c] * sqrt(C))
// ---------------------------------------------------------------------------
__global__ void rmsnorm_ch_kernel(const float* __restrict__ x,
                                  const float* __restrict__ g,
                                  float* __restrict__ out) {
    size_t idx = (size_t)blockIdx.x * blockDim.x + threadIdx.x; // over B*L
    int b = (int)(idx >> 12);
    int l = (int)(idx & (L - 1));
    const float* xp = x + ((size_t)b * C) * L + l;
    float ss = 0.f;
#pragma unroll 8
    for (int c = 0; c < C; c++) {
        float v = xp[(size_t)c * L];
        ss += v * v;
    }
    float n = fmaxf(sqrtf(ss), 1e-12f);
    float scale = SQRT_C / n;
    float* op = out + ((size_t)b * C) * L + l;
#pragma unroll 8
    for (int c = 0; c < C; c++) {
        op[(size_t)c * L] = xp[(size_t)c * L] * scale * g[c];
    }
}

// ---------------------------------------------------------------------------
// Kernel 7: final RMSNorm + residual
// ---------------------------------------------------------------------------
__global__ void rmsnorm_res_kernel(const float* __restrict__ o,
                                   const float* __restrict__ g,
                                   const float* __restrict__ x,
                                   float* __restrict__ out) {
    size_t idx = (size_t)blockIdx.x * blockDim.x + threadIdx.x;
    int b = (int)(idx >> 12);
    int l = (int)(idx & (L - 1));
    size_t base = ((size_t)b * C) * L + l;
    const float* op = o + base;
    float ss = 0.f;
#pragma unroll 8
    for (int c = 0; c < C; c++) {
        float v = op[(size_t)c * L];
        ss += v * v;
    }
    float n = fmaxf(sqrtf(ss), 1e-12f);
    float scale = SQRT_C / n;
    const float* xp = x + base;
    float* dp = out + base;
#pragma unroll 8
    for (int c = 0; c < C; c++) {
        dp[(size_t)c * L] = op[(size_t)c * L] * scale * g[c] + xp[(size_t)c * L];
    }
}

// ---------------------------------------------------------------------------
// Batched tf32 tensor-core GEMM: Cmat[bz] = A @ Bmat[bz] (+bias), row-major.
// A [M,K] shared across batch; Bmat[bz] = Bb + bz*strideB, [K,N];
// Cmat[bz] = Cb + bz*strideC, [M,N]. M%128==0, N%128==0, K%16==0.
// 128x128x16 block tile, 8 warps (2x4), 64x32 warp tile, m16n8k8 tf32 mma.
// Double-buffered smem; conversion to tf32 (cvt.rna) at smem-fill time.
// smem stride 136 -> conflict-free fragment LDS.
// ---------------------------------------------------------------------------
#define LDSS 136
__global__ __launch_bounds__(256) void sgemm_tf32(
    const float* __restrict__ A, const float* __restrict__ Bb,
    float* __restrict__ Cb, const float* __restrict__ bias,
    int M, int N, int K, size_t strideB, size_t strideC) {
    __shared__ uint32_t As[2][16 * LDSS];
    __shared__ uint32_t Bs[2][16 * LDSS];

    const int tid = threadIdx.x;
    const int lane = tid & 31;
    const int warp = tid >> 5;
    const int gid = lane >> 2;   // 0..7
    const int t4 = lane & 3;     // 0..3
    const int wm = warp >> 2;    // 0..1
    const int wn = warp & 3;     // 0..3

    const float* Ap = A + (size_t)blockIdx.y * 128 * K;
    const float* Bp = Bb + (size_t)blockIdx.z * strideB + (size_t)blockIdx.x * 128;
    float* Cp = Cb + (size_t)blockIdx.z * strideC +
                (size_t)blockIdx.y * 128 * N + (size_t)blockIdx.x * 128;

    // A staging: row = tid>>1 (0..127), half = tid&1 -> k cols half*8..half*8+7
    const int aRow = tid >> 1;
    const int aH = (tid & 1) * 8;
    // B staging: k rows tid>>5 and (tid>>5)+8, 4 cols at (tid&31)*4
    const int bK = tid >> 5;
    const int bC4 = (tid & 31) * 4;

    float4 ar0, ar1, br0, br1;

    float acc[4][4][4];
#pragma unroll
    for (int mi = 0; mi < 4; mi++)
#pragma unroll
        for (int ni = 0; ni < 4; ni++)
#pragma unroll
            for (int r = 0; r < 4; r++) acc[mi][ni][r] = 0.f;

    // prologue: load + store stage 0
    {
        const float* p = Ap + (size_t)aRow * K + aH;
        ar0 = *(const float4*)p;
        ar1 = *(const float4*)(p + 4);
        br0 = *(const float4*)(Bp + (size_t)bK * N + bC4);
        br1 = *(const float4*)(Bp + (size_t)(bK + 8) * N + bC4);
#pragma unroll
        for (int j = 0; j < 4; j++) {
            As[0][(aH + j) * LDSS + aRow] = f2tf32(((float*)&ar0)[j]);
            As[0][(aH + 4 + j) * LDSS + aRow] = f2tf32(((float*)&ar1)[j]);
            Bs[0][bK * LDSS + bC4 + j] = f2tf32(((float*)&br0)[j]);
            Bs[0][(bK + 8) * LDSS + bC4 + j] = f2tf32(((float*)&br1)[j]);
        }
    }
    __syncthreads();

    const int nstage = K >> 4;
    int buf = 0;
    for (int s = 0; s < nstage; s++) {
        const bool more = (s + 1 < nstage);
        if (more) {
            int k0 = (s + 1) << 4;
            const float* p = Ap + (size_t)aRow * K + k0 + aH;
            ar0 = *(const float4*)p;
            ar1 = *(const float4*)(p + 4);
            br0 = *(const float4*)(Bp + (size_t)(k0 + bK) * N + bC4);
            br1 = *(const float4*)(Bp + (size_t)(k0 + bK + 8) * N + bC4);
        }

        const uint32_t* Ab = As[buf];
        const uint32_t* Bbuf = Bs[buf];
#pragma unroll
        for (int kk = 0; kk < 2; kk++) {
            const int kb = kk * 8;
            uint32_t af[4][4], bf[4][2];
#pragma unroll
            for (int mi = 0; mi < 4; mi++) {
                const int m0 = wm * 64 + mi * 16;
                af[mi][0] = Ab[(kb + t4) * LDSS + m0 + gid];
                af[mi][1] = Ab[(kb + t4) * LDSS + m0 + gid + 8];
                af[mi][2] = Ab[(kb + t4 + 4) * LDSS + m0 + gid];
                af[mi][3] = Ab[(kb + t4 + 4) * LDSS + m0 + gid + 8];
            }
#pragma unroll
            for (int ni = 0; ni < 4; ni++) {
                const int n0 = wn * 32 + ni * 8;
                bf[ni][0] = Bbuf[(kb + t4) * LDSS + n0 + gid];
                bf[ni][1] = Bbuf[(kb + t4 + 4) * LDSS + n0 + gid];
            }
#pragma unroll
            for (int mi = 0; mi < 4; mi++)
#pragma unroll
                for (int ni = 0; ni < 4; ni++)
                    mma_tf32(acc[mi][ni], af[mi], bf[ni]);
        }

        if (more) {
            int nb = buf ^ 1;
#pragma unroll
            for (int j = 0; j < 4; j++) {
                As[nb][(aH + j) * LDSS + aRow] = f2tf32(((float*)&ar0)[j]);
                As[nb][(aH + 4 + j) * LDSS + aRow] = f2tf32(((float*)&ar1)[j]);
                Bs[nb][bK * LDSS + bC4 + j] = f2tf32(((float*)&br0)[j]);
                Bs[nb][(bK + 8) * LDSS + bC4 + j] = f2tf32(((float*)&br1)[j]);
            }
        }
        __syncthreads();
        buf ^= 1;
    }

    // epilogue
#pragma unroll
    for (int mi = 0; mi < 4; mi++) {
        const int r0 = wm * 64 + mi * 16 + gid;
        const float bv0 = bias ? bias[blockIdx.y * 128 + r0] : 0.f;
        const float bv1 = bias ? bias[blockIdx.y * 128 + r0 + 8] : 0.f;
#pragma unroll
        for (int ni = 0; ni < 4; ni++) {
            const int col = wn * 32 + ni * 8 + t4 * 2;
            float2 v0 = make_float2(acc[mi][ni][0] + bv0, acc[mi][ni][1] + bv0);
            float2 v1 = make_float2(acc[mi][ni][2] + bv1, acc[mi][ni][3] + bv1);
            *(float2*)&Cp[(size_t)r0 * N + col] = v0;
            *(float2*)&Cp[(size_t)(r0 + 8) * N + col] = v1;
        }
    }
}

// ---------------------------------------------------------------------------
// Kernel 3: softmax over L for the k channels (qkv channels [512, 1024)),
// in place. One block per (b, channel) row of 4096.
// ---------------------------------------------------------------------------
__global__ void ksoftmax_kernel(float* __restrict__ qkv) {
    int row = blockIdx.x;           // 0..B*HIDDEN-1
    int b = row >> 9;
    int ch = row & (HIDDEN - 1);
    float* p = qkv + ((size_t)b * QKV_CH + HIDDEN + ch) * L;
    int tid = threadIdx.x;          // 256 threads, 16 elems each
    float v[16];
    float m = -INFINITY;
#pragma unroll
    for (int i = 0; i < 16; i++) {
        v[i] = p[tid + i * 256];
        m = fmaxf(m, v[i]);
    }
    __shared__ float red[256];
    red[tid] = m;
    __syncthreads();
    for (int s = 128; s > 0; s >>= 1) {
        if (tid < s) red[tid] = fmaxf(red[tid], red[tid + s]);
        __syncthreads();
    }
    m = red[0];
    __syncthreads();
    float sum = 0.f;
#pragma unroll
    for (int i = 0; i < 16; i++) {
        v[i] = expf(v[i] - m);
        sum += v[i];
    }
    red[tid] = sum;
    __syncthreads();
    for (int s = 128; s > 0; s >>= 1) {
        if (tid < s) red[tid] += red[tid + s];
        __syncthreads();
    }
    float inv = 1.f / red[0];
#pragma unroll
    for (int i = 0; i < 16; i++) p[tid + i * 256] = v[i] * inv;
}

// ---------------------------------------------------------------------------
// Kernel 4a: partial context over an L-chunk.
// grid = (B*HEADS, NCHUNK). Each block handles L/NCHUNK = 256 columns.
// ---------------------------------------------------------------------------
__global__ __launch_bounds__(256) void ctx_part_kernel(const float* __restrict__ qkv,
                                                       float* __restrict__ ctxp) {
    int bh = blockIdx.x;
    int chunk = blockIdx.y;
    int b = bh >> 3, h = bh & 7;
    const float* kp = qkv + ((size_t)b * QKV_CH + HIDDEN + h * DHEAD) * L;
    const float* vp = qkv + ((size_t)b * QKV_CH + 2 * HIDDEN + h * DHEAD) * L;
    __shared__ float ks[64][65];
    __shared__ float vs[64][65];
    int tid = threadIdx.x;
    int d0 = (tid >> 4) * 4;
    int e0 = (tid & 15) * 4;
    float acc[4][4];
#pragma unroll
    for (int i = 0; i < 4; i++)
#pragma unroll
        for (int j = 0; j < 4; j++) acc[i][j] = 0.f;

    int nbeg = chunk * (L / NCHUNK);
    int nend = nbeg + (L / NCHUNK);
    for (int n0 = nbeg; n0 < nend; n0 += 64) {
        for (int idx = tid; idx < 64 * 64; idx += 256) {
            int r = idx >> 6, c2 = idx & 63;
            ks[r][c2] = kp[(size_t)r * L + n0 + c2];
            vs[r][c2] = vp[(size_t)r * L + n0 + c2];
        }
        __syncthreads();
#pragma unroll 4
        for (int nn = 0; nn < 64; nn++) {
            float rk[4], rv[4];
#pragma unroll
            for (int i = 0; i < 4; i++) rk[i] = ks[d0 + i][nn];
#pragma unroll
            for (int j = 0; j < 4; j++) rv[j] = vs[e0 + j][nn];
#pragma unroll
            for (int i = 0; i < 4; i++)
#pragma unroll
                for (int j = 0; j < 4; j++) acc[i][j] = fmaf(rk[i], rv[j], acc[i][j]);
        }
        __syncthreads();
    }
    float* cp = ctxp + ((size_t)chunk * (B * HEADS) + bh) * (DHEAD * DHEAD);
#pragma unroll
    for (int i = 0; i < 4; i++)
#pragma unroll
        for (int j = 0; j < 4; j++) cp[(d0 + i) * DHEAD + e0 + j] = acc[i][j];
}

// ---------------------------------------------------------------------------
// Kernel 4b: reduce NCHUNK partial contexts -> ctx
// ---------------------------------------------------------------------------
__global__ void ctx_reduce_kernel(const float* __restrict__ ctxp,
                                  float* __restrict__ ctx) {
    int i = blockIdx.x * 256 + threadIdx.x; // over B*HEADS*DHEAD*DHEAD
    float s = 0.f;
#pragma unroll
    for (int c = 0; c < NCHUNK; c++)
        s += ctxp[(size_t)c * (B * HEADS * DHEAD * DHEAD) + i];
    ctx[i] = s;
}

// ---------------------------------------------------------------------------
// Kernel 5: q-softmax (over d) fused with out[e,n] = sum_d ctx[d,e]*qs[d,n].
// ---------------------------------------------------------------------------
__global__ __launch_bounds__(128) void attn_apply_kernel(const float* __restrict__ qkv,
                                                         const float* __restrict__ ctx,
                                                         float* __restrict__ attn) {
    int n = blockIdx.x * 128 + threadIdx.x;
    int bh = blockIdx.y;
    int b = bh >> 3, h = bh & 7;

    __shared__ float4 cs[64][16];
    const float4* cp4 = reinterpret_cast<const float4*>(ctx + (size_t)bh * DHEAD * DHEAD);
    for (int idx = threadIdx.x; idx < 64 * 16; idx += 128)
        cs[idx >> 4][idx & 15] = cp4[idx];
    __syncthreads();

    const float* qp = qkv + ((size_t)b * QKV_CH + h * DHEAD) * L + n;
    float m = -INFINITY;
#pragma unroll 8
    for (int d = 0; d < DHEAD; d++) m = fmaxf(m, qp[(size_t)d * L]);
    float sum = 0.f;
#pragma unroll 8
    for (int d = 0; d < DHEAD; d++) sum += expf(qp[(size_t)d * L] - m);
    float inv = ATTN_SCALE / sum;

    float4 acc[16];
#pragma unroll
    for (int e = 0; e < 16; e++) acc[e] = make_float4(0.f, 0.f, 0.f, 0.f);

#pragma unroll 4
    for (int d = 0; d < DHEAD; d++) {
        float qs = expf(qp[(size_t)d * L] - m) * inv;
#pragma unroll
        for (int e = 0; e < 16; e++) {
            float4 c4 = cs[d][e];
            acc[e].x = fmaf(c4.x, qs, acc[e].x);
            acc[e].y = fmaf(c4.y, qs, acc[e].y);
            acc[e].z = fmaf(c4.z, qs, acc[e].z);
            acc[e].w = fmaf(c4.w, qs, acc[e].w);
        }
    }

    float* op = attn + ((size_t)b * HIDDEN + h * DHEAD) * L + n;
#pragma unroll
    for (int e = 0; e < 16; e++) {
        op[(size_t)(e * 4 + 0) * L] = acc[e].x;
        op[(size_t)(e * 4 + 1) * L] = acc[e].y;
        op[(size_t)(e * 4 + 2) * L] = acc[e].z;
        op[(size_t)(e * 4 + 3) * L] = acc[e].w;
    }
}

// ---------------------------------------------------------------------------
extern "C" void kernel_launch(void* const* d_in, const int* in_sizes, int n_in,
                              void* d_out, int out_size) {
    const float* x     = (const float*)d_in[0];
    const float* g_in  = (const float*)d_in[1];
    const float* w_qkv = (const float*)d_in[2];
    const float* w_out = (const float*)d_in[3];
    const float* b_out = (const float*)d_in[4];
    const float* g_out = (const float*)d_in[5];
    float* out = (float*)d_out;

    float *xn, *qkv, *ctxp, *ctx, *attn, *o;
    cudaGetSymbolAddress((void**)&xn, g_xn);
    cudaGetSymbolAddress((void**)&qkv, g_qkv);
    cudaGetSymbolAddress((void**)&ctxp, g_ctxp);
    cudaGetSymbolAddress((void**)&ctx, g_ctx);
    cudaGetSymbolAddress((void**)&attn, g_attn);
    cudaGetSymbolAddress((void**)&o, g_o);

    // 1. RMSNorm(x) -> xn
    rmsnorm_ch_kernel<<<(B * L) / 256, 256>>>(x, g_in, xn);

    // 2. qkv = w_qkv @ xn   [1536,512]x[512,4096] x8  (tf32 tensor core)
    sgemm_tf32<<<dim3(L / 128, QKV_CH / 128, B), 256>>>(
        w_qkv, xn, qkv, nullptr, QKV_CH, L, C,
        (size_t)C * L, (size_t)QKV_CH * L);

    // 3. k softmax over L (in place)
    ksoftmax_kernel<<<B * HIDDEN, 256>>>(qkv);

    // 4. context = k @ v^T per (b,h), split over L then reduced
    ctx_part_kernel<<<dim3(B * HEADS, NCHUNK), 256>>>(qkv, ctxp);
    ctx_reduce_kernel<<<(B * HEADS * DHEAD * DHEAD) / 256, 256>>>(ctxp, ctx);

    // 5. attn = ctx^T @ softmax_d(q)*scale
    attn_apply_kernel<<<dim3(L / 128, B * HEADS), 128>>>(qkv, ctx, attn);

    // 6. o = w_out @ attn + b_out   [512,512]x[512,4096] x8  (tf32 tensor core)
    sgemm_tf32<<<dim3(L / 128, C / 128, B), 256>>>(
        w_out, attn, o, b_out, C, L, HIDDEN,
        (size_t)HIDDEN * L, (size_t)C * L);

    // 7. RMSNorm(o) + residual -> out
    rmsnorm_res_kernel<<<(B * L) / 256, 256>>>(o, g_out, x, out);
}

// round 3
// speedup vs baseline: 2.6418x; 1.1651x over previous
#include <cuda_runtime.h>
#include <cuda_bf16.h>
#include <math.h>
#include <stdint.h>

// Problem constants
#define B 8
#define C 512
#define L 4096
#define HEADS 8
#define DHEAD 64
#define HIDDEN 512           // HEADS*DHEAD
#define QKV_CH 1536          // 3*HIDDEN
#define SQRT_C 22.627416998f // sqrt(512)
#define ATTN_SCALE 0.125f    // 64^-0.5
#define NCHUNK 32            // ctx split factor over L

// Scratch buffers (static device allocations; no cudaMalloc allowed)
__device__ float g_w2[(size_t)QKV_CH * C];       // 3 MB  (w_qkv * g_in)
__device__ float g_s[(size_t)B * L];             // 128 KB (rmsnorm col scales)
__device__ float g_qkv[(size_t)B * QKV_CH * L];  // 192 MB
__device__ float g_ctxp[(size_t)NCHUNK * B * HEADS * DHEAD * DHEAD]; // 32 MB
__device__ float g_ctx[(size_t)B * HEADS * DHEAD * DHEAD];           // 1 MB
__device__ float g_attn[(size_t)B * HIDDEN * L]; // 64 MB
__device__ float g_o[(size_t)B * C * L];         // 64 MB

// ---------------------------------------------------------------------------
// cp.async helpers
// ---------------------------------------------------------------------------
__device__ __forceinline__ void cp_async16(uint32_t dst, const void* src) {
    asm volatile("cp.async.cg.shared.global [%0], [%1], 16;" :: "r"(dst), "l"(src));
}
__device__ __forceinline__ void cp_commit() {
    asm volatile("cp.async.commit_group;");
}
template <int N>
__device__ __forceinline__ void cp_wait() {
    asm volatile("cp.async.wait_group %0;" :: "n"(N));
}

__device__ __forceinline__ void mma_tf32(float d[4], const uint32_t a[4],
                                         const uint32_t b[2]) {
    asm volatile(
        "mma.sync.aligned.m16n8k8.row.col.f32.tf32.tf32.f32 "
        "{%0,%1,%2,%3}, {%4,%5,%6,%7}, {%8,%9}, {%0,%1,%2,%3};"
        : "+f"(d[0]), "+f"(d[1]), "+f"(d[2]), "+f"(d[3])
        : "r"(a[0]), "r"(a[1]), "r"(a[2]), "r"(a[3]),
          "r"(b[0]), "r"(b[1]));
}

// ---------------------------------------------------------------------------
// Kernel 0: fold g_in into w_qkv  (w2[o,c] = w_qkv[o,c] * g_in[c])
// ---------------------------------------------------------------------------
__global__ void fold_w_kernel(const float* __restrict__ w,
                              const float* __restrict__ g,
                              float* __restrict__ w2) {
    int i = blockIdx.x * 256 + threadIdx.x;
    w2[i] = w[i] * g[i & (C - 1)];
}

// ---------------------------------------------------------------------------
// Kernel 1: per-column rmsnorm scale  s[b,l] = sqrt(C)/max(||x[:,l]||, eps)
// ---------------------------------------------------------------------------
__global__ void normscale_kernel(const float* __restrict__ x,
                                 float* __restrict__ s) {
    size_t idx = (size_t)blockIdx.x * blockDim.x + threadIdx.x; // over B*L
    int b = (int)(idx >> 12);
    int l = (int)(idx & (L - 1));
    const float* xp = x + ((size_t)b * C) * L + l;
    float ss = 0.f;
#pragma unroll 8
    for (int c = 0; c < C; c++) {
        float v = xp[(size_t)c * L];
        ss += v * v;
    }
    s[idx] = SQRT_C / fmaxf(sqrtf(ss), 1e-12f);
}

// ---------------------------------------------------------------------------
// Kernel 7: final RMSNorm + residual
// ---------------------------------------------------------------------------
__global__ void rmsnorm_res_kernel(const float* __restrict__ o,
                                   const float* __restrict__ g,
                                   const float* __restrict__ x,
                                   float* __restrict__ out) {
    size_t idx = (size_t)blockIdx.x * blockDim.x + threadIdx.x;
    int b = (int)(idx >> 12);
    int l = (int)(idx & (L - 1));
    size_t base = ((size_t)b * C) * L + l;
    const float* op = o + base;
    float ss = 0.f;
#pragma unroll 8
    for (int c = 0; c < C; c++) {
        float v = op[(size_t)c * L];
        ss += v * v;
    }
    float n = fmaxf(sqrtf(ss), 1e-12f);
    float scale = SQRT_C / n;
    const float* xp = x + base;
    float* dp = out + base;
#pragma unroll 8
    for (int c = 0; c < C; c++) {
        dp[(size_t)c * L] = op[(size_t)c * L] * scale * g[c] + xp[(size_t)c * L];
    }
}

// ---------------------------------------------------------------------------
// Batched tf32 tensor-core GEMM with cp.async 3-stage pipeline.
// Cmat[bz] = A @ Bmat[bz]; optional +bias[row]; optional *colscale[bz*N+col].
// A [M,K] row-major shared across batch; Bmat[bz]=[K,N] row-major.
// 128x128 block tile, BK=16, 8 warps (2x4), 64x32 warp tiles, m16n8k8 tf32.
// A smem: [m][k] stride 20 (conflict-free frag LDS); B smem: [k][n] stride 136.
// fp32 bits fed to HMMA directly (tf32 truncation).
// ---------------------------------------------------------------------------
#define AS_LD 20
#define BS_LD 136
#define STAGES 3
#define GEMM_SMEM (STAGES * (128 * AS_LD + 16 * BS_LD) * 4)

extern __shared__ float sgm[];

__device__ __forceinline__ void gemm_load_tile(uint32_t sa, uint32_t sb, int stage,
                                               const float* Ap, const float* Bp,
                                               int k0, int K, int N, int tid) {
    {
        int c = tid;
        int row = c >> 2, kc = (c & 3) * 4;
        cp_async16(sa + (uint32_t)(stage * 128 * AS_LD + row * AS_LD + kc) * 4,
                   Ap + (size_t)row * K + k0 + kc);
        c = tid + 256;
        row = c >> 2; kc = (c & 3) * 4;
        cp_async16(sa + (uint32_t)(stage * 128 * AS_LD + row * AS_LD + kc) * 4,
                   Ap + (size_t)row * K + k0 + kc);
    }
    {
        int c = tid;
        int kr = c >> 5, n4 = (c & 31) * 4;
        cp_async16(sb + (uint32_t)(stage * 16 * BS_LD + kr * BS_LD + n4) * 4,
                   Bp + (size_t)(k0 + kr) * N + n4);
        c = tid + 256;
        kr = c >> 5; n4 = (c & 31) * 4;
        cp_async16(sb + (uint32_t)(stage * 16 * BS_LD + kr * BS_LD + n4) * 4,
                   Bp + (size_t)(k0 + kr) * N + n4);
    }
}

__global__ __launch_bounds__(256) void gemm_tf32(
    const float* __restrict__ A, const float* __restrict__ Bb,
    float* __restrict__ Cb, const float* __restrict__ bias,
    const float* __restrict__ colscale,
    int M, int N, int K, size_t strideB, size_t strideC) {
    float* As = sgm;
    float* Bs = sgm + STAGES * 128 * AS_LD;
    uint32_t sa = (uint32_t)__cvta_generic_to_shared(As);
    uint32_t sb = (uint32_t)__cvta_generic_to_shared(Bs);

    const int tid = threadIdx.x;
    const int lane = tid & 31;
    const int warp = tid >> 5;
    const int gid = lane >> 2;   // 0..7
    const int t4 = lane & 3;     // 0..3
    const int wm = warp >> 2;    // 0..1
    const int wn = warp & 3;     // 0..3

    const float* Ap = A + (size_t)blockIdx.y * 128 * K;
    const float* Bp = Bb + (size_t)blockIdx.z * strideB + (size_t)blockIdx.x * 128;
    float* Cp = Cb + (size_t)blockIdx.z * strideC +
                (size_t)blockIdx.y * 128 * N + (size_t)blockIdx.x * 128;

    float acc[4][4][4];
#pragma unroll
    for (int mi = 0; mi < 4; mi++)
#pragma unroll
        for (int ni = 0; ni < 4; ni++)
#pragma unroll
            for (int r = 0; r < 4; r++) acc[mi][ni][r] = 0.f;

    const int ktiles = K >> 4;
    // prologue: stages 0..STAGES-2
#pragma unroll
    for (int s = 0; s < STAGES - 1; s++) {
        gemm_load_tile(sa, sb, s, Ap, Bp, s * 16, K, N, tid);
        cp_commit();
    }
    cp_wait<STAGES - 2>();
    __syncthreads();

    for (int kt = 0; kt < ktiles; kt++) {
        const float* Ab = As + (kt % STAGES) * 128 * AS_LD;
        const float* Bbuf = Bs + (kt % STAGES) * 16 * BS_LD;
#pragma unroll
        for (int kk = 0; kk < 2; kk++) {
            const int kb = kk * 8;
            uint32_t af[4][4], bf[4][2];
#pragma unroll
            for (int mi = 0; mi < 4; mi++) {
                const int m0 = wm * 64 + mi * 16;
                af[mi][0] = __float_as_uint(Ab[(m0 + gid) * AS_LD + kb + t4]);
                af[mi][1] = __float_as_uint(Ab[(m0 + gid + 8) * AS_LD + kb + t4]);
                af[mi][2] = __float_as_uint(Ab[(m0 + gid) * AS_LD + kb + t4 + 4]);
                af[mi][3] = __float_as_uint(Ab[(m0 + gid + 8) * AS_LD + kb + t4 + 4]);
            }
#pragma unroll
            for (int ni = 0; ni < 4; ni++) {
                const int n0 = wn * 32 + ni * 8;
                bf[ni][0] = __float_as_uint(Bbuf[(kb + t4) * BS_LD + n0 + gid]);
                bf[ni][1] = __float_as_uint(Bbuf[(kb + t4 + 4) * BS_LD + n0 + gid]);
            }
#pragma unroll
            for (int mi = 0; mi < 4; mi++)
#pragma unroll
                for (int ni = 0; ni < 4; ni++)
                    mma_tf32(acc[mi][ni], af[mi], bf[ni]);
        }
        int nt = kt + STAGES - 1;
        if (nt < ktiles)
            gemm_load_tile(sa, sb, nt % STAGES, Ap, Bp, nt * 16, K, N, tid);
        cp_commit();
        cp_wait<STAGES - 2>();
        __syncthreads();
    }

    // epilogue
#pragma unroll
    for (int mi = 0; mi < 4; mi++) {
        const int r0 = wm * 64 + mi * 16 + gid;
        const float bv0 = bias ? bias[blockIdx.y * 128 + r0] : 0.f;
        const float bv1 = bias ? bias[blockIdx.y * 128 + r0 + 8] : 0.f;
#pragma unroll
        for (int ni = 0; ni < 4; ni++) {
            const int col = wn * 32 + ni * 8 + t4 * 2;
            float s0 = 1.f, s1 = 1.f;
            if (colscale) {
                const float* sp = colscale + (size_t)blockIdx.z * N +
                                  (size_t)blockIdx.x * 128 + col;
                s0 = sp[0];
                s1 = sp[1];
            }
            float2 v0 = make_float2(acc[mi][ni][0] * s0 + bv0,
                                    acc[mi][ni][1] * s1 + bv0);
            float2 v1 = make_float2(acc[mi][ni][2] * s0 + bv1,
                                    acc[mi][ni][3] * s1 + bv1);
            *(float2*)&Cp[(size_t)r0 * N + col] = v0;
            *(float2*)&Cp[(size_t)(r0 + 8) * N + col] = v1;
        }
    }
}

// ---------------------------------------------------------------------------
// Kernel 3: softmax over L for the k channels (qkv channels [512,1024)), in place.
// ---------------------------------------------------------------------------
__global__ void ksoftmax_kernel(float* __restrict__ qkv) {
    int row = blockIdx.x;           // 0..B*HIDDEN-1
    int b = row >> 9;
    int ch = row & (HIDDEN - 1);
    float* p = qkv + ((size_t)b * QKV_CH + HIDDEN + ch) * L;
    int tid = threadIdx.x;          // 256 threads, 16 elems each
    float v[16];
    float m = -INFINITY;
#pragma unroll
    for (int i = 0; i < 16; i++) {
        v[i] = p[tid + i * 256];
        m = fmaxf(m, v[i]);
    }
    __shared__ float red[256];
    red[tid] = m;
    __syncthreads();
    for (int s = 128; s > 0; s >>= 1) {
        if (tid < s) red[tid] = fmaxf(red[tid], red[tid + s]);
        __syncthreads();
    }
    m = red[0];
    __syncthreads();
    float sum = 0.f;
#pragma unroll
    for (int i = 0; i < 16; i++) {
        v[i] = expf(v[i] - m);
        sum += v[i];
    }
    red[tid] = sum;
    __syncthreads();
    for (int s = 128; s > 0; s >>= 1) {
        if (tid < s) red[tid] += red[tid + s];
        __syncthreads();
    }
    float inv = 1.f / red[0];
#pragma unroll
    for (int i = 0; i < 16; i++) p[tid + i * 256] = v[i] * inv;
}

// ---------------------------------------------------------------------------
// Kernel 4a: partial context over an L-chunk (128 cols per block).
// grid = (B*HEADS, NCHUNK). float4 staging, padded smem.
// ---------------------------------------------------------------------------
__global__ __launch_bounds__(256) void ctx_part_kernel(const float* __restrict__ qkv,
                                                       float* __restrict__ ctxp) {
    int bh = blockIdx.x;
    int chunk = blockIdx.y;
    int b = bh >> 3, h = bh & 7;
    const float* kp = qkv + ((size_t)b * QKV_CH + HIDDEN + h * DHEAD) * L;
    const float* vp = qkv + ((size_t)b * QKV_CH + 2 * HIDDEN + h * DHEAD) * L;
    __shared__ float ks[64][68];
    __shared__ float vs[64][68];
    int tid = threadIdx.x;
    int d0 = (tid >> 4) * 4;
    int e0 = (tid & 15) * 4;
    float acc[4][4];
#pragma unroll
    for (int i = 0; i < 4; i++)
#pragma unroll
        for (int j = 0; j < 4; j++) acc[i][j] = 0.f;

    int nbeg = chunk * (L / NCHUNK);
#pragma unroll
    for (int c0 = 0; c0 < (L / NCHUNK); c0 += 64) {
        int n0 = nbeg + c0;
        for (int idx = tid; idx < 64 * 16; idx += 256) {
            int r = idx >> 4, c4 = (idx & 15) * 4;
            *(float4*)&ks[r][c4] = *(const float4*)&kp[(size_t)r * L + n0 + c4];
            *(float4*)&vs[r][c4] = *(const float4*)&vp[(size_t)r * L + n0 + c4];
        }
        __syncthreads();
#pragma unroll 4
        for (int nn = 0; nn < 64; nn++) {
            float rk[4], rv[4];
#pragma unroll
            for (int i = 0; i < 4; i++) rk[i] = ks[d0 + i][nn];
#pragma unroll
            for (int j = 0; j < 4; j++) rv[j] = vs[e0 + j][nn];
#pragma unroll
            for (int i = 0; i < 4; i++)
#pragma unroll
                for (int j = 0; j < 4; j++) acc[i][j] = fmaf(rk[i], rv[j], acc[i][j]);
        }
        __syncthreads();
    }
    float* cp = ctxp + ((size_t)chunk * (B * HEADS) + bh) * (DHEAD * DHEAD);
#pragma unroll
    for (int i = 0; i < 4; i++)
#pragma unroll
        for (int j = 0; j < 4; j++) cp[(d0 + i) * DHEAD + e0 + j] = acc[i][j];
}

// ---------------------------------------------------------------------------
// Kernel 4b: reduce NCHUNK partial contexts -> ctx
// ---------------------------------------------------------------------------
__global__ void ctx_reduce_kernel(const float* __restrict__ ctxp,
                                  float* __restrict__ ctx) {
    int i = blockIdx.x * 256 + threadIdx.x; // over B*HEADS*DHEAD*DHEAD
    float s = 0.f;
#pragma unroll
    for (int c = 0; c < NCHUNK; c++)
        s += ctxp[(size_t)c * (B * HEADS * DHEAD * DHEAD) + i];
    ctx[i] = s;
}

// ---------------------------------------------------------------------------
// Kernel 5: q-softmax (over d) fused with out[e,n] = sum_d ctx[d,e]*qs[d,n].
// q tile staged in smem (global q read once).
// ---------------------------------------------------------------------------
__global__ __launch_bounds__(128) void attn_apply_kernel(const float* __restrict__ qkv,
                                                         const float* __restrict__ ctx,
                                                         float* __restrict__ attn) {
    int n0 = blockIdx.x * 128;
    int bh = blockIdx.y;
    int b = bh >> 3, h = bh & 7;

    __shared__ float4 cs[64][16];   // ctx [d][e/4]
    __shared__ float qs_s[64][128]; // q tile [d][n]
    const float4* cp4 = reinterpret_cast<const float4*>(ctx + (size_t)bh * DHEAD * DHEAD);
    for (int idx = threadIdx.x; idx < 64 * 16; idx += 128)
        cs[idx >> 4][idx & 15] = cp4[idx];

    const float* qp = qkv + ((size_t)b * QKV_CH + h * DHEAD) * L + n0;
    for (int idx = threadIdx.x; idx < 64 * 128; idx += 128) {
        int d = idx >> 7, col = idx & 127;
        qs_s[d][col] = qp[(size_t)d * L + col];
    }
    __syncthreads();

    int t = threadIdx.x;
    float m = -INFINITY;
#pragma unroll 8
    for (int d = 0; d < DHEAD; d++) m = fmaxf(m, qs_s[d][t]);
    float sum = 0.f;
#pragma unroll 8
    for (int d = 0; d < DHEAD; d++) sum += expf(qs_s[d][t] - m);
    float inv = ATTN_SCALE / sum;

    float4 acc[16];
#pragma unroll
    for (int e = 0; e < 16; e++) acc[e] = make_float4(0.f, 0.f, 0.f, 0.f);

#pragma unroll 4
    for (int d = 0; d < DHEAD; d++) {
        float qv = expf(qs_s[d][t] - m) * inv;
#pragma unroll
        for (int e = 0; e < 16; e++) {
            float4 c4 = cs[d][e];
            acc[e].x = fmaf(c4.x, qv, acc[e].x);
            acc[e].y = fmaf(c4.y, qv, acc[e].y);
            acc[e].z = fmaf(c4.z, qv, acc[e].z);
            acc[e].w = fmaf(c4.w, qv, acc[e].w);
        }
    }

    float* op = attn + ((size_t)b * HIDDEN + h * DHEAD) * L + n0 + t;
#pragma unroll
    for (int e = 0; e < 16; e++) {
        op[(size_t)(e * 4 + 0) * L] = acc[e].x;
        op[(size_t)(e * 4 + 1) * L] = acc[e].y;
        op[(size_t)(e * 4 + 2) * L] = acc[e].z;
        op[(size_t)(e * 4 + 3) * L] = acc[e].w;
    }
}

// ---------------------------------------------------------------------------
extern "C" void kernel_launch(void* const* d_in, const int* in_sizes, int n_in,
                              void* d_out, int out_size) {
    const float* x     = (const float*)d_in[0];
    const float* g_in  = (const float*)d_in[1];
    const float* w_qkv = (const float*)d_in[2];
    const float* w_out = (const float*)d_in[3];
    const float* b_out = (const float*)d_in[4];
    const float* g_out = (const float*)d_in[5];
    float* out = (float*)d_out;

    float *w2, *s, *qkv, *ctxp, *ctx, *attn, *o;
    cudaGetSymbolAddress((void**)&w2, g_w2);
    cudaGetSymbolAddress((void**)&s, g_s);
    cudaGetSymbolAddress((void**)&qkv, g_qkv);
    cudaGetSymbolAddress((void**)&ctxp, g_ctxp);
    cudaGetSymbolAddress((void**)&ctx, g_ctx);
    cudaGetSymbolAddress((void**)&attn, g_attn);
    cudaGetSymbolAddress((void**)&o, g_o);

    cudaFuncSetAttribute(gemm_tf32, cudaFuncAttributeMaxDynamicSharedMemorySize,
                         GEMM_SMEM);

    // 0. fold g_in into w_qkv
    fold_w_kernel<<<(QKV_CH * C) / 256, 256>>>(w_qkv, g_in, w2);

    // 1. per-column rmsnorm scales
    normscale_kernel<<<(B * L) / 256, 256>>>(x, s);

    // 2. qkv = (w_qkv*g) @ x, scaled by s at epilogue  (tf32 TC, cp.async)
    gemm_tf32<<<dim3(L / 128, QKV_CH / 128, B), 256, GEMM_SMEM>>>(
        w2, x, qkv, nullptr, s, QKV_CH, L, C,
        (size_t)C * L, (size_t)QKV_CH * L);

    // 3. k softmax over L (in place)
    ksoftmax_kernel<<<B * HIDDEN, 256>>>(qkv);

    // 4. context = k @ v^T per (b,h), split over L then reduced
    ctx_part_kernel<<<dim3(B * HEADS, NCHUNK), 256>>>(qkv, ctxp);
    ctx_reduce_kernel<<<(B * HEADS * DHEAD * DHEAD) / 256, 256>>>(ctxp, ctx);

    // 5. attn = ctx^T @ softmax_d(q)*scale
    attn_apply_kernel<<<dim3(L / 128, B * HEADS), 128>>>(qkv, ctx, attn);

    // 6. o = w_out @ attn + b_out  (tf32 TC, cp.async)
    gemm_tf32<<<dim3(L / 128, C / 128, B), 256, GEMM_SMEM>>>(
        w_out, attn, o, b_out, nullptr, C, L, HIDDEN,
        (size_t)HIDDEN * L, (size_t)C * L);

    // 7. RMSNorm(o) + residual -> out
    rmsnorm_res_kernel<<<(B * L) / 256, 256>>>(o, g_out, x, out);
}

// round 5
// speedup vs baseline: 2.6754x; 1.0127x over previous
#include <cuda_runtime.h>
#include <cuda_bf16.h>
#include <math.h>
#include <stdint.h>

// Problem constants
#define B 8
#define C 512
#define L 4096
#define HEADS 8
#define DHEAD 64
#define HIDDEN 512           // HEADS*DHEAD
#define QKV_CH 1536          // 3*HIDDEN
#define SQRT_C 22.627416998f // sqrt(512)
#define ATTN_SCALE 0.125f    // 64^-0.5
#define NCHUNK 32            // ctx split factor over L

// Scratch buffers (static device allocations; no cudaMalloc allowed)
__device__ float g_w2[(size_t)QKV_CH * C];       // 3 MB  (w_qkv * g_in)
__device__ float g_s[(size_t)B * L];             // 128 KB (rmsnorm col scales)
__device__ float g_qkv[(size_t)B * QKV_CH * L];  // 192 MB
__device__ float g_ctxp[(size_t)NCHUNK * B * HEADS * DHEAD * DHEAD]; // 32 MB
__device__ float g_ctx[(size_t)B * HEADS * DHEAD * DHEAD];           // 1 MB
__device__ float g_attn[(size_t)B * HIDDEN * L]; // 64 MB
__device__ float g_o[(size_t)B * C * L];         // 64 MB

// ---------------------------------------------------------------------------
// cp.async helpers
// ---------------------------------------------------------------------------
__device__ __forceinline__ void cp_async16(uint32_t dst, const void* src) {
    asm volatile("cp.async.cg.shared.global [%0], [%1], 16;" :: "r"(dst), "l"(src));
}
__device__ __forceinline__ void cp_commit() {
    asm volatile("cp.async.commit_group;");
}
template <int N>
__device__ __forceinline__ void cp_wait() {
    asm volatile("cp.async.wait_group %0;" :: "n"(N));
}

__device__ __forceinline__ void mma_tf32(float d[4], const uint32_t a[4],
                                         const uint32_t b[2]) {
    asm volatile(
        "mma.sync.aligned.m16n8k8.row.col.f32.tf32.tf32.f32 "
        "{%0,%1,%2,%3}, {%4,%5,%6,%7}, {%8,%9}, {%0,%1,%2,%3};"
        : "+f"(d[0]), "+f"(d[1]), "+f"(d[2]), "+f"(d[3])
        : "r"(a[0]), "r"(a[1]), "r"(a[2]), "r"(a[3]),
          "r"(b[0]), "r"(b[1]));
}

// ---------------------------------------------------------------------------
// Kernel 0: fold g_in into w_qkv  (w2[o,c] = w_qkv[o,c] * g_in[c])
// ---------------------------------------------------------------------------
__global__ void fold_w_kernel(const float* __restrict__ w,
                              const float* __restrict__ g,
                              float* __restrict__ w2) {
    int i = blockIdx.x * 256 + threadIdx.x;
    w2[i] = w[i] * g[i & (C - 1)];
}

// ---------------------------------------------------------------------------
// Kernel 1: per-column rmsnorm scale  s[b,l] = sqrt(C)/max(||x[:,l]||, eps)
// ---------------------------------------------------------------------------
__global__ void normscale_kernel(const float* __restrict__ x,
                                 float* __restrict__ s) {
    size_t idx = (size_t)blockIdx.x * blockDim.x + threadIdx.x; // over B*L
    int b = (int)(idx >> 12);
    int l = (int)(idx & (L - 1));
    const float* xp = x + ((size_t)b * C) * L + l;
    float ss = 0.f;
#pragma unroll 8
    for (int c = 0; c < C; c++) {
        float v = xp[(size_t)c * L];
        ss += v * v;
    }
    s[idx] = SQRT_C / fmaxf(sqrtf(ss), 1e-12f);
}

// ---------------------------------------------------------------------------
// Kernel 7: final RMSNorm + residual
// ---------------------------------------------------------------------------
__global__ void rmsnorm_res_kernel(const float* __restrict__ o,
                                   const float* __restrict__ g,
                                   const float* __restrict__ x,
                                   float* __restrict__ out) {
    size_t idx = (size_t)blockIdx.x * blockDim.x + threadIdx.x;
    int b = (int)(idx >> 12);
    int l = (int)(idx & (L - 1));
    size_t base = ((size_t)b * C) * L + l;
    const float* op = o + base;
    float ss = 0.f;
#pragma unroll 8
    for (int c = 0; c < C; c++) {
        float v = op[(size_t)c * L];
        ss += v * v;
    }
    float n = fmaxf(sqrtf(ss), 1e-12f);
    float scale = SQRT_C / n;
    const float* xp = x + base;
    float* dp = out + base;
#pragma unroll 8
    for (int c = 0; c < C; c++) {
        dp[(size_t)c * L] = op[(size_t)c * L] * scale * g[c] + xp[(size_t)c * L];
    }
}

// ---------------------------------------------------------------------------
// Batched tf32 tensor-core GEMM with cp.async 3-stage pipeline.
// Cmat[bz] = A @ Bmat[bz]; optional +bias[row]; optional *colscale[bz*N+col].
// A [M,K] row-major shared across batch; Bmat[bz]=[K,N] row-major.
// 128x128 CTA tile, BK=16, 4 warps (2x2), 64x64 warp tiles, m16n8k8 tf32.
// A smem: [m][k] stride 20; B smem: [k][n] stride 136 (conflict-free).
// fp32 bits fed to HMMA directly (tf32 truncation).
// ---------------------------------------------------------------------------
#define AS_LD 20
#define BS_LD 136
#define STAGES 3
#define GEMM_SMEM (STAGES * (128 * AS_LD + 16 * BS_LD) * 4)

extern __shared__ float sgm[];

__device__ __forceinline__ void gemm_load_tile(uint32_t sa, uint32_t sb, int stage,
                                               const float* Ap, const float* Bp,
                                               int k0, int K, int N, int tid) {
#pragma unroll
    for (int i = 0; i < 4; i++) {
        int c = tid + i * 128;
        int row = c >> 2, kc = (c & 3) * 4;
        cp_async16(sa + (uint32_t)(stage * 128 * AS_LD + row * AS_LD + kc) * 4,
                   Ap + (size_t)row * K + k0 + kc);
    }
#pragma unroll
    for (int i = 0; i < 4; i++) {
        int c = tid + i * 128;
        int kr = c >> 5, n4 = (c & 31) * 4;
        cp_async16(sb + (uint32_t)(stage * 16 * BS_LD + kr * BS_LD + n4) * 4,
                   Bp + (size_t)(k0 + kr) * N + n4);
    }
}

__global__ __launch_bounds__(128) void gemm_tf32(
    const float* __restrict__ A, const float* __restrict__ Bb,
    float* __restrict__ Cb, const float* __restrict__ bias,
    const float* __restrict__ colscale,
    int M, int N, int K, size_t strideB, size_t strideC) {
    float* As = sgm;
    float* Bs = sgm + STAGES * 128 * AS_LD;
    uint32_t sa = (uint32_t)__cvta_generic_to_shared(As);
    uint32_t sb = (uint32_t)__cvta_generic_to_shared(Bs);

    const int tid = threadIdx.x;
    const int lane = tid & 31;
    const int warp = tid >> 5;
    const int gid = lane >> 2;   // 0..7
    const int t4 = lane & 3;     // 0..3
    const int wm = warp >> 1;    // 0..1
    const int wn = warp & 1;     // 0..1

    const float* Ap = A + (size_t)blockIdx.y * 128 * K;
    const float* Bp = Bb + (size_t)blockIdx.z * strideB + (size_t)blockIdx.x * 128;
    float* Cp = Cb + (size_t)blockIdx.z * strideC +
                (size_t)blockIdx.y * 128 * N + (size_t)blockIdx.x * 128;

    float acc[4][8][4];
#pragma unroll
    for (int mi = 0; mi < 4; mi++)
#pragma unroll
        for (int ni = 0; ni < 8; ni++)
#pragma unroll
            for (int r = 0; r < 4; r++) acc[mi][ni][r] = 0.f;

    const int ktiles = K >> 4;
    // prologue: stages 0..STAGES-2
#pragma unroll
    for (int s = 0; s < STAGES - 1; s++) {
        gemm_load_tile(sa, sb, s, Ap, Bp, s * 16, K, N, tid);
        cp_commit();
    }
    cp_wait<STAGES - 2>();
    __syncthreads();

    for (int kt = 0; kt < ktiles; kt++) {
        const float* Ab = As + (kt % STAGES) * 128 * AS_LD;
        const float* Bbuf = Bs + (kt % STAGES) * 16 * BS_LD;
#pragma unroll
        for (int kk = 0; kk < 2; kk++) {
            const int kb = kk * 8;
            uint32_t af[4][4], bf[8][2];
#pragma unroll
            for (int mi = 0; mi < 4; mi++) {
                const int m0 = wm * 64 + mi * 16;
                af[mi][0] = __float_as_uint(Ab[(m0 + gid) * AS_LD + kb + t4]);
                af[mi][1] = __float_as_uint(Ab[(m0 + gid + 8) * AS_LD + kb + t4]);
                af[mi][2] = __float_as_uint(Ab[(m0 + gid) * AS_LD + kb + t4 + 4]);
                af[mi][3] = __float_as_uint(Ab[(m0 + gid + 8) * AS_LD + kb + t4 + 4]);
            }
#pragma unroll
            for (int ni = 0; ni < 8; ni++) {
                const int n0 = wn * 64 + ni * 8;
                bf[ni][0] = __float_as_uint(Bbuf[(kb + t4) * BS_LD + n0 + gid]);
                bf[ni][1] = __float_as_uint(Bbuf[(kb + t4 + 4) * BS_LD + n0 + gid]);
            }
#pragma unroll
            for (int mi = 0; mi < 4; mi++)
#pragma unroll
                for (int ni = 0; ni < 8; ni++)
                    mma_tf32(acc[mi][ni], af[mi], bf[ni]);
        }
        int nt = kt + STAGES - 1;
        if (nt < ktiles)
            gemm_load_tile(sa, sb, nt % STAGES, Ap, Bp, nt * 16, K, N, tid);
        cp_commit();
        cp_wait<STAGES - 2>();
        __syncthreads();
    }

    // epilogue
#pragma unroll
    for (int mi = 0; mi < 4; mi++) {
        const int r0 = wm * 64 + mi * 16 + gid;
        const float bv0 = bias ? bias[blockIdx.y * 128 + r0] : 0.f;
        const float bv1 = bias ? bias[blockIdx.y * 128 + r0 + 8] : 0.f;
#pragma unroll
        for (int ni = 0; ni < 8; ni++) {
            const int col = wn * 64 + ni * 8 + t4 * 2;
            float s0 = 1.f, s1 = 1.f;
            if (colscale) {
                const float* sp = colscale + (size_t)blockIdx.z * N +
                                  (size_t)blockIdx.x * 128 + col;
                s0 = sp[0];
                s1 = sp[1];
            }
            float2 v0 = make_float2(acc[mi][ni][0] * s0 + bv0,
                                    acc[mi][ni][1] * s1 + bv0);
            float2 v1 = make_float2(acc[mi][ni][2] * s0 + bv1,
                                    acc[mi][ni][3] * s1 + bv1);
            *(float2*)&Cp[(size_t)r0 * N + col] = v0;
            *(float2*)&Cp[(size_t)(r0 + 8) * N + col] = v1;
        }
    }
}

// ---------------------------------------------------------------------------
// Kernel 3: softmax over L for the k channels (qkv channels [512,1024)), in place.
// ---------------------------------------------------------------------------
__global__ void ksoftmax_kernel(float* __restrict__ qkv) {
    int row = blockIdx.x;           // 0..B*HIDDEN-1
    int b = row >> 9;
    int ch = row & (HIDDEN - 1);
    float* p = qkv + ((size_t)b * QKV_CH + HIDDEN + ch) * L;
    int tid = threadIdx.x;          // 256 threads, 16 elems each
    float v[16];
    float m = -INFINITY;
#pragma unroll
    for (int i = 0; i < 16; i++) {
        v[i] = p[tid + i * 256];
        m = fmaxf(m, v[i]);
    }
    __shared__ float red[256];
    red[tid] = m;
    __syncthreads();
    for (int s = 128; s > 0; s >>= 1) {
        if (tid < s) red[tid] = fmaxf(red[tid], red[tid + s]);
        __syncthreads();
    }
    m = red[0];
    __syncthreads();
    float sum = 0.f;
#pragma unroll
    for (int i = 0; i < 16; i++) {
        v[i] = expf(v[i] - m);
        sum += v[i];
    }
    red[tid] = sum;
    __syncthreads();
    for (int s = 128; s > 0; s >>= 1) {
        if (tid < s) red[tid] += red[tid + s];
        __syncthreads();
    }
    float inv = 1.f / red[0];
#pragma unroll
    for (int i = 0; i < 16; i++) p[tid + i * 256] = v[i] * inv;
}

// ---------------------------------------------------------------------------
// Kernel 4a: partial context over an L-chunk (128 cols per block).
// ---------------------------------------------------------------------------
__global__ __launch_bounds__(256) void ctx_part_kernel(const float* __restrict__ qkv,
                                                       float* __restrict__ ctxp) {
    int bh = blockIdx.x;
    int chunk = blockIdx.y;
    int b = bh >> 3, h = bh & 7;
    const float* kp = qkv + ((size_t)b * QKV_CH + HIDDEN + h * DHEAD) * L;
    const float* vp = qkv + ((size_t)b * QKV_CH + 2 * HIDDEN + h * DHEAD) * L;
    __shared__ float ks[64][68];
    __shared__ float vs[64][68];
    int tid = threadIdx.x;
    int d0 = (tid >> 4) * 4;
    int e0 = (tid & 15) * 4;
    float acc[4][4];
#pragma unroll
    for (int i = 0; i < 4; i++)
#pragma unroll
        for (int j = 0; j < 4; j++) acc[i][j] = 0.f;

    int nbeg = chunk * (L / NCHUNK);
#pragma unroll
    for (int c0 = 0; c0 < (L / NCHUNK); c0 += 64) {
        int n0 = nbeg + c0;
        for (int idx = tid; idx < 64 * 16; idx += 256) {
            int r = idx >> 4, c4 = (idx & 15) * 4;
            *(float4*)&ks[r][c4] = *(const float4*)&kp[(size_t)r * L + n0 + c4];
            *(float4*)&vs[r][c4] = *(const float4*)&vp[(size_t)r * L + n0 + c4];
        }
        __syncthreads();
#pragma unroll 4
        for (int nn = 0; nn < 64; nn++) {
            float rk[4], rv[4];
#pragma unroll
            for (int i = 0; i < 4; i++) rk[i] = ks[d0 + i][nn];
#pragma unroll
            for (int j = 0; j < 4; j++) rv[j] = vs[e0 + j][nn];
#pragma unroll
            for (int i = 0; i < 4; i++)
#pragma unroll
                for (int j = 0; j < 4; j++) acc[i][j] = fmaf(rk[i], rv[j], acc[i][j]);
        }
        __syncthreads();
    }
    float* cp = ctxp + ((size_t)chunk * (B * HEADS) + bh) * (DHEAD * DHEAD);
#pragma unroll
    for (int i = 0; i < 4; i++)
#pragma unroll
        for (int j = 0; j < 4; j++) cp[(d0 + i) * DHEAD + e0 + j] = acc[i][j];
}

// ---------------------------------------------------------------------------
// Kernel 4b: reduce NCHUNK partial contexts -> ctx
// ---------------------------------------------------------------------------
__global__ void ctx_reduce_kernel(const float* __restrict__ ctxp,
                                  float* __restrict__ ctx) {
    int i = blockIdx.x * 256 + threadIdx.x; // over B*HEADS*DHEAD*DHEAD
    float s = 0.f;
#pragma unroll
    for (int c = 0; c < NCHUNK; c++)
        s += ctxp[(size_t)c * (B * HEADS * DHEAD * DHEAD) + i];
    ctx[i] = s;
}

// ---------------------------------------------------------------------------
// Kernel 5: q-softmax (over d) fused with out[e,n] = sum_d ctx[d,e]*qs[d,n].
// q tile staged in smem (global q read once).
// ---------------------------------------------------------------------------
__global__ __launch_bounds__(128) void attn_apply_kernel(const float* __restrict__ qkv,
                                                         const float* __restrict__ ctx,
                                                         float* __restrict__ attn) {
    int n0 = blockIdx.x * 128;
    int bh = blockIdx.y;
    int b = bh >> 3, h = bh & 7;

    __shared__ float4 cs[64][16];   // ctx [d][e/4]
    __shared__ float qs_s[64][128]; // q tile [d][n]
    const float4* cp4 = reinterpret_cast<const float4*>(ctx + (size_t)bh * DHEAD * DHEAD);
    for (int idx = threadIdx.x; idx < 64 * 16; idx += 128)
        cs[idx >> 4][idx & 15] = cp4[idx];

    const float* qp = qkv + ((size_t)b * QKV_CH + h * DHEAD) * L + n0;
    for (int idx = threadIdx.x; idx < 64 * 128; idx += 128) {
        int d = idx >> 7, col = idx & 127;
        qs_s[d][col] = qp[(size_t)d * L + col];
    }
    __syncthreads();

    int t = threadIdx.x;
    float m = -INFINITY;
#pragma unroll 8
    for (int d = 0; d < DHEAD; d++) m = fmaxf(m, qs_s[d][t]);
    float sum = 0.f;
#pragma unroll 8
    for (int d = 0; d < DHEAD; d++) sum += expf(qs_s[d][t] - m);
    float inv = ATTN_SCALE / sum;

    float4 acc[16];
#pragma unroll
    for (int e = 0; e < 16; e++) acc[e] = make_float4(0.f, 0.f, 0.f, 0.f);

#pragma unroll 4
    for (int d = 0; d < DHEAD; d++) {
        float qv = expf(qs_s[d][t] - m) * inv;
#pragma unroll
        for (int e = 0; e < 16; e++) {
            float4 c4 = cs[d][e];
            acc[e].x = fmaf(c4.x, qv, acc[e].x);
            acc[e].y = fmaf(c4.y, qv, acc[e].y);
            acc[e].z = fmaf(c4.z, qv, acc[e].z);
            acc[e].w = fmaf(c4.w, qv, acc[e].w);
        }
    }

    float* op = attn + ((size_t)b * HIDDEN + h * DHEAD) * L + n0 + t;
#pragma unroll
    for (int e = 0; e < 16; e++) {
        op[(size_t)(e * 4 + 0) * L] = acc[e].x;
        op[(size_t)(e * 4 + 1) * L] = acc[e].y;
        op[(size_t)(e * 4 + 2) * L] = acc[e].z;
        op[(size_t)(e * 4 + 3) * L] = acc[e].w;
    }
}

// ---------------------------------------------------------------------------
extern "C" void kernel_launch(void* const* d_in, const int* in_sizes, int n_in,
                              void* d_out, int out_size) {
    const float* x     = (const float*)d_in[0];
    const float* g_in  = (const float*)d_in[1];
    const float* w_qkv = (const float*)d_in[2];
    const float* w_out = (const float*)d_in[3];
    const float* b_out = (const float*)d_in[4];
    const float* g_out = (const float*)d_in[5];
    float* out = (float*)d_out;

    float *w2, *s, *qkv, *ctxp, *ctx, *attn, *o;
    cudaGetSymbolAddress((void**)&w2, g_w2);
    cudaGetSymbolAddress((void**)&s, g_s);
    cudaGetSymbolAddress((void**)&qkv, g_qkv);
    cudaGetSymbolAddress((void**)&ctxp, g_ctxp);
    cudaGetSymbolAddress((void**)&ctx, g_ctx);
    cudaGetSymbolAddress((void**)&attn, g_attn);
    cudaGetSymbolAddress((void**)&o, g_o);

    cudaFuncSetAttribute(gemm_tf32, cudaFuncAttributeMaxDynamicSharedMemorySize,
                         GEMM_SMEM);

    // 0. fold g_in into w_qkv
    fold_w_kernel<<<(QKV_CH * C) / 256, 256>>>(w_qkv, g_in, w2);

    // 1. per-column rmsnorm scales
    normscale_kernel<<<(B * L) / 256, 256>>>(x, s);

    // 2. qkv = (w_qkv*g) @ x, scaled by s at epilogue  (tf32 TC, cp.async)
    gemm_tf32<<<dim3(L / 128, QKV_CH / 128, B), 128, GEMM_SMEM>>>(
        w2, x, qkv, nullptr, s, QKV_CH, L, C,
        (size_t)C * L, (size_t)QKV_CH * L);

    // 3. k softmax over L (in place)
    ksoftmax_kernel<<<B * HIDDEN, 256>>>(qkv);

    // 4. context = k @ v^T per (b,h), split over L then reduced
    ctx_part_kernel<<<dim3(B * HEADS, NCHUNK), 256>>>(qkv, ctxp);
    ctx_reduce_kernel<<<(B * HEADS * DHEAD * DHEAD) / 256, 256>>>(ctxp, ctx);

    // 5. attn = ctx^T @ softmax_d(q)*scale
    attn_apply_kernel<<<dim3(L / 128, B * HEADS), 128>>>(qkv, ctx, attn);

    // 6. o = w_out @ attn + b_out  (tf32 TC, cp.async)
    gemm_tf32<<<dim3(L / 128, C / 128, B), 128, GEMM_SMEM>>>(
        w_out, attn, o, b_out, nullptr, C, L, HIDDEN,
        (size_t)HIDDEN * L, (size_t)C * L);

    // 7. RMSNorm(o) + residual -> out
    rmsnorm_res_kernel<<<(B * L) / 256, 256>>>(o, g_out, x, out);
}

// round 6
// speedup vs baseline: 3.0654x; 1.1458x over previous
#include <cuda_runtime.h>
#include <cuda_fp16.h>
#include <math.h>
#include <stdint.h>

// Problem constants
#define B 8
#define C 512
#define L 4096
#define HEADS 8
#define DHEAD 64
#define HIDDEN 512           // HEADS*DHEAD
#define QKV_CH 1536          // 3*HIDDEN
#define SQRT_C 22.627416998f // sqrt(512)
#define ATTN_SCALE 0.125f    // 64^-0.5
#define NCHUNK 32            // ctx split factor over L

// Scratch buffers (static device allocations; no cudaMalloc allowed)
__device__ __half g_w2h[(size_t)QKV_CH * C];        // 1.5 MB (w_qkv * g_in, fp16)
__device__ __half g_wouth[(size_t)C * HIDDEN];      // 0.5 MB
__device__ float  g_s[(size_t)B * L];               // rmsnorm col scales
__device__ __half g_xhT[(size_t)B * L * C];         // 32 MB  (x*s)^T fp16 [b][l][c]
__device__ float  g_qkv[(size_t)B * QKV_CH * L];    // 192 MB
__device__ float  g_ctxp[(size_t)NCHUNK * B * HEADS * DHEAD * DHEAD];
__device__ float  g_ctx[(size_t)B * HEADS * DHEAD * DHEAD];
__device__ __half g_attnT[(size_t)B * L * HIDDEN];  // 32 MB fp16 [b][l][e]
__device__ float  g_o[(size_t)B * C * L];           // 64 MB

// ---------------------------------------------------------------------------
// cp.async helpers
// ---------------------------------------------------------------------------
__device__ __forceinline__ void cp_async16(uint32_t dst, const void* src) {
    asm volatile("cp.async.cg.shared.global [%0], [%1], 16;" :: "r"(dst), "l"(src));
}
__device__ __forceinline__ void cp_commit() {
    asm volatile("cp.async.commit_group;");
}
template <int N>
__device__ __forceinline__ void cp_wait() {
    asm volatile("cp.async.wait_group %0;" :: "n"(N));
}

__device__ __forceinline__ void mma_f16(float d[4], const uint32_t a[4],
                                        const uint32_t b[2]) {
    asm volatile(
        "mma.sync.aligned.m16n8k16.row.col.f32.f16.f16.f32 "
        "{%0,%1,%2,%3}, {%4,%5,%6,%7}, {%8,%9}, {%0,%1,%2,%3};"
        : "+f"(d[0]), "+f"(d[1]), "+f"(d[2]), "+f"(d[3])
        : "r"(a[0]), "r"(a[1]), "r"(a[2]), "r"(a[3]),
          "r"(b[0]), "r"(b[1]));
}

// ---------------------------------------------------------------------------
// Kernel 0a: w2h[o][c] = fp16(w_qkv[o][c] * g_in[c])
// ---------------------------------------------------------------------------
__global__ void convert_wqkv_kernel(const float* __restrict__ w,
                                    const float* __restrict__ g,
                                    __half* __restrict__ w2h) {
    int i = blockIdx.x * 256 + threadIdx.x;
    w2h[i] = __float2half(w[i] * g[i & (C - 1)]);
}

// ---------------------------------------------------------------------------
// Kernel 0b: whout = fp16(w_out)
// ---------------------------------------------------------------------------
__global__ void convert_wout_kernel(const float* __restrict__ w,
                                    __half* __restrict__ wh) {
    int i = blockIdx.x * 256 + threadIdx.x;
    wh[i] = __float2half(w[i]);
}

// ---------------------------------------------------------------------------
// Kernel 1: per-column rmsnorm scale  s[b,l] = sqrt(C)/max(||x[:,l]||, eps)
// ---------------------------------------------------------------------------
__global__ void normscale_kernel(const float* __restrict__ x,
                                 float* __restrict__ s) {
    size_t idx = (size_t)blockIdx.x * blockDim.x + threadIdx.x; // over B*L
    int b = (int)(idx >> 12);
    int l = (int)(idx & (L - 1));
    const float* xp = x + ((size_t)b * C) * L + l;
    float ss = 0.f;
#pragma unroll 8
    for (int c = 0; c < C; c++) {
        float v = xp[(size_t)c * L];
        ss += v * v;
    }
    s[idx] = SQRT_C / fmaxf(sqrtf(ss), 1e-12f);
}

// ---------------------------------------------------------------------------
// Kernel 2: xhT[b][l][c] = fp16(x[b][c][l] * s[b,l])   (g folded into w2h)
// ---------------------------------------------------------------------------
__global__ void transpose_scale_kernel(const float* __restrict__ x,
                                       const float* __restrict__ s,
                                       __half* __restrict__ xhT) {
    __shared__ float t[32][33];
    int b = blockIdx.z;
    int l0 = blockIdx.x * 32, c0 = blockIdx.y * 32;
    const float* xp = x + ((size_t)b * C + c0) * L + l0;
#pragma unroll
    for (int i = threadIdx.y; i < 32; i += 8)
        t[i][threadIdx.x] = xp[(size_t)i * L + threadIdx.x]; // t[c][l]
    __syncthreads();
    __half* op = xhT + ((size_t)b * L + l0) * C + c0;
#pragma unroll
    for (int i = threadIdx.y; i < 32; i += 8) {
        float sc = s[(size_t)b * L + l0 + i];
        op[(size_t)i * C + threadIdx.x] = __float2half(t[threadIdx.x][i] * sc);
    }
}

// ---------------------------------------------------------------------------
// Kernel 7: final RMSNorm + residual
// ---------------------------------------------------------------------------
__global__ void rmsnorm_res_kernel(const float* __restrict__ o,
                                   const float* __restrict__ g,
                                   const float* __restrict__ x,
                                   float* __restrict__ out) {
    size_t idx = (size_t)blockIdx.x * blockDim.x + threadIdx.x;
    int b = (int)(idx >> 12);
    int l = (int)(idx & (L - 1));
    size_t base = ((size_t)b * C) * L + l;
    const float* op = o + base;
    float ss = 0.f;
#pragma unroll 8
    for (int c = 0; c < C; c++) {
        float v = op[(size_t)c * L];
        ss += v * v;
    }
    float n = fmaxf(sqrtf(ss), 1e-12f);
    float scale = SQRT_C / n;
    const float* xp = x + base;
    float* dp = out + base;
#pragma unroll 8
    for (int c = 0; c < C; c++) {
        dp[(size_t)c * L] = op[(size_t)c * L] * scale * g[c] + xp[(size_t)c * L];
    }
}

// ---------------------------------------------------------------------------
// Batched fp16 tensor-core GEMM, both operands K-major fp16.
// C[bz][m][n] = sum_k A[m][k] * Bt[bz][n][k]  (+bias[m])
// A [M,K] fp16 shared across batch; Bt[bz] = Bb + bz*strideB, [N,K] fp16.
// C row stride ldc (fp32 out). 128x128 CTA, BK=32, 8 warps (2x4), 64x32 warp
// tiles, m16n8k16. smem rows padded to 40 halfs (conflict-free, verified).
// 3-stage cp.async ring.
// ---------------------------------------------------------------------------
#define H_LD 40                       // halfs per smem row (32 data + 8 pad)
#define H_TILE (128 * H_LD)           // halfs per operand tile
#define STAGES 3
#define GEMM_SMEM (STAGES * 2 * H_TILE * 2)

extern __shared__ __half sgm_h[];

__device__ __forceinline__ void gemm_load_tile(uint32_t sa, uint32_t sb, int stage,
                                               const __half* Ap, const __half* Bp,
                                               int k0, int K, int tid) {
#pragma unroll
    for (int i = 0; i < 2; i++) {
        int c = tid + i * 256;
        int row = c >> 2, kc = (c & 3) * 8;
        cp_async16(sa + (uint32_t)(stage * H_TILE + row * H_LD + kc) * 2,
                   Ap + (size_t)row * K + k0 + kc);
    }
#pragma unroll
    for (int i = 0; i < 2; i++) {
        int c = tid + i * 256;
        int row = c >> 2, kc = (c & 3) * 8;
        cp_async16(sb + (uint32_t)(stage * H_TILE + row * H_LD + kc) * 2,
                   Bp + (size_t)row * K + k0 + kc);
    }
}

__global__ __launch_bounds__(256) void gemm_f16(
    const __half* __restrict__ A, const __half* __restrict__ Bb,
    float* __restrict__ Cb, const float* __restrict__ bias,
    int K, int ldc, size_t strideB, size_t strideC) {
    __half* As = sgm_h;
    __half* Bs = sgm_h + STAGES * H_TILE;
    uint32_t sa = (uint32_t)__cvta_generic_to_shared(As);
    uint32_t sb = (uint32_t)__cvta_generic_to_shared(Bs);

    const int tid = threadIdx.x;
    const int lane = tid & 31;
    const int warp = tid >> 5;
    const int gid = lane >> 2;   // 0..7
    const int t4 = lane & 3;     // 0..3
    const int wm = warp >> 2;    // 0..1
    const int wn = warp & 3;     // 0..3

    const __half* Ap = A + (size_t)blockIdx.y * 128 * K;
    const __half* Bp = Bb + (size_t)blockIdx.z * strideB + (size_t)blockIdx.x * 128 * K;
    float* Cp = Cb + (size_t)blockIdx.z * strideC +
                (size_t)blockIdx.y * 128 * ldc + (size_t)blockIdx.x * 128;

    float acc[4][4][4];
#pragma unroll
    for (int mi = 0; mi < 4; mi++)
#pragma unroll
        for (int ni = 0; ni < 4; ni++)
#pragma unroll
            for (int r = 0; r < 4; r++) acc[mi][ni][r] = 0.f;

    const int ktiles = K >> 5;
#pragma unroll
    for (int s = 0; s < STAGES - 1; s++) {
        gemm_load_tile(sa, sb, s, Ap, Bp, s * 32, K, tid);
        cp_commit();
    }
    cp_wait<STAGES - 2>();
    __syncthreads();

    for (int kt = 0; kt < ktiles; kt++) {
        const uint32_t* Ab = (const uint32_t*)(As + (kt % STAGES) * H_TILE);
        const uint32_t* Bbuf = (const uint32_t*)(Bs + (kt % STAGES) * H_TILE);
#pragma unroll
        for (int kk = 0; kk < 2; kk++) {
            const int kb = kk * 8; // uint32 offset: 8 u32 = 16 halfs
            uint32_t af[4][4], bf[4][2];
#pragma unroll
            for (int mi = 0; mi < 4; mi++) {
                const int m0 = wm * 64 + mi * 16;
                af[mi][0] = Ab[(m0 + gid) * 20 + kb + t4];
                af[mi][1] = Ab[(m0 + gid + 8) * 20 + kb + t4];
                af[mi][2] = Ab[(m0 + gid) * 20 + kb + t4 + 4];
                af[mi][3] = Ab[(m0 + gid + 8) * 20 + kb + t4 + 4];
            }
#pragma unroll
            for (int ni = 0; ni < 4; ni++) {
                const int n0 = wn * 32 + ni * 8;
                bf[ni][0] = Bbuf[(n0 + gid) * 20 + kb + t4];
                bf[ni][1] = Bbuf[(n0 + gid) * 20 + kb + t4 + 4];
            }
#pragma unroll
            for (int mi = 0; mi < 4; mi++)
#pragma unroll
                for (int ni = 0; ni < 4; ni++)
                    mma_f16(acc[mi][ni], af[mi], bf[ni]);
        }
        int nt = kt + STAGES - 1;
        if (nt < ktiles)
            gemm_load_tile(sa, sb, nt % STAGES, Ap, Bp, nt * 32, K, tid);
        cp_commit();
        cp_wait<STAGES - 2>();
        __syncthreads();
    }

    // epilogue
#pragma unroll
    for (int mi = 0; mi < 4; mi++) {
        const int r0 = wm * 64 + mi * 16 + gid;
        const float bv0 = bias ? bias[blockIdx.y * 128 + r0] : 0.f;
        const float bv1 = bias ? bias[blockIdx.y * 128 + r0 + 8] : 0.f;
#pragma unroll
        for (int ni = 0; ni < 4; ni++) {
            const int col = wn * 32 + ni * 8 + t4 * 2;
            float2 v0 = make_float2(acc[mi][ni][0] + bv0, acc[mi][ni][1] + bv0);
            float2 v1 = make_float2(acc[mi][ni][2] + bv1, acc[mi][ni][3] + bv1);
            *(float2*)&Cp[(size_t)r0 * ldc + col] = v0;
            *(float2*)&Cp[(size_t)(r0 + 8) * ldc + col] = v1;
        }
    }
}

// ---------------------------------------------------------------------------
// Kernel 3: softmax over L for the k channels (qkv channels [512,1024)), in place.
// ---------------------------------------------------------------------------
__global__ void ksoftmax_kernel(float* __restrict__ qkv) {
    int row = blockIdx.x;           // 0..B*HIDDEN-1
    int b = row >> 9;
    int ch = row & (HIDDEN - 1);
    float* p = qkv + ((size_t)b * QKV_CH + HIDDEN + ch) * L;
    int tid = threadIdx.x;          // 256 threads, 16 elems each
    float v[16];
    float m = -INFINITY;
#pragma unroll
    for (int i = 0; i < 16; i++) {
        v[i] = p[tid + i * 256];
        m = fmaxf(m, v[i]);
    }
    __shared__ float red[256];
    red[tid] = m;
    __syncthreads();
    for (int s = 128; s > 0; s >>= 1) {
        if (tid < s) red[tid] = fmaxf(red[tid], red[tid + s]);
        __syncthreads();
    }
    m = red[0];
    __syncthreads();
    float sum = 0.f;
#pragma unroll
    for (int i = 0; i < 16; i++) {
        v[i] = expf(v[i] - m);
        sum += v[i];
    }
    red[tid] = sum;
    __syncthreads();
    for (int s = 128; s > 0; s >>= 1) {
        if (tid < s) red[tid] += red[tid + s];
        __syncthreads();
    }
    float inv = 1.f / red[0];
#pragma unroll
    for (int i = 0; i < 16; i++) p[tid + i * 256] = v[i] * inv;
}

// ---------------------------------------------------------------------------
// Kernel 4a: partial context over an L-chunk (128 cols per block).
// ---------------------------------------------------------------------------
__global__ __launch_bounds__(256) void ctx_part_kernel(const float* __restrict__ qkv,
                                                       float* __restrict__ ctxp) {
    int bh = blockIdx.x;
    int chunk = blockIdx.y;
    int b = bh >> 3, h = bh & 7;
    const float* kp = qkv + ((size_t)b * QKV_CH + HIDDEN + h * DHEAD) * L;
    const float* vp = qkv + ((size_t)b * QKV_CH + 2 * HIDDEN + h * DHEAD) * L;
    __shared__ float ks[64][68];
    __shared__ float vs[64][68];
    int tid = threadIdx.x;
    int d0 = (tid >> 4) * 4;
    int e0 = (tid & 15) * 4;
    float acc[4][4];
#pragma unroll
    for (int i = 0; i < 4; i++)
#pragma unroll
        for (int j = 0; j < 4; j++) acc[i][j] = 0.f;

    int nbeg = chunk * (L / NCHUNK);
#pragma unroll
    for (int c0 = 0; c0 < (L / NCHUNK); c0 += 64) {
        int n0 = nbeg + c0;
        for (int idx = tid; idx < 64 * 16; idx += 256) {
            int r = idx >> 4, c4 = (idx & 15) * 4;
            *(float4*)&ks[r][c4] = *(const float4*)&kp[(size_t)r * L + n0 + c4];
            *(float4*)&vs[r][c4] = *(const float4*)&vp[(size_t)r * L + n0 + c4];
        }
        __syncthreads();
#pragma unroll 4
        for (int nn = 0; nn < 64; nn++) {
            float rk[4], rv[4];
#pragma unroll
            for (int i = 0; i < 4; i++) rk[i] = ks[d0 + i][nn];
#pragma unroll
            for (int j = 0; j < 4; j++) rv[j] = vs[e0 + j][nn];
#pragma unroll
            for (int i = 0; i < 4; i++)
#pragma unroll
                for (int j = 0; j < 4; j++) acc[i][j] = fmaf(rk[i], rv[j], acc[i][j]);
        }
        __syncthreads();
    }
    float* cp = ctxp + ((size_t)chunk * (B * HEADS) + bh) * (DHEAD * DHEAD);
#pragma unroll
    for (int i = 0; i < 4; i++)
#pragma unroll
        for (int j = 0; j < 4; j++) cp[(d0 + i) * DHEAD + e0 + j] = acc[i][j];
}

// ---------------------------------------------------------------------------
// Kernel 4b: reduce NCHUNK partial contexts -> ctx
// ---------------------------------------------------------------------------
__global__ void ctx_reduce_kernel(const float* __restrict__ ctxp,
                                  float* __restrict__ ctx) {
    int i = blockIdx.x * 256 + threadIdx.x; // over B*HEADS*DHEAD*DHEAD
    float s = 0.f;
#pragma unroll
    for (int c = 0; c < NCHUNK; c++)
        s += ctxp[(size_t)c * (B * HEADS * DHEAD * DHEAD) + i];
    ctx[i] = s;
}

// ---------------------------------------------------------------------------
// Kernel 5: q-softmax (over d) fused with out[e,n] = sum_d ctx[d,e]*qs[d,n].
// Writes attnT[b][n][h*64+e] as fp16 (contiguous 128B per thread).
// ---------------------------------------------------------------------------
__global__ __launch_bounds__(128) void attn_apply_kernel(const float* __restrict__ qkv,
                                                         const float* __restrict__ ctx,
                                                         __half* __restrict__ attnT) {
    int n0 = blockIdx.x * 128;
    int bh = blockIdx.y;
    int b = bh >> 3, h = bh & 7;

    __shared__ float4 cs[64][16];   // ctx [d][e/4]
    __shared__ float qs_s[64][128]; // q tile [d][n]
    const float4* cp4 = reinterpret_cast<const float4*>(ctx + (size_t)bh * DHEAD * DHEAD);
    for (int idx = threadIdx.x; idx < 64 * 16; idx += 128)
        cs[idx >> 4][idx & 15] = cp4[idx];

    const float* qp = qkv + ((size_t)b * QKV_CH + h * DHEAD) * L + n0;
    for (int idx = threadIdx.x; idx < 64 * 128; idx += 128) {
        int d = idx >> 7, col = idx & 127;
        qs_s[d][col] = qp[(size_t)d * L + col];
    }
    __syncthreads();

    int t = threadIdx.x;
    float m = -INFINITY;
#pragma unroll 8
    for (int d = 0; d < DHEAD; d++) m = fmaxf(m, qs_s[d][t]);
    float sum = 0.f;
#pragma unroll 8
    for (int d = 0; d < DHEAD; d++) sum += expf(qs_s[d][t] - m);
    float inv = ATTN_SCALE / sum;

    float4 acc[16];
#pragma unroll
    for (int e = 0; e < 16; e++) acc[e] = make_float4(0.f, 0.f, 0.f, 0.f);

#pragma unroll 4
    for (int d = 0; d < DHEAD; d++) {
        float qv = expf(qs_s[d][t] - m) * inv;
#pragma unroll
        for (int e = 0; e < 16; e++) {
            float4 c4 = cs[d][e];
            acc[e].x = fmaf(c4.x, qv, acc[e].x);
            acc[e].y = fmaf(c4.y, qv, acc[e].y);
            acc[e].z = fmaf(c4.z, qv, acc[e].z);
            acc[e].w = fmaf(c4.w, qv, acc[e].w);
        }
    }

    __half* op = attnT + ((size_t)b * L + n0 + t) * HIDDEN + h * DHEAD;
#pragma unroll
    for (int e = 0; e < 16; e++) {
        __half2 h0 = __floats2half2_rn(acc[e].x, acc[e].y);
        __half2 h1 = __floats2half2_rn(acc[e].z, acc[e].w);
        *(uint2*)&op[e * 4] = make_uint2(*(uint32_t*)&h0, *(uint32_t*)&h1);
    }
}

// ---------------------------------------------------------------------------
extern "C" void kernel_launch(void* const* d_in, const int* in_sizes, int n_in,
                              void* d_out, int out_size) {
    const float* x     = (const float*)d_in[0];
    const float* g_in  = (const float*)d_in[1];
    const float* w_qkv = (const float*)d_in[2];
    const float* w_out = (const float*)d_in[3];
    const float* b_out = (const float*)d_in[4];
    const float* g_out = (const float*)d_in[5];
    float* out = (float*)d_out;

    __half *w2h, *wouth, *xhT, *attnT;
    float *s, *qkv, *ctxp, *ctx, *o;
    cudaGetSymbolAddress((void**)&w2h, g_w2h);
    cudaGetSymbolAddress((void**)&wouth, g_wouth);
    cudaGetSymbolAddress((void**)&s, g_s);
    cudaGetSymbolAddress((void**)&xhT, g_xhT);
    cudaGetSymbolAddress((void**)&qkv, g_qkv);
    cudaGetSymbolAddress((void**)&ctxp, g_ctxp);
    cudaGetSymbolAddress((void**)&ctx, g_ctx);
    cudaGetSymbolAddress((void**)&attnT, g_attnT);
    cudaGetSymbolAddress((void**)&o, g_o);

    cudaFuncSetAttribute(gemm_f16, cudaFuncAttributeMaxDynamicSharedMemorySize,
                         GEMM_SMEM);

    // 0. weight conversions
    convert_wqkv_kernel<<<(QKV_CH * C) / 256, 256>>>(w_qkv, g_in, w2h);
    convert_wout_kernel<<<(C * HIDDEN) / 256, 256>>>(w_out, wouth);

    // 1. per-column rmsnorm scales
    normscale_kernel<<<(B * L) / 256, 256>>>(x, s);

    // 2. xhT[b][l][c] = fp16(x[b][c][l] * s)
    transpose_scale_kernel<<<dim3(L / 32, C / 32, B), dim3(32, 8)>>>(x, s, xhT);

    // 3. qkv = w2h @ xn   (fp16 HMMA)
    gemm_f16<<<dim3(L / 128, QKV_CH / 128, B), 256, GEMM_SMEM>>>(
        w2h, xhT, qkv, nullptr, C, L, (size_t)L * C, (size_t)QKV_CH * L);

    // 4. k softmax over L (in place)
    ksoftmax_kernel<<<B * HIDDEN, 256>>>(qkv);

    // 5. context = k @ v^T per (b,h), split over L then reduced
    ctx_part_kernel<<<dim3(B * HEADS, NCHUNK), 256>>>(qkv, ctxp);
    ctx_reduce_kernel<<<(B * HEADS * DHEAD * DHEAD) / 256, 256>>>(ctxp, ctx);

    // 6. attnT = (ctx^T @ softmax_d(q)*scale)^T  -> fp16 [b][l][e]
    attn_apply_kernel<<<dim3(L / 128, B * HEADS), 128>>>(qkv, ctx, attnT);

    // 7. o = wouth @ attn + b_out  (fp16 HMMA)
    gemm_f16<<<dim3(L / 128, C / 128, B), 256, GEMM_SMEM>>>(
        wouth, attnT, o, b_out, HIDDEN, L, (size_t)L * HIDDEN, (size_t)C * L);

    // 8. RMSNorm(o) + residual -> out
    rmsnorm_res_kernel<<<(B * L) / 256, 256>>>(o, g_out, x, out);
}

// round 7
// speedup vs baseline: 3.7148x; 1.2118x over previous
#include <cuda_runtime.h>
#include <cuda_fp16.h>
#include <math.h>
#include <stdint.h>

// Problem constants
#define B 8
#define C 512
#define L 4096
#define HEADS 8
#define DHEAD 64
#define HIDDEN 512           // HEADS*DHEAD
#define QKV_CH 1536          // 3*HIDDEN
#define SQRT_C 22.627416998f // sqrt(512)
#define ATTN_SCALE 0.125f    // 64^-0.5
#define NCHUNK 32            // ctx split factor over L

// Scratch buffers
__device__ __half g_w2h[(size_t)QKV_CH * C];        // w_qkv * g_in, fp16
__device__ __half g_wouth[(size_t)C * HIDDEN];
__device__ __half g_xhT[(size_t)B * L * C];         // (x*s)^T fp16 [b][l][c]
__device__ float  g_qkv[(size_t)B * QKV_CH * L];    // 192 MB
__device__ float  g_ctxp[(size_t)NCHUNK * B * HEADS * DHEAD * DHEAD];
__device__ float  g_ctx[(size_t)B * HEADS * DHEAD * DHEAD];
__device__ __half g_attnT[(size_t)B * L * HIDDEN];  // fp16 [b][l][e]

// ---------------------------------------------------------------------------
// PTX helpers
// ---------------------------------------------------------------------------
__device__ __forceinline__ void cp_async16(uint32_t dst, const void* src) {
    asm volatile("cp.async.cg.shared.global [%0], [%1], 16;" :: "r"(dst), "l"(src));
}
__device__ __forceinline__ void cp_commit() {
    asm volatile("cp.async.commit_group;");
}
template <int N>
__device__ __forceinline__ void cp_wait() {
    asm volatile("cp.async.wait_group %0;" :: "n"(N));
}
__device__ __forceinline__ void ldsm_x4(uint32_t r[4], uint32_t addr) {
    asm volatile("ldmatrix.sync.aligned.m8n8.x4.shared.b16 {%0,%1,%2,%3}, [%4];"
                 : "=r"(r[0]), "=r"(r[1]), "=r"(r[2]), "=r"(r[3]) : "r"(addr));
}
__device__ __forceinline__ void mma_f16(float d[4], const uint32_t a[4],
                                        const uint32_t b[2]) {
    asm volatile(
        "mma.sync.aligned.m16n8k16.row.col.f32.f16.f16.f32 "
        "{%0,%1,%2,%3}, {%4,%5,%6,%7}, {%8,%9}, {%0,%1,%2,%3};"
        : "+f"(d[0]), "+f"(d[1]), "+f"(d[2]), "+f"(d[3])
        : "r"(a[0]), "r"(a[1]), "r"(a[2]), "r"(a[3]),
          "r"(b[0]), "r"(b[1]));
}

// ---------------------------------------------------------------------------
// Weight conversions
// ---------------------------------------------------------------------------
__global__ void convert_wqkv_kernel(const float* __restrict__ w,
                                    const float* __restrict__ g,
                                    __half* __restrict__ w2h) {
    int i = blockIdx.x * 256 + threadIdx.x;
    w2h[i] = __float2half(w[i] * g[i & (C - 1)]);
}
__global__ void convert_wout_kernel(const float* __restrict__ w,
                                    __half* __restrict__ wh) {
    int i = blockIdx.x * 256 + threadIdx.x;
    wh[i] = __float2half(w[i]);
}

// ---------------------------------------------------------------------------
// Fused rmsnorm-scale + transpose: xhT[b][l][c] = fp16(x[b][c][l] * s[b,l])
// One block per 32 l's; x read exactly once.
// ---------------------------------------------------------------------------
#define NX_SMEM (512 * 33 * 4)
extern __shared__ float nx_sm[];
__global__ __launch_bounds__(256) void normxpose_kernel(const float* __restrict__ x,
                                                        __half* __restrict__ xhT) {
    float* t = nx_sm;               // t[c*33 + l]
    __shared__ float sc[32];
    int b = blockIdx.y;
    int l0 = blockIdx.x * 32;
    int tid = threadIdx.x;
    const float* xp = x + ((size_t)b * C) * L + l0;
#pragma unroll
    for (int i = 0; i < 64; i++) {
        int flat = i * 256 + tid;
        int c = flat >> 5, l = flat & 31;
        t[c * 33 + l] = xp[(size_t)c * L + l];
    }
    __syncthreads();
    int warp = tid >> 5, lane = tid & 31;
#pragma unroll
    for (int li = 0; li < 4; li++) {
        int l = warp * 4 + li;
        float ss = 0.f;
#pragma unroll
        for (int ci = 0; ci < 16; ci++) {
            float v = t[(ci * 32 + lane) * 33 + l];
            ss += v * v;
        }
#pragma unroll
        for (int off = 16; off > 0; off >>= 1)
            ss += __shfl_xor_sync(0xFFFFFFFFu, ss, off);
        if (lane == 0) sc[l] = SQRT_C / fmaxf(sqrtf(ss), 1e-12f);
    }
    __syncthreads();
    __half* op = xhT + ((size_t)b * L + l0) * C;
#pragma unroll
    for (int i = 0; i < 64; i++) {
        int flat = i * 256 + tid;
        int l = flat >> 9, c = flat & 511;
        op[(size_t)l * C + c] = __float2half(t[c * 33 + l] * sc[l]);
    }
}

// ---------------------------------------------------------------------------
// QKV GEMM: fp16 HMMA + ldmatrix, both operands K-major.
// qkv[bz][m][n] = sum_k w2h[m][k] * xhT[bz][n][k]
// 128x128 CTA, BK=32, 8 warps (2x4), 64x32 warp tiles, 3-stage cp.async.
// ---------------------------------------------------------------------------
#define H_LD 40
#define H_TILEB (128 * H_LD * 2)      // bytes per operand stage
#define STAGES 3
#define GEMM_SMEM (STAGES * 2 * H_TILEB)

extern __shared__ __half sgm_h[];

__device__ __forceinline__ void qkv_load_tile(uint32_t sa, uint32_t sb, int stage,
                                              const __half* Ap, const __half* Bp,
                                              int k0, int K, int tid) {
#pragma unroll
    for (int i = 0; i < 2; i++) {
        int c = tid + i * 256;
        int row = c >> 2, kc = (c & 3) * 8;
        cp_async16(sa + stage * H_TILEB + (row * H_LD + kc) * 2,
                   Ap + (size_t)row * K + k0 + kc);
    }
#pragma unroll
    for (int i = 0; i < 2; i++) {
        int c = tid + i * 256;
        int row = c >> 2, kc = (c & 3) * 8;
        cp_async16(sb + stage * H_TILEB + (row * H_LD + kc) * 2,
                   Bp + (size_t)row * K + k0 + kc);
    }
}

__global__ __launch_bounds__(256) void gemm_qkv(
    const __half* __restrict__ A, const __half* __restrict__ Bb,
    float* __restrict__ Cb, int K, int ldc, size_t strideB, size_t strideC) {
    uint32_t sa = (uint32_t)__cvta_generic_to_shared(sgm_h);
    uint32_t sb = sa + STAGES * H_TILEB;

    const int tid = threadIdx.x;
    const int lane = tid & 31;
    const int warp = tid >> 5;
    const int gid = lane >> 2;
    const int t4 = lane & 3;
    const int wm = warp >> 2;    // 0..1
    const int wn = warp & 3;     // 0..3
    const int t8 = lane >> 3;    // ldmatrix tile select
    const int r8 = lane & 7;

    const __half* Ap = A + (size_t)blockIdx.y * 128 * K;
    const __half* Bp = Bb + (size_t)blockIdx.z * strideB + (size_t)blockIdx.x * 128 * K;
    float* Cp = Cb + (size_t)blockIdx.z * strideC +
                (size_t)blockIdx.y * 128 * ldc + (size_t)blockIdx.x * 128;

    float acc[4][4][4];
#pragma unroll
    for (int mi = 0; mi < 4; mi++)
#pragma unroll
        for (int ni = 0; ni < 4; ni++)
#pragma unroll
            for (int r = 0; r < 4; r++) acc[mi][ni][r] = 0.f;

    const int ktiles = K >> 5;
#pragma unroll
    for (int s = 0; s < STAGES - 1; s++) {
        qkv_load_tile(sa, sb, s, Ap, Bp, s * 32, K, tid);
        cp_commit();
    }
    cp_wait<STAGES - 2>();
    __syncthreads();

    for (int kt = 0; kt < ktiles; kt++) {
        uint32_t abase = sa + (kt % STAGES) * H_TILEB;
        uint32_t bbase = sb + (kt % STAGES) * H_TILEB;
#pragma unroll
        for (int kk = 0; kk < 2; kk++) {
            const int kbh = kk * 16;
            uint32_t af[4][4], bf[4][2];
#pragma unroll
            for (int mi = 0; mi < 4; mi++) {
                int row = wm * 64 + mi * 16 + r8 + (t8 & 1) * 8;
                int col = kbh + (t8 >> 1) * 8;
                ldsm_x4(af[mi], abase + (row * H_LD + col) * 2);
            }
#pragma unroll
            for (int np = 0; np < 2; np++) {
                int row = wn * 32 + np * 16 + r8 + (t8 >> 1) * 8;
                int col = kbh + (t8 & 1) * 8;
                uint32_t r4[4];
                ldsm_x4(r4, bbase + (row * H_LD + col) * 2);
                bf[np * 2][0] = r4[0]; bf[np * 2][1] = r4[1];
                bf[np * 2 + 1][0] = r4[2]; bf[np * 2 + 1][1] = r4[3];
            }
#pragma unroll
            for (int mi = 0; mi < 4; mi++)
#pragma unroll
                for (int ni = 0; ni < 4; ni++)
                    mma_f16(acc[mi][ni], af[mi], bf[ni]);
        }
        int nt = kt + STAGES - 1;
        if (nt < ktiles)
            qkv_load_tile(sa, sb, nt % STAGES, Ap, Bp, nt * 32, K, tid);
        cp_commit();
        cp_wait<STAGES - 2>();
        __syncthreads();
    }

#pragma unroll
    for (int mi = 0; mi < 4; mi++) {
        const int r0 = wm * 64 + mi * 16 + gid;
#pragma unroll
        for (int ni = 0; ni < 4; ni++) {
            const int col = wn * 32 + ni * 8 + t4 * 2;
            *(float2*)&Cp[(size_t)r0 * ldc + col] =
                make_float2(acc[mi][ni][0], acc[mi][ni][1]);
            *(float2*)&Cp[(size_t)(r0 + 8) * ldc + col] =
                make_float2(acc[mi][ni][2], acc[mi][ni][3]);
        }
    }
}

// ---------------------------------------------------------------------------
// Fused out-GEMM + bias + channel RMSNorm + residual.
// CTA computes full M=512 x N=32 tile (K=512): o = wouth @ attnT^T + b_out,
// then per-column scale = sqrt(C)/||o||, out = o*scale*g_out + x.
// 2-stage cp.async; 8 warps each 64x32.
// ---------------------------------------------------------------------------
#define OA_BYTES (512 * H_LD * 2)
#define OB_BYTES (32 * H_LD * 2)
#define OSTG_BYTES (OA_BYTES + OB_BYTES)
#define OUT_SMEM (2 * OSTG_BYTES)

__global__ __launch_bounds__(256) void gemm_out_fused(
    const __half* __restrict__ A, const __half* __restrict__ Bb,
    const float* __restrict__ bias, const float* __restrict__ gout,
    const float* __restrict__ x, float* __restrict__ out) {
    __shared__ float colsum[32];
    uint32_t sbase = (uint32_t)__cvta_generic_to_shared(sgm_h);

    const int tid = threadIdx.x;
    const int lane = tid & 31;
    const int warp = tid >> 5;     // 0..7 = m block
    const int gid = lane >> 2;
    const int t4 = lane & 3;
    const int t8 = lane >> 3;
    const int r8 = lane & 7;
    const int bz = blockIdx.y;
    const int l0 = blockIdx.x * 32;

    const __half* Bp = Bb + ((size_t)bz * L + l0) * HIDDEN;

    float acc[4][4][4];
#pragma unroll
    for (int mi = 0; mi < 4; mi++)
#pragma unroll
        for (int ni = 0; ni < 4; ni++)
#pragma unroll
            for (int r = 0; r < 4; r++) acc[mi][ni][r] = 0.f;

    // stage loaders
    auto load_stage = [&](int kt, int buf) {
        uint32_t sA = sbase + buf * OSTG_BYTES;
        uint32_t sB = sA + OA_BYTES;
        int k0 = kt * 32;
#pragma unroll
        for (int i = 0; i < 8; i++) {
            int c = tid + i * 256;
            int row = c >> 2, kc = (c & 3) * 8;
            cp_async16(sA + (row * H_LD + kc) * 2, A + (size_t)row * HIDDEN + k0 + kc);
        }
        if (tid < 128) {
            int row = tid >> 2, kc = (tid & 3) * 8;
            cp_async16(sB + (row * H_LD + kc) * 2, Bp + (size_t)row * HIDDEN + k0 + kc);
        }
    };

    load_stage(0, 0);
    cp_commit();
    cp_wait<0>();
    __syncthreads();

    const int ktiles = HIDDEN >> 5; // 16
    for (int kt = 0; kt < ktiles; kt++) {
        if (kt + 1 < ktiles) {
            load_stage(kt + 1, (kt + 1) & 1);
            cp_commit();
        }
        uint32_t abase = sbase + (kt & 1) * OSTG_BYTES;
        uint32_t bbase = abase + OA_BYTES;
#pragma unroll
        for (int kk = 0; kk < 2; kk++) {
            const int kbh = kk * 16;
            uint32_t af[4][4], bf[4][2];
#pragma unroll
            for (int mi = 0; mi < 4; mi++) {
                int row = warp * 64 + mi * 16 + r8 + (t8 & 1) * 8;
                int col = kbh + (t8 >> 1) * 8;
                ldsm_x4(af[mi], abase + (row * H_LD + col) * 2);
            }
#pragma unroll
            for (int np = 0; np < 2; np++) {
                int row = np * 16 + r8 + (t8 >> 1) * 8;
                int col = kbh + (t8 & 1) * 8;
                uint32_t r4[4];
                ldsm_x4(r4, bbase + (row * H_LD + col) * 2);
                bf[np * 2][0] = r4[0]; bf[np * 2][1] = r4[1];
                bf[np * 2 + 1][0] = r4[2]; bf[np * 2 + 1][1] = r4[3];
            }
#pragma unroll
            for (int mi = 0; mi < 4; mi++)
#pragma unroll
                for (int ni = 0; ni < 4; ni++)
                    mma_f16(acc[mi][ni], af[mi], bf[ni]);
        }
        cp_wait<0>();
        __syncthreads();
    }

    // --- fused epilogue ---
    // add bias, accumulate per-column sum of squares
    float bvs[4][2];
#pragma unroll
    for (int mi = 0; mi < 4; mi++) {
        int r0 = warp * 64 + mi * 16 + gid;
        bvs[mi][0] = bias[r0];
        bvs[mi][1] = bias[r0 + 8];
    }
    if (tid < 32) colsum[tid] = 0.f;
    __syncthreads();

#pragma unroll
    for (int ni = 0; ni < 4; ni++) {
#pragma unroll
        for (int c01 = 0; c01 < 2; c01++) {
            float part = 0.f;
#pragma unroll
            for (int mi = 0; mi < 4; mi++) {
                float v0 = acc[mi][ni][c01] + bvs[mi][0];
                float v1 = acc[mi][ni][2 + c01] + bvs[mi][1];
                acc[mi][ni][c01] = v0;        // store biased value back
                acc[mi][ni][2 + c01] = v1;
                part += v0 * v0 + v1 * v1;
            }
            part += __shfl_xor_sync(0xFFFFFFFFu, part, 4);
            part += __shfl_xor_sync(0xFFFFFFFFu, part, 8);
            part += __shfl_xor_sync(0xFFFFFFFFu, part, 16);
            if (gid == 0) atomicAdd(&colsum[ni * 8 + t4 * 2 + c01], part);
        }
    }
    __syncthreads();

    float scl[4][2];
#pragma unroll
    for (int ni = 0; ni < 4; ni++) {
        int col = ni * 8 + t4 * 2;
        scl[ni][0] = SQRT_C / fmaxf(sqrtf(colsum[col]), 1e-12f);
        scl[ni][1] = SQRT_C / fmaxf(sqrtf(colsum[col + 1]), 1e-12f);
    }

#pragma unroll
    for (int mi = 0; mi < 4; mi++) {
        int r0 = warp * 64 + mi * 16 + gid;
        float g0 = gout[r0], g1 = gout[r0 + 8];
        const float* xr0 = x + ((size_t)bz * C + r0) * L + l0;
        const float* xr1 = x + ((size_t)bz * C + r0 + 8) * L + l0;
        float* or0 = out + ((size_t)bz * C + r0) * L + l0;
        float* or1 = out + ((size_t)bz * C + r0 + 8) * L + l0;
#pragma unroll
        for (int ni = 0; ni < 4; ni++) {
            int col = ni * 8 + t4 * 2;
            float2 xv0 = *(const float2*)&xr0[col];
            float2 xv1 = *(const float2*)&xr1[col];
            float2 v0 = make_float2(acc[mi][ni][0] * scl[ni][0] * g0 + xv0.x,
                                    acc[mi][ni][1] * scl[ni][1] * g0 + xv0.y);
            float2 v1 = make_float2(acc[mi][ni][2] * scl[ni][0] * g1 + xv1.x,
                                    acc[mi][ni][3] * scl[ni][1] * g1 + xv1.y);
            *(float2*)&or0[col] = v0;
            *(float2*)&or1[col] = v1;
        }
    }
}

// ---------------------------------------------------------------------------
// k softmax over L (in place)
// ---------------------------------------------------------------------------
__global__ void ksoftmax_kernel(float* __restrict__ qkv) {
    int row = blockIdx.x;
    int b = row >> 9;
    int ch = row & (HIDDEN - 1);
    float* p = qkv + ((size_t)b * QKV_CH + HIDDEN + ch) * L;
    int tid = threadIdx.x;
    float v[16];
    float m = -INFINITY;
#pragma unroll
    for (int i = 0; i < 16; i++) {
        v[i] = p[tid + i * 256];
        m = fmaxf(m, v[i]);
    }
    __shared__ float red[256];
    red[tid] = m;
    __syncthreads();
    for (int s = 128; s > 0; s >>= 1) {
        if (tid < s) red[tid] = fmaxf(red[tid], red[tid + s]);
        __syncthreads();
    }
    m = red[0];
    __syncthreads();
    float sum = 0.f;
#pragma unroll
    for (int i = 0; i < 16; i++) {
        v[i] = expf(v[i] - m);
        sum += v[i];
    }
    red[tid] = sum;
    __syncthreads();
    for (int s = 128; s > 0; s >>= 1) {
        if (tid < s) red[tid] += red[tid + s];
        __syncthreads();
    }
    float inv = 1.f / red[0];
#pragma unroll
    for (int i = 0; i < 16; i++) p[tid + i * 256] = v[i] * inv;
}

// ---------------------------------------------------------------------------
// partial context over an L-chunk
// ---------------------------------------------------------------------------
__global__ __launch_bounds__(256) void ctx_part_kernel(const float* __restrict__ qkv,
                                                       float* __restrict__ ctxp) {
    int bh = blockIdx.x;
    int chunk = blockIdx.y;
    int b = bh >> 3, h = bh & 7;
    const float* kp = qkv + ((size_t)b * QKV_CH + HIDDEN + h * DHEAD) * L;
    const float* vp = qkv + ((size_t)b * QKV_CH + 2 * HIDDEN + h * DHEAD) * L;
    __shared__ float ks[64][68];
    __shared__ float vs[64][68];
    int tid = threadIdx.x;
    int d0 = (tid >> 4) * 4;
    int e0 = (tid & 15) * 4;
    float acc[4][4];
#pragma unroll
    for (int i = 0; i < 4; i++)
#pragma unroll
        for (int j = 0; j < 4; j++) acc[i][j] = 0.f;

    int nbeg = chunk * (L / NCHUNK);
#pragma unroll
    for (int c0 = 0; c0 < (L / NCHUNK); c0 += 64) {
        int n0 = nbeg + c0;
        for (int idx = tid; idx < 64 * 16; idx += 256) {
            int r = idx >> 4, c4 = (idx & 15) * 4;
            *(float4*)&ks[r][c4] = *(const float4*)&kp[(size_t)r * L + n0 + c4];
            *(float4*)&vs[r][c4] = *(const float4*)&vp[(size_t)r * L + n0 + c4];
        }
        __syncthreads();
#pragma unroll 4
        for (int nn = 0; nn < 64; nn++) {
            float rk[4], rv[4];
#pragma unroll
            for (int i = 0; i < 4; i++) rk[i] = ks[d0 + i][nn];
#pragma unroll
            for (int j = 0; j < 4; j++) rv[j] = vs[e0 + j][nn];
#pragma unroll
            for (int i = 0; i < 4; i++)
#pragma unroll
                for (int j = 0; j < 4; j++) acc[i][j] = fmaf(rk[i], rv[j], acc[i][j]);
        }
        __syncthreads();
    }
    float* cp = ctxp + ((size_t)chunk * (B * HEADS) + bh) * (DHEAD * DHEAD);
#pragma unroll
    for (int i = 0; i < 4; i++)
#pragma unroll
        for (int j = 0; j < 4; j++) cp[(d0 + i) * DHEAD + e0 + j] = acc[i][j];
}

__global__ void ctx_reduce_kernel(const float* __restrict__ ctxp,
                                  float* __restrict__ ctx) {
    int i = blockIdx.x * 256 + threadIdx.x;
    float s = 0.f;
#pragma unroll
    for (int c = 0; c < NCHUNK; c++)
        s += ctxp[(size_t)c * (B * HEADS * DHEAD * DHEAD) + i];
    ctx[i] = s;
}

// ---------------------------------------------------------------------------
// q-softmax + ctx apply -> attnT[b][l][e] fp16
// ---------------------------------------------------------------------------
__global__ __launch_bounds__(128) void attn_apply_kernel(const float* __restrict__ qkv,
                                                         const float* __restrict__ ctx,
                                                         __half* __restrict__ attnT) {
    int n0 = blockIdx.x * 128;
    int bh = blockIdx.y;
    int b = bh >> 3, h = bh & 7;

    __shared__ float4 cs[64][16];
    __shared__ float qs_s[64][128];
    const float4* cp4 = reinterpret_cast<const float4*>(ctx + (size_t)bh * DHEAD * DHEAD);
    for (int idx = threadIdx.x; idx < 64 * 16; idx += 128)
        cs[idx >> 4][idx & 15] = cp4[idx];

    const float* qp = qkv + ((size_t)b * QKV_CH + h * DHEAD) * L + n0;
    for (int idx = threadIdx.x; idx < 64 * 128; idx += 128) {
        int d = idx >> 7, col = idx & 127;
        qs_s[d][col] = qp[(size_t)d * L + col];
    }
    __syncthreads();

    int t = threadIdx.x;
    float m = -INFINITY;
#pragma unroll 8
    for (int d = 0; d < DHEAD; d++) m = fmaxf(m, qs_s[d][t]);
    float sum = 0.f;
#pragma unroll 8
    for (int d = 0; d < DHEAD; d++) sum += expf(qs_s[d][t] - m);
    float inv = ATTN_SCALE / sum;

    float4 acc[16];
#pragma unroll
    for (int e = 0; e < 16; e++) acc[e] = make_float4(0.f, 0.f, 0.f, 0.f);

#pragma unroll 4
    for (int d = 0; d < DHEAD; d++) {
        float qv = expf(qs_s[d][t] - m) * inv;
#pragma unroll
        for (int e = 0; e < 16; e++) {
            float4 c4 = cs[d][e];
            acc[e].x = fmaf(c4.x, qv, acc[e].x);
            acc[e].y = fmaf(c4.y, qv, acc[e].y);
            acc[e].z = fmaf(c4.z, qv, acc[e].z);
            acc[e].w = fmaf(c4.w, qv, acc[e].w);
        }
    }

    __half* op = attnT + ((size_t)b * L + n0 + t) * HIDDEN + h * DHEAD;
#pragma unroll
    for (int e = 0; e < 16; e++) {
        __half2 h0 = __floats2half2_rn(acc[e].x, acc[e].y);
        __half2 h1 = __floats2half2_rn(acc[e].z, acc[e].w);
        *(uint2*)&op[e * 4] = make_uint2(*(uint32_t*)&h0, *(uint32_t*)&h1);
    }
}

// ---------------------------------------------------------------------------
extern "C" void kernel_launch(void* const* d_in, const int* in_sizes, int n_in,
                              void* d_out, int out_size) {
    const float* x     = (const float*)d_in[0];
    const float* g_in  = (const float*)d_in[1];
    const float* w_qkv = (const float*)d_in[2];
    const float* w_out = (const float*)d_in[3];
    const float* b_out = (const float*)d_in[4];
    const float* g_out = (const float*)d_in[5];
    float* out = (float*)d_out;

    __half *w2h, *wouth, *xhT, *attnT;
    float *qkv, *ctxp, *ctx;
    cudaGetSymbolAddress((void**)&w2h, g_w2h);
    cudaGetSymbolAddress((void**)&wouth, g_wouth);
    cudaGetSymbolAddress((void**)&xhT, g_xhT);
    cudaGetSymbolAddress((void**)&qkv, g_qkv);
    cudaGetSymbolAddress((void**)&ctxp, g_ctxp);
    cudaGetSymbolAddress((void**)&ctx, g_ctx);
    cudaGetSymbolAddress((void**)&attnT, g_attnT);

    cudaFuncSetAttribute(normxpose_kernel, cudaFuncAttributeMaxDynamicSharedMemorySize,
                         NX_SMEM);
    cudaFuncSetAttribute(gemm_qkv, cudaFuncAttributeMaxDynamicSharedMemorySize,
                         GEMM_SMEM);
    cudaFuncSetAttribute(gemm_out_fused, cudaFuncAttributeMaxDynamicSharedMemorySize,
                         OUT_SMEM);

    // 0. weight conversions
    convert_wqkv_kernel<<<(QKV_CH * C) / 256, 256>>>(w_qkv, g_in, w2h);
    convert_wout_kernel<<<(C * HIDDEN) / 256, 256>>>(w_out, wouth);

    // 1. fused rmsnorm scale + transpose -> xhT fp16
    normxpose_kernel<<<dim3(L / 32, B), 256, NX_SMEM>>>(x, xhT);

    // 2. qkv = w2h @ xn   (fp16 HMMA + ldmatrix)
    gemm_qkv<<<dim3(L / 128, QKV_CH / 128, B), 256, GEMM_SMEM>>>(
        w2h, xhT, qkv, C, L, (size_t)L * C, (size_t)QKV_CH * L);

    // 3. k softmax over L
    ksoftmax_kernel<<<B * HIDDEN, 256>>>(qkv);

    // 4. context per (b,h)
    ctx_part_kernel<<<dim3(B * HEADS, NCHUNK), 256>>>(qkv, ctxp);
    ctx_reduce_kernel<<<(B * HEADS * DHEAD * DHEAD) / 256, 256>>>(ctxp, ctx);

    // 5. attnT fp16
    attn_apply_kernel<<<dim3(L / 128, B * HEADS), 128>>>(qkv, ctx, attnT);

    // 6. out = rmsnorm(wouth @ attn + b_out)*g_out + x   (fully fused)
    gemm_out_fused<<<dim3(L / 32, B), 256, OUT_SMEM>>>(
        wouth, attnT, b_out, g_out, x, out);
}

// round 8
// speedup vs baseline: 3.7841x; 1.0186x over previous
#include <cuda_runtime.h>
#include <cuda_fp16.h>
#include <math.h>
#include <stdint.h>

// Problem constants
#define B 8
#define C 512
#define L 4096
#define HEADS 8
#define DHEAD 64
#define HIDDEN 512           // HEADS*DHEAD
#define QKV_CH 1536          // 3*HIDDEN
#define SQRT_C 22.627416998f // sqrt(512)
#define ATTN_SCALE 0.125f    // 64^-0.5
#define NCHUNK 32            // ctx split factor over L

// Scratch buffers
__device__ __half g_w2h[(size_t)QKV_CH * C];        // w_qkv * g_in, fp16
__device__ __half g_wouth[(size_t)C * HIDDEN];
__device__ __half g_xhT[(size_t)B * L * C];         // (x*s)^T fp16 [b][l][c]
__device__ __half g_qkvh[(size_t)B * QKV_CH * L];   // 96 MB fp16 [b][ch][l]
__device__ float  g_ctxp[(size_t)NCHUNK * B * HEADS * DHEAD * DHEAD];
__device__ float  g_ctx[(size_t)B * HEADS * DHEAD * DHEAD];
__device__ __half g_attnT[(size_t)B * L * HIDDEN];  // fp16 [b][l][e]

// ---------------------------------------------------------------------------
// PTX helpers
// ---------------------------------------------------------------------------
__device__ __forceinline__ void cp_async16(uint32_t dst, const void* src) {
    asm volatile("cp.async.cg.shared.global [%0], [%1], 16;" :: "r"(dst), "l"(src));
}
__device__ __forceinline__ void cp_commit() {
    asm volatile("cp.async.commit_group;");
}
template <int N>
__device__ __forceinline__ void cp_wait() {
    asm volatile("cp.async.wait_group %0;" :: "n"(N));
}
__device__ __forceinline__ void ldsm_x4(uint32_t r[4], uint32_t addr) {
    asm volatile("ldmatrix.sync.aligned.m8n8.x4.shared.b16 {%0,%1,%2,%3}, [%4];"
                 : "=r"(r[0]), "=r"(r[1]), "=r"(r[2]), "=r"(r[3]) : "r"(addr));
}
__device__ __forceinline__ void mma_f16(float d[4], const uint32_t a[4],
                                        const uint32_t b[2]) {
    asm volatile(
        "mma.sync.aligned.m16n8k16.row.col.f32.f16.f16.f32 "
        "{%0,%1,%2,%3}, {%4,%5,%6,%7}, {%8,%9}, {%0,%1,%2,%3};"
        : "+f"(d[0]), "+f"(d[1]), "+f"(d[2]), "+f"(d[3])
        : "r"(a[0]), "r"(a[1]), "r"(a[2]), "r"(a[3]),
          "r"(b[0]), "r"(b[1]));
}

// ---------------------------------------------------------------------------
// Weight conversions
// ---------------------------------------------------------------------------
__global__ void convert_wqkv_kernel(const float* __restrict__ w,
                                    const float* __restrict__ g,
                                    __half* __restrict__ w2h) {
    int i = blockIdx.x * 256 + threadIdx.x;
    w2h[i] = __float2half(w[i] * g[i & (C - 1)]);
}
__global__ void convert_wout_kernel(const float* __restrict__ w,
                                    __half* __restrict__ wh) {
    int i = blockIdx.x * 256 + threadIdx.x;
    wh[i] = __float2half(w[i]);
}

// ---------------------------------------------------------------------------
// Fused rmsnorm-scale + transpose: xhT[b][l][c] = fp16(x[b][c][l] * s[b,l])
// ---------------------------------------------------------------------------
#define NX_SMEM (512 * 33 * 4)
extern __shared__ float nx_sm[];
__global__ __launch_bounds__(256) void normxpose_kernel(const float* __restrict__ x,
                                                        __half* __restrict__ xhT) {
    float* t = nx_sm;               // t[c*33 + l]
    __shared__ float sc[32];
    int b = blockIdx.y;
    int l0 = blockIdx.x * 32;
    int tid = threadIdx.x;
    const float* xp = x + ((size_t)b * C) * L + l0;
#pragma unroll
    for (int i = 0; i < 64; i++) {
        int flat = i * 256 + tid;
        int c = flat >> 5, l = flat & 31;
        t[c * 33 + l] = xp[(size_t)c * L + l];
    }
    __syncthreads();
    int warp = tid >> 5, lane = tid & 31;
#pragma unroll
    for (int li = 0; li < 4; li++) {
        int l = warp * 4 + li;
        float ss = 0.f;
#pragma unroll
        for (int ci = 0; ci < 16; ci++) {
            float v = t[(ci * 32 + lane) * 33 + l];
            ss += v * v;
        }
#pragma unroll
        for (int off = 16; off > 0; off >>= 1)
            ss += __shfl_xor_sync(0xFFFFFFFFu, ss, off);
        if (lane == 0) sc[l] = SQRT_C / fmaxf(sqrtf(ss), 1e-12f);
    }
    __syncthreads();
    __half* op = xhT + ((size_t)b * L + l0) * C;
#pragma unroll
    for (int i = 0; i < 64; i++) {
        int flat = i * 256 + tid;
        int l = flat >> 9, c = flat & 511;
        op[(size_t)l * C + c] = __float2half(t[c * 33 + l] * sc[l]);
    }
}

// ---------------------------------------------------------------------------
// QKV GEMM: fp16 HMMA + ldmatrix, K-major operands, fp16 output.
// ---------------------------------------------------------------------------
#define H_LD 40
#define H_TILEB (128 * H_LD * 2)
#define STAGES 3
#define GEMM_SMEM (STAGES * 2 * H_TILEB)

extern __shared__ __half sgm_h[];

__device__ __forceinline__ void qkv_load_tile(uint32_t sa, uint32_t sb, int stage,
                                              const __half* Ap, const __half* Bp,
                                              int k0, int K, int tid) {
#pragma unroll
    for (int i = 0; i < 2; i++) {
        int c = tid + i * 256;
        int row = c >> 2, kc = (c & 3) * 8;
        cp_async16(sa + stage * H_TILEB + (row * H_LD + kc) * 2,
                   Ap + (size_t)row * K + k0 + kc);
    }
#pragma unroll
    for (int i = 0; i < 2; i++) {
        int c = tid + i * 256;
        int row = c >> 2, kc = (c & 3) * 8;
        cp_async16(sb + stage * H_TILEB + (row * H_LD + kc) * 2,
                   Bp + (size_t)row * K + k0 + kc);
    }
}

__global__ __launch_bounds__(256) void gemm_qkv(
    const __half* __restrict__ A, const __half* __restrict__ Bb,
    __half* __restrict__ Cb, int K, int ldc, size_t strideB, size_t strideC) {
    uint32_t sa = (uint32_t)__cvta_generic_to_shared(sgm_h);
    uint32_t sb = sa + STAGES * H_TILEB;

    const int tid = threadIdx.x;
    const int lane = tid & 31;
    const int warp = tid >> 5;
    const int gid = lane >> 2;
    const int t4 = lane & 3;
    const int wm = warp >> 2;
    const int wn = warp & 3;
    const int t8 = lane >> 3;
    const int r8 = lane & 7;

    const __half* Ap = A + (size_t)blockIdx.y * 128 * K;
    const __half* Bp = Bb + (size_t)blockIdx.z * strideB + (size_t)blockIdx.x * 128 * K;
    __half* Cp = Cb + (size_t)blockIdx.z * strideC +
                 (size_t)blockIdx.y * 128 * ldc + (size_t)blockIdx.x * 128;

    float acc[4][4][4];
#pragma unroll
    for (int mi = 0; mi < 4; mi++)
#pragma unroll
        for (int ni = 0; ni < 4; ni++)
#pragma unroll
            for (int r = 0; r < 4; r++) acc[mi][ni][r] = 0.f;

    const int ktiles = K >> 5;
#pragma unroll
    for (int s = 0; s < STAGES - 1; s++) {
        qkv_load_tile(sa, sb, s, Ap, Bp, s * 32, K, tid);
        cp_commit();
    }
    cp_wait<STAGES - 2>();
    __syncthreads();

    for (int kt = 0; kt < ktiles; kt++) {
        uint32_t abase = sa + (kt % STAGES) * H_TILEB;
        uint32_t bbase = sb + (kt % STAGES) * H_TILEB;
#pragma unroll
        for (int kk = 0; kk < 2; kk++) {
            const int kbh = kk * 16;
            uint32_t af[4][4], bf[4][2];
#pragma unroll
            for (int mi = 0; mi < 4; mi++) {
                int row = wm * 64 + mi * 16 + r8 + (t8 & 1) * 8;
                int col = kbh + (t8 >> 1) * 8;
                ldsm_x4(af[mi], abase + (row * H_LD + col) * 2);
            }
#pragma unroll
            for (int np = 0; np < 2; np++) {
                int row = wn * 32 + np * 16 + r8 + (t8 >> 1) * 8;
                int col = kbh + (t8 & 1) * 8;
                uint32_t r4[4];
                ldsm_x4(r4, bbase + (row * H_LD + col) * 2);
                bf[np * 2][0] = r4[0]; bf[np * 2][1] = r4[1];
                bf[np * 2 + 1][0] = r4[2]; bf[np * 2 + 1][1] = r4[3];
            }
#pragma unroll
            for (int mi = 0; mi < 4; mi++)
#pragma unroll
                for (int ni = 0; ni < 4; ni++)
                    mma_f16(acc[mi][ni], af[mi], bf[ni]);
        }
        int nt = kt + STAGES - 1;
        if (nt < ktiles)
            qkv_load_tile(sa, sb, nt % STAGES, Ap, Bp, nt * 32, K, tid);
        cp_commit();
        cp_wait<STAGES - 2>();
        __syncthreads();
    }

#pragma unroll
    for (int mi = 0; mi < 4; mi++) {
        const int r0 = wm * 64 + mi * 16 + gid;
#pragma unroll
        for (int ni = 0; ni < 4; ni++) {
            const int col = wn * 32 + ni * 8 + t4 * 2;
            __half2 h0 = __floats2half2_rn(acc[mi][ni][0], acc[mi][ni][1]);
            __half2 h1 = __floats2half2_rn(acc[mi][ni][2], acc[mi][ni][3]);
            *(__half2*)&Cp[(size_t)r0 * ldc + col] = h0;
            *(__half2*)&Cp[(size_t)(r0 + 8) * ldc + col] = h1;
        }
    }
}

// ---------------------------------------------------------------------------
// k softmax over L, fp16 in/out (math fp32)
// ---------------------------------------------------------------------------
__global__ void ksoftmax_kernel(__half* __restrict__ qkvh) {
    int row = blockIdx.x;
    int b = row >> 9;
    int ch = row & (HIDDEN - 1);
    __half2* p = (__half2*)(qkvh + ((size_t)b * QKV_CH + HIDDEN + ch) * L); // 2048 half2
    int tid = threadIdx.x;
    float2 v[8];
    float m = -INFINITY;
#pragma unroll
    for (int i = 0; i < 8; i++) {
        v[i] = __half22float2(p[tid + i * 256]);
        m = fmaxf(m, fmaxf(v[i].x, v[i].y));
    }
    __shared__ float red[256];
    red[tid] = m;
    __syncthreads();
    for (int s = 128; s > 0; s >>= 1) {
        if (tid < s) red[tid] = fmaxf(red[tid], red[tid + s]);
        __syncthreads();
    }
    m = red[0];
    __syncthreads();
    float sum = 0.f;
#pragma unroll
    for (int i = 0; i < 8; i++) {
        v[i].x = expf(v[i].x - m);
        v[i].y = expf(v[i].y - m);
        sum += v[i].x + v[i].y;
    }
    red[tid] = sum;
    __syncthreads();
    for (int s = 128; s > 0; s >>= 1) {
        if (tid < s) red[tid] += red[tid + s];
        __syncthreads();
    }
    float inv = 1.f / red[0];
#pragma unroll
    for (int i = 0; i < 8; i++)
        p[tid + i * 256] = __floats2half2_rn(v[i].x * inv, v[i].y * inv);
}

// ---------------------------------------------------------------------------
// partial context over an L-chunk, fp16 inputs
// ---------------------------------------------------------------------------
__global__ __launch_bounds__(256) void ctx_part_kernel(const __half* __restrict__ qkvh,
                                                       float* __restrict__ ctxp) {
    int bh = blockIdx.x;
    int chunk = blockIdx.y;
    int b = bh >> 3, h = bh & 7;
    const __half* kp = qkvh + ((size_t)b * QKV_CH + HIDDEN + h * DHEAD) * L;
    const __half* vp = qkvh + ((size_t)b * QKV_CH + 2 * HIDDEN + h * DHEAD) * L;
    __shared__ float ks[64][68];
    __shared__ float vs[64][68];
    int tid = threadIdx.x;
    int d0 = (tid >> 4) * 4;
    int e0 = (tid & 15) * 4;
    float acc[4][4];
#pragma unroll
    for (int i = 0; i < 4; i++)
#pragma unroll
        for (int j = 0; j < 4; j++) acc[i][j] = 0.f;

    int nbeg = chunk * (L / NCHUNK);
#pragma unroll
    for (int c0 = 0; c0 < (L / NCHUNK); c0 += 64) {
        int n0 = nbeg + c0;
#pragma unroll
        for (int ii = 0; ii < 2; ii++) {
            int idx = tid + ii * 256;           // 0..511
            int r = idx >> 3, c8 = (idx & 7) * 8;
            uint4 kr = *(const uint4*)&kp[(size_t)r * L + n0 + c8];
            uint4 vr = *(const uint4*)&vp[(size_t)r * L + n0 + c8];
            const __half2* kh = (const __half2*)&kr;
            const __half2* vh = (const __half2*)&vr;
#pragma unroll
            for (int q = 0; q < 4; q++) {
                float2 kf = __half22float2(kh[q]);
                float2 vf = __half22float2(vh[q]);
                ks[r][c8 + q * 2] = kf.x; ks[r][c8 + q * 2 + 1] = kf.y;
                vs[r][c8 + q * 2] = vf.x; vs[r][c8 + q * 2 + 1] = vf.y;
            }
        }
        __syncthreads();
#pragma unroll 4
        for (int nn = 0; nn < 64; nn++) {
            float rk[4], rv[4];
#pragma unroll
            for (int i = 0; i < 4; i++) rk[i] = ks[d0 + i][nn];
#pragma unroll
            for (int j = 0; j < 4; j++) rv[j] = vs[e0 + j][nn];
#pragma unroll
            for (int i = 0; i < 4; i++)
#pragma unroll
                for (int j = 0; j < 4; j++) acc[i][j] = fmaf(rk[i], rv[j], acc[i][j]);
        }
        __syncthreads();
    }
    float* cp = ctxp + ((size_t)chunk * (B * HEADS) + bh) * (DHEAD * DHEAD);
#pragma unroll
    for (int i = 0; i < 4; i++)
#pragma unroll
        for (int j = 0; j < 4; j++) cp[(d0 + i) * DHEAD + e0 + j] = acc[i][j];
}

__global__ void ctx_reduce_kernel(const float* __restrict__ ctxp,
                                  float* __restrict__ ctx) {
    int i = blockIdx.x * 256 + threadIdx.x;
    float s = 0.f;
#pragma unroll
    for (int c = 0; c < NCHUNK; c++)
        s += ctxp[(size_t)c * (B * HEADS * DHEAD * DHEAD) + i];
    ctx[i] = s;
}

// ---------------------------------------------------------------------------
// q-softmax + ctx apply -> attnT[b][l][e] fp16  (q read fp16)
// ---------------------------------------------------------------------------
__global__ __launch_bounds__(128) void attn_apply_kernel(const __half* __restrict__ qkvh,
                                                         const float* __restrict__ ctx,
                                                         __half* __restrict__ attnT) {
    int n0 = blockIdx.x * 128;
    int bh = blockIdx.y;
    int b = bh >> 3, h = bh & 7;

    __shared__ float4 cs[64][16];
    __shared__ float qs_s[64][128];
    const float4* cp4 = reinterpret_cast<const float4*>(ctx + (size_t)bh * DHEAD * DHEAD);
    for (int idx = threadIdx.x; idx < 64 * 16; idx += 128)
        cs[idx >> 4][idx & 15] = cp4[idx];

    const __half* qp = qkvh + ((size_t)b * QKV_CH + h * DHEAD) * L + n0;
    for (int idx = threadIdx.x; idx < 64 * 64; idx += 128) {
        int d = idx >> 6, c2 = (idx & 63) * 2;
        float2 qf = __half22float2(*(const __half2*)&qp[(size_t)d * L + c2]);
        qs_s[d][c2] = qf.x;
        qs_s[d][c2 + 1] = qf.y;
    }
    __syncthreads();

    int t = threadIdx.x;
    float m = -INFINITY;
#pragma unroll 8
    for (int d = 0; d < DHEAD; d++) m = fmaxf(m, qs_s[d][t]);
    float sum = 0.f;
#pragma unroll 8
    for (int d = 0; d < DHEAD; d++) sum += expf(qs_s[d][t] - m);
    float inv = ATTN_SCALE / sum;

    float4 acc[16];
#pragma unroll
    for (int e = 0; e < 16; e++) acc[e] = make_float4(0.f, 0.f, 0.f, 0.f);

#pragma unroll 4
    for (int d = 0; d < DHEAD; d++) {
        float qv = expf(qs_s[d][t] - m) * inv;
#pragma unroll
        for (int e = 0; e < 16; e++) {
            float4 c4 = cs[d][e];
            acc[e].x = fmaf(c4.x, qv, acc[e].x);
            acc[e].y = fmaf(c4.y, qv, acc[e].y);
            acc[e].z = fmaf(c4.z, qv, acc[e].z);
            acc[e].w = fmaf(c4.w, qv, acc[e].w);
        }
    }

    __half* op = attnT + ((size_t)b * L + n0 + t) * HIDDEN + h * DHEAD;
#pragma unroll
    for (int e = 0; e < 16; e++) {
        __half2 h0 = __floats2half2_rn(acc[e].x, acc[e].y);
        __half2 h1 = __floats2half2_rn(acc[e].z, acc[e].w);
        *(uint2*)&op[e * 4] = make_uint2(*(uint32_t*)&h0, *(uint32_t*)&h1);
    }
}

// ---------------------------------------------------------------------------
// Fused out-GEMM + bias + channel RMSNorm + residual.
// CTA: full M=512 x N=64 (K=512). 512 threads, 16 warps, warp tile 32x64.
// 2-stage cp.async. Epilogue: per-column ||o||, out = o*scale*g_out + x.
// ---------------------------------------------------------------------------
#define OA_BYTES (512 * H_LD * 2)
#define OB_BYTES (64 * H_LD * 2)
#define OSTG_BYTES (OA_BYTES + OB_BYTES)
#define OUT_SMEM (2 * OSTG_BYTES)

__global__ __launch_bounds__(512) void gemm_out_fused(
    const __half* __restrict__ A, const __half* __restrict__ Bb,
    const float* __restrict__ bias, const float* __restrict__ gout,
    const float* __restrict__ x, float* __restrict__ out) {
    __shared__ float colsum[64];
    uint32_t sbase = (uint32_t)__cvta_generic_to_shared(sgm_h);

    const int tid = threadIdx.x;
    const int lane = tid & 31;
    const int warp = tid >> 5;     // 0..15 = m block (32 rows each)
    const int gid = lane >> 2;
    const int t4 = lane & 3;
    const int t8 = lane >> 3;
    const int r8 = lane & 7;
    const int bz = blockIdx.y;
    const int l0 = blockIdx.x * 64;

    const __half* Bp = Bb + ((size_t)bz * L + l0) * HIDDEN;

    float acc[2][8][4];
#pragma unroll
    for (int mi = 0; mi < 2; mi++)
#pragma unroll
        for (int ni = 0; ni < 8; ni++)
#pragma unroll
            for (int r = 0; r < 4; r++) acc[mi][ni][r] = 0.f;

    auto load_stage = [&](int kt, int buf) {
        uint32_t sA = sbase + buf * OSTG_BYTES;
        uint32_t sB = sA + OA_BYTES;
        int k0 = kt * 32;
#pragma unroll
        for (int i = 0; i < 4; i++) {
            int c = tid + i * 512;
            int row = c >> 2, kc = (c & 3) * 8;
            cp_async16(sA + (row * H_LD + kc) * 2, A + (size_t)row * HIDDEN + k0 + kc);
        }
        if (tid < 256) {
            int row = tid >> 2, kc = (tid & 3) * 8;
            cp_async16(sB + (row * H_LD + kc) * 2, Bp + (size_t)row * HIDDEN + k0 + kc);
        }
    };

    load_stage(0, 0);
    cp_commit();
    cp_wait<0>();
    __syncthreads();

    const int ktiles = HIDDEN >> 5; // 16
    for (int kt = 0; kt < ktiles; kt++) {
        if (kt + 1 < ktiles) {
            load_stage(kt + 1, (kt + 1) & 1);
            cp_commit();
        }
        uint32_t abase = sbase + (kt & 1) * OSTG_BYTES;
        uint32_t bbase = abase + OA_BYTES;
#pragma unroll
        for (int kk = 0; kk < 2; kk++) {
            const int kbh = kk * 16;
            uint32_t af[2][4], bf[8][2];
#pragma unroll
            for (int mi = 0; mi < 2; mi++) {
                int row = warp * 32 + mi * 16 + r8 + (t8 & 1) * 8;
                int col = kbh + (t8 >> 1) * 8;
                ldsm_x4(af[mi], abase + (row * H_LD + col) * 2);
            }
#pragma unroll
            for (int np = 0; np < 4; np++) {
                int row = np * 16 + r8 + (t8 >> 1) * 8;
                int col = kbh + (t8 & 1) * 8;
                uint32_t r4[4];
                ldsm_x4(r4, bbase + (row * H_LD + col) * 2);
                bf[np * 2][0] = r4[0]; bf[np * 2][1] = r4[1];
                bf[np * 2 + 1][0] = r4[2]; bf[np * 2 + 1][1] = r4[3];
            }
#pragma unroll
            for (int mi = 0; mi < 2; mi++)
#pragma unroll
                for (int ni = 0; ni < 8; ni++)
                    mma_f16(acc[mi][ni], af[mi], bf[ni]);
        }
        cp_wait<0>();
        __syncthreads();
    }

    // --- fused epilogue ---
    float bvs[2][2];
#pragma unroll
    for (int mi = 0; mi < 2; mi++) {
        int r0 = warp * 32 + mi * 16 + gid;
        bvs[mi][0] = bias[r0];
        bvs[mi][1] = bias[r0 + 8];
    }
    if (tid < 64) colsum[tid] = 0.f;
    __syncthreads();

#pragma unroll
    for (int ni = 0; ni < 8; ni++) {
#pragma unroll
        for (int c01 = 0; c01 < 2; c01++) {
            float part = 0.f;
#pragma unroll
            for (int mi = 0; mi < 2; mi++) {
                float v0 = acc[mi][ni][c01] + bvs[mi][0];
                float v1 = acc[mi][ni][2 + c01] + bvs[mi][1];
                acc[mi][ni][c01] = v0;
                acc[mi][ni][2 + c01] = v1;
                part += v0 * v0 + v1 * v1;
            }
            part += __shfl_xor_sync(0xFFFFFFFFu, part, 4);
            part += __shfl_xor_sync(0xFFFFFFFFu, part, 8);
            part += __shfl_xor_sync(0xFFFFFFFFu, part, 16);
            if (gid == 0) atomicAdd(&colsum[ni * 8 + t4 * 2 + c01], part);
        }
    }
    __syncthreads();

    float scl[8][2];
#pragma unroll
    for (int ni = 0; ni < 8; ni++) {
        int col = ni * 8 + t4 * 2;
        scl[ni][0] = SQRT_C / fmaxf(sqrtf(colsum[col]), 1e-12f);
        scl[ni][1] = SQRT_C / fmaxf(sqrtf(colsum[col + 1]), 1e-12f);
    }

#pragma unroll
    for (int mi = 0; mi < 2; mi++) {
        int r0 = warp * 32 + mi * 16 + gid;
        float g0 = gout[r0], g1 = gout[r0 + 8];
        const float* xr0 = x + ((size_t)bz * C + r0) * L + l0;
        const float* xr1 = x + ((size_t)bz * C + r0 + 8) * L + l0;
        float* or0 = out + ((size_t)bz * C + r0) * L + l0;
        float* or1 = out + ((size_t)bz * C + r0 + 8) * L + l0;
#pragma unroll
        for (int ni = 0; ni < 8; ni++) {
            int col = ni * 8 + t4 * 2;
            float2 xv0 = *(const float2*)&xr0[col];
            float2 xv1 = *(const float2*)&xr1[col];
            float2 v0 = make_float2(acc[mi][ni][0] * scl[ni][0] * g0 + xv0.x,
                                    acc[mi][ni][1] * scl[ni][1] * g0 + xv0.y);
            float2 v1 = make_float2(acc[mi][ni][2] * scl[ni][0] * g1 + xv1.x,
                                    acc[mi][ni][3] * scl[ni][1] * g1 + xv1.y);
            *(float2*)&or0[col] = v0;
            *(float2*)&or1[col] = v1;
        }
    }
}

// ---------------------------------------------------------------------------
extern "C" void kernel_launch(void* const* d_in, const int* in_sizes, int n_in,
                              void* d_out, int out_size) {
    const float* x     = (const float*)d_in[0];
    const float* g_in  = (const float*)d_in[1];
    const float* w_qkv = (const float*)d_in[2];
    const float* w_out = (const float*)d_in[3];
    const float* b_out = (const float*)d_in[4];
    const float* g_out = (const float*)d_in[5];
    float* out = (float*)d_out;

    __half *w2h, *wouth, *xhT, *qkvh, *attnT;
    float *ctxp, *ctx;
    cudaGetSymbolAddress((void**)&w2h, g_w2h);
    cudaGetSymbolAddress((void**)&wouth, g_wouth);
    cudaGetSymbolAddress((void**)&xhT, g_xhT);
    cudaGetSymbolAddress((void**)&qkvh, g_qkvh);
    cudaGetSymbolAddress((void**)&ctxp, g_ctxp);
    cudaGetSymbolAddress((void**)&ctx, g_ctx);
    cudaGetSymbolAddress((void**)&attnT, g_attnT);

    cudaFuncSetAttribute(normxpose_kernel, cudaFuncAttributeMaxDynamicSharedMemorySize,
                         NX_SMEM);
    cudaFuncSetAttribute(gemm_qkv, cudaFuncAttributeMaxDynamicSharedMemorySize,
                         GEMM_SMEM);
    cudaFuncSetAttribute(gemm_out_fused, cudaFuncAttributeMaxDynamicSharedMemorySize,
                         OUT_SMEM);

    // 0. weight conversions
    convert_wqkv_kernel<<<(QKV_CH * C) / 256, 256>>>(w_qkv, g_in, w2h);
    convert_wout_kernel<<<(C * HIDDEN) / 256, 256>>>(w_out, wouth);

    // 1. fused rmsnorm scale + transpose -> xhT fp16
    normxpose_kernel<<<dim3(L / 32, B), 256, NX_SMEM>>>(x, xhT);

    // 2. qkv = w2h @ xn   (fp16 HMMA, fp16 out)
    gemm_qkv<<<dim3(L / 128, QKV_CH / 128, B), 256, GEMM_SMEM>>>(
        w2h, xhT, qkvh, C, L, (size_t)L * C, (size_t)QKV_CH * L);

    // 3. k softmax over L (fp16 in/out)
    ksoftmax_kernel<<<B * HIDDEN, 256>>>(qkvh);

    // 4. context per (b,h)
    ctx_part_kernel<<<dim3(B * HEADS, NCHUNK), 256>>>(qkvh, ctxp);
    ctx_reduce_kernel<<<(B * HEADS * DHEAD * DHEAD) / 256, 256>>>(ctxp, ctx);

    // 5. attnT fp16
    attn_apply_kernel<<<dim3(L / 128, B * HEADS), 128>>>(qkvh, ctx, attnT);

    // 6. out = rmsnorm(wouth @ attn + b_out)*g_out + x   (fully fused, N=64)
    gemm_out_fused<<<dim3(L / 64, B), 512, OUT_SMEM>>>(
        wouth, attnT, b_out, g_out, x, out);
}

// round 9
// speedup vs baseline: 3.9018x; 1.0311x over previous
#include <cuda_runtime.h>
#include <cuda_fp16.h>
#include <math.h>
#include <stdint.h>

// Problem constants
#define B 8
#define C 512
#define L 4096
#define HEADS 8
#define DHEAD 64
#define HIDDEN 512           // HEADS*DHEAD
#define QKV_CH 1536          // 3*HIDDEN
#define SQRT_C 22.627416998f // sqrt(512)
#define ATTN_SCALE 0.125f    // 64^-0.5
#define NCHUNK 32            // ctx split factor over L

// Scratch buffers
__device__ __half g_w2h[(size_t)QKV_CH * C];        // w_qkv * g_in, fp16
__device__ __half g_wouth[(size_t)C * HIDDEN];
__device__ __half g_xhT[(size_t)B * L * C];         // (x*s)^T fp16 [b][l][c]
__device__ __half g_qkvh[(size_t)B * QKV_CH * L];   // 96 MB fp16 [b][ch][l]
__device__ float  g_ctxp[(size_t)NCHUNK * B * HEADS * DHEAD * DHEAD];
__device__ float  g_ctx[(size_t)B * HEADS * DHEAD * DHEAD];
__device__ __half g_attnT[(size_t)B * L * HIDDEN];  // fp16 [b][l][e]

// ---------------------------------------------------------------------------
// PTX helpers
// ---------------------------------------------------------------------------
__device__ __forceinline__ void cp_async16(uint32_t dst, const void* src) {
    asm volatile("cp.async.cg.shared.global [%0], [%1], 16;" :: "r"(dst), "l"(src));
}
__device__ __forceinline__ void cp_commit() {
    asm volatile("cp.async.commit_group;");
}
template <int N>
__device__ __forceinline__ void cp_wait() {
    asm volatile("cp.async.wait_group %0;" :: "n"(N));
}
__device__ __forceinline__ void ldsm_x4(uint32_t r[4], uint32_t addr) {
    asm volatile("ldmatrix.sync.aligned.m8n8.x4.shared.b16 {%0,%1,%2,%3}, [%4];"
                 : "=r"(r[0]), "=r"(r[1]), "=r"(r[2]), "=r"(r[3]) : "r"(addr));
}
__device__ __forceinline__ void mma_f16(float d[4], const uint32_t a[4],
                                        const uint32_t b[2]) {
    asm volatile(
        "mma.sync.aligned.m16n8k16.row.col.f32.f16.f16.f32 "
        "{%0,%1,%2,%3}, {%4,%5,%6,%7}, {%8,%9}, {%0,%1,%2,%3};"
        : "+f"(d[0]), "+f"(d[1]), "+f"(d[2]), "+f"(d[3])
        : "r"(a[0]), "r"(a[1]), "r"(a[2]), "r"(a[3]),
          "r"(b[0]), "r"(b[1]));
}

// ---------------------------------------------------------------------------
// Weight conversions
// ---------------------------------------------------------------------------
__global__ void convert_wqkv_kernel(const float* __restrict__ w,
                                    const float* __restrict__ g,
                                    __half* __restrict__ w2h) {
    int i = blockIdx.x * 256 + threadIdx.x;
    w2h[i] = __float2half(w[i] * g[i & (C - 1)]);
}
__global__ void convert_wout_kernel(const float* __restrict__ w,
                                    __half* __restrict__ wh) {
    int i = blockIdx.x * 256 + threadIdx.x;
    wh[i] = __float2half(w[i]);
}

// ---------------------------------------------------------------------------
// Fused rmsnorm-scale + transpose: xhT[b][l][c] = fp16(x[b][c][l] * s[b,l])
// ---------------------------------------------------------------------------
#define NX_SMEM (512 * 33 * 4)
extern __shared__ float nx_sm[];
__global__ __launch_bounds__(256) void normxpose_kernel(const float* __restrict__ x,
                                                        __half* __restrict__ xhT) {
    float* t = nx_sm;               // t[c*33 + l]
    __shared__ float sc[32];
    int b = blockIdx.y;
    int l0 = blockIdx.x * 32;
    int tid = threadIdx.x;
    const float* xp = x + ((size_t)b * C) * L + l0;
#pragma unroll
    for (int i = 0; i < 64; i++) {
        int flat = i * 256 + tid;
        int c = flat >> 5, l = flat & 31;
        t[c * 33 + l] = xp[(size_t)c * L + l];
    }
    __syncthreads();
    int warp = tid >> 5, lane = tid & 31;
#pragma unroll
    for (int li = 0; li < 4; li++) {
        int l = warp * 4 + li;
        float ss = 0.f;
#pragma unroll
        for (int ci = 0; ci < 16; ci++) {
            float v = t[(ci * 32 + lane) * 33 + l];
            ss += v * v;
        }
#pragma unroll
        for (int off = 16; off > 0; off >>= 1)
            ss += __shfl_xor_sync(0xFFFFFFFFu, ss, off);
        if (lane == 0) sc[l] = SQRT_C / fmaxf(sqrtf(ss), 1e-12f);
    }
    __syncthreads();
    __half* op = xhT + ((size_t)b * L + l0) * C;
#pragma unroll
    for (int i = 0; i < 64; i++) {
        int flat = i * 256 + tid;
        int l = flat >> 9, c = flat & 511;
        op[(size_t)l * C + c] = __float2half(t[c * 33 + l] * sc[l]);
    }
}

// ---------------------------------------------------------------------------
// QKV GEMM: 128x256x32 CTA tile, 8 warps (2x4) of 64x64, 4-stage cp.async.
// Both operands K-major fp16; fp16 output.
// ---------------------------------------------------------------------------
#define H_LD 40
#define QA_BYTES (128 * H_LD * 2)   // 10240
#define QB_BYTES (256 * H_LD * 2)   // 20480
#define QSTG_BYTES (QA_BYTES + QB_BYTES)
#define QSTAGES 4
#define GEMM_SMEM (QSTAGES * QSTG_BYTES)

extern __shared__ __half sgm_h[];

__device__ __forceinline__ void qkv_load_tile(uint32_t sbase, int stage,
                                              const __half* Ap, const __half* Bp,
                                              int k0, int K, int tid) {
    uint32_t sA = sbase + stage * QSTG_BYTES;
    uint32_t sB = sA + QA_BYTES;
    // A: 128 rows x 32 halfs = 512 cp16; 256 threads -> 2 each
#pragma unroll
    for (int i = 0; i < 2; i++) {
        int c = tid + i * 256;
        int row = c >> 2, kc = (c & 3) * 8;
        cp_async16(sA + (row * H_LD + kc) * 2, Ap + (size_t)row * K + k0 + kc);
    }
    // B: 256 rows x 32 halfs = 1024 cp16 -> 4 each
#pragma unroll
    for (int i = 0; i < 4; i++) {
        int c = tid + i * 256;
        int row = c >> 2, kc = (c & 3) * 8;
        cp_async16(sB + (row * H_LD + kc) * 2, Bp + (size_t)row * K + k0 + kc);
    }
}

__global__ __launch_bounds__(256, 1) void gemm_qkv(
    const __half* __restrict__ A, const __half* __restrict__ Bb,
    __half* __restrict__ Cb, int K, int ldc, size_t strideB, size_t strideC) {
    uint32_t sbase = (uint32_t)__cvta_generic_to_shared(sgm_h);

    const int tid = threadIdx.x;
    const int lane = tid & 31;
    const int warp = tid >> 5;
    const int gid = lane >> 2;
    const int t4 = lane & 3;
    const int wm = warp >> 2;    // 0..1
    const int wn = warp & 3;     // 0..3
    const int t8 = lane >> 3;
    const int r8 = lane & 7;

    const __half* Ap = A + (size_t)blockIdx.y * 128 * K;
    const __half* Bp = Bb + (size_t)blockIdx.z * strideB + (size_t)blockIdx.x * 256 * K;
    __half* Cp = Cb + (size_t)blockIdx.z * strideC +
                 (size_t)blockIdx.y * 128 * ldc + (size_t)blockIdx.x * 256;

    float acc[4][8][4];
#pragma unroll
    for (int mi = 0; mi < 4; mi++)
#pragma unroll
        for (int ni = 0; ni < 8; ni++)
#pragma unroll
            for (int r = 0; r < 4; r++) acc[mi][ni][r] = 0.f;

    const int ktiles = K >> 5;   // 16
#pragma unroll
    for (int s = 0; s < QSTAGES - 1; s++) {
        qkv_load_tile(sbase, s, Ap, Bp, s * 32, K, tid);
        cp_commit();
    }
    cp_wait<QSTAGES - 2>();
    __syncthreads();

    for (int kt = 0; kt < ktiles; kt++) {
        uint32_t abase = sbase + (kt % QSTAGES) * QSTG_BYTES;
        uint32_t bbase = abase + QA_BYTES;
#pragma unroll
        for (int kk = 0; kk < 2; kk++) {
            const int kbh = kk * 16;
            uint32_t af[4][4], bf[8][2];
#pragma unroll
            for (int mi = 0; mi < 4; mi++) {
                int row = wm * 64 + mi * 16 + r8 + (t8 & 1) * 8;
                int col = kbh + (t8 >> 1) * 8;
                ldsm_x4(af[mi], abase + (row * H_LD + col) * 2);
            }
#pragma unroll
            for (int np = 0; np < 4; np++) {
                int row = wn * 64 + np * 16 + r8 + (t8 >> 1) * 8;
                int col = kbh + (t8 & 1) * 8;
                uint32_t r4[4];
                ldsm_x4(r4, bbase + (row * H_LD + col) * 2);
                bf[np * 2][0] = r4[0]; bf[np * 2][1] = r4[1];
                bf[np * 2 + 1][0] = r4[2]; bf[np * 2 + 1][1] = r4[3];
            }
#pragma unroll
            for (int mi = 0; mi < 4; mi++)
#pragma unroll
                for (int ni = 0; ni < 8; ni++)
                    mma_f16(acc[mi][ni], af[mi], bf[ni]);
        }
        int nt = kt + QSTAGES - 1;
        if (nt < ktiles) {
            qkv_load_tile(sbase, nt % QSTAGES, Ap, Bp, nt * 32, K, tid);
            cp_commit();
            cp_wait<QSTAGES - 2>();
        } else {
            cp_wait<0>();
        }
        __syncthreads();
    }

#pragma unroll
    for (int mi = 0; mi < 4; mi++) {
        const int r0 = wm * 64 + mi * 16 + gid;
#pragma unroll
        for (int ni = 0; ni < 8; ni++) {
            const int col = wn * 64 + ni * 8 + t4 * 2;
            __half2 h0 = __floats2half2_rn(acc[mi][ni][0], acc[mi][ni][1]);
            __half2 h1 = __floats2half2_rn(acc[mi][ni][2], acc[mi][ni][3]);
            *(__half2*)&Cp[(size_t)r0 * ldc + col] = h0;
            *(__half2*)&Cp[(size_t)(r0 + 8) * ldc + col] = h1;
        }
    }
}

// ---------------------------------------------------------------------------
// k softmax over L, fp16 in/out (math fp32)
// ---------------------------------------------------------------------------
__global__ void ksoftmax_kernel(__half* __restrict__ qkvh) {
    int row = blockIdx.x;
    int b = row >> 9;
    int ch = row & (HIDDEN - 1);
    __half2* p = (__half2*)(qkvh + ((size_t)b * QKV_CH + HIDDEN + ch) * L);
    int tid = threadIdx.x;
    float2 v[8];
    float m = -INFINITY;
#pragma unroll
    for (int i = 0; i < 8; i++) {
        v[i] = __half22float2(p[tid + i * 256]);
        m = fmaxf(m, fmaxf(v[i].x, v[i].y));
    }
    __shared__ float red[256];
    red[tid] = m;
    __syncthreads();
    for (int s = 128; s > 0; s >>= 1) {
        if (tid < s) red[tid] = fmaxf(red[tid], red[tid + s]);
        __syncthreads();
    }
    m = red[0];
    __syncthreads();
    float sum = 0.f;
#pragma unroll
    for (int i = 0; i < 8; i++) {
        v[i].x = expf(v[i].x - m);
        v[i].y = expf(v[i].y - m);
        sum += v[i].x + v[i].y;
    }
    red[tid] = sum;
    __syncthreads();
    for (int s = 128; s > 0; s >>= 1) {
        if (tid < s) red[tid] += red[tid + s];
        __syncthreads();
    }
    float inv = 1.f / red[0];
#pragma unroll
    for (int i = 0; i < 8; i++)
        p[tid + i * 256] = __floats2half2_rn(v[i].x * inv, v[i].y * inv);
}

// ---------------------------------------------------------------------------
// partial context over an L-chunk, fp16 inputs
// ---------------------------------------------------------------------------
__global__ __launch_bounds__(256) void ctx_part_kernel(const __half* __restrict__ qkvh,
                                                       float* __restrict__ ctxp) {
    int bh = blockIdx.x;
    int chunk = blockIdx.y;
    int b = bh >> 3, h = bh & 7;
    const __half* kp = qkvh + ((size_t)b * QKV_CH + HIDDEN + h * DHEAD) * L;
    const __half* vp = qkvh + ((size_t)b * QKV_CH + 2 * HIDDEN + h * DHEAD) * L;
    __shared__ float ks[64][68];
    __shared__ float vs[64][68];
    int tid = threadIdx.x;
    int d0 = (tid >> 4) * 4;
    int e0 = (tid & 15) * 4;
    float acc[4][4];
#pragma unroll
    for (int i = 0; i < 4; i++)
#pragma unroll
        for (int j = 0; j < 4; j++) acc[i][j] = 0.f;

    int nbeg = chunk * (L / NCHUNK);
#pragma unroll
    for (int c0 = 0; c0 < (L / NCHUNK); c0 += 64) {
        int n0 = nbeg + c0;
#pragma unroll
        for (int ii = 0; ii < 2; ii++) {
            int idx = tid + ii * 256;
            int r = idx >> 3, c8 = (idx & 7) * 8;
            uint4 kr = *(const uint4*)&kp[(size_t)r * L + n0 + c8];
            uint4 vr = *(const uint4*)&vp[(size_t)r * L + n0 + c8];
            const __half2* kh = (const __half2*)&kr;
            const __half2* vh = (const __half2*)&vr;
#pragma unroll
            for (int q = 0; q < 4; q++) {
                float2 kf = __half22float2(kh[q]);
                float2 vf = __half22float2(vh[q]);
                ks[r][c8 + q * 2] = kf.x; ks[r][c8 + q * 2 + 1] = kf.y;
                vs[r][c8 + q * 2] = vf.x; vs[r][c8 + q * 2 + 1] = vf.y;
            }
        }
        __syncthreads();
#pragma unroll 4
        for (int nn = 0; nn < 64; nn++) {
            float rk[4], rv[4];
#pragma unroll
            for (int i = 0; i < 4; i++) rk[i] = ks[d0 + i][nn];
#pragma unroll
            for (int j = 0; j < 4; j++) rv[j] = vs[e0 + j][nn];
#pragma unroll
            for (int i = 0; i < 4; i++)
#pragma unroll
                for (int j = 0; j < 4; j++) acc[i][j] = fmaf(rk[i], rv[j], acc[i][j]);
        }
        __syncthreads();
    }
    float* cp = ctxp + ((size_t)chunk * (B * HEADS) + bh) * (DHEAD * DHEAD);
#pragma unroll
    for (int i = 0; i < 4; i++)
#pragma unroll
        for (int j = 0; j < 4; j++) cp[(d0 + i) * DHEAD + e0 + j] = acc[i][j];
}

__global__ void ctx_reduce_kernel(const float* __restrict__ ctxp,
                                  float* __restrict__ ctx) {
    int i = blockIdx.x * 256 + threadIdx.x;
    float s = 0.f;
#pragma unroll
    for (int c = 0; c < NCHUNK; c++)
        s += ctxp[(size_t)c * (B * HEADS * DHEAD * DHEAD) + i];
    ctx[i] = s;
}

// ---------------------------------------------------------------------------
// q-softmax + ctx apply -> attnT[b][l][e] fp16  (q read fp16)
// ---------------------------------------------------------------------------
__global__ __launch_bounds__(128) void attn_apply_kernel(const __half* __restrict__ qkvh,
                                                         const float* __restrict__ ctx,
                                                         __half* __restrict__ attnT) {
    int n0 = blockIdx.x * 128;
    int bh = blockIdx.y;
    int b = bh >> 3, h = bh & 7;

    __shared__ float4 cs[64][16];
    __shared__ float qs_s[64][128];
    const float4* cp4 = reinterpret_cast<const float4*>(ctx + (size_t)bh * DHEAD * DHEAD);
    for (int idx = threadIdx.x; idx < 64 * 16; idx += 128)
        cs[idx >> 4][idx & 15] = cp4[idx];

    const __half* qp = qkvh + ((size_t)b * QKV_CH + h * DHEAD) * L + n0;
    for (int idx = threadIdx.x; idx < 64 * 64; idx += 128) {
        int d = idx >> 6, c2 = (idx & 63) * 2;
        float2 qf = __half22float2(*(const __half2*)&qp[(size_t)d * L + c2]);
        qs_s[d][c2] = qf.x;
        qs_s[d][c2 + 1] = qf.y;
    }
    __syncthreads();

    int t = threadIdx.x;
    float m = -INFINITY;
#pragma unroll 8
    for (int d = 0; d < DHEAD; d++) m = fmaxf(m, qs_s[d][t]);
    float sum = 0.f;
#pragma unroll 8
    for (int d = 0; d < DHEAD; d++) sum += expf(qs_s[d][t] - m);
    float inv = ATTN_SCALE / sum;

    float4 acc[16];
#pragma unroll
    for (int e = 0; e < 16; e++) acc[e] = make_float4(0.f, 0.f, 0.f, 0.f);

#pragma unroll 4
    for (int d = 0; d < DHEAD; d++) {
        float qv = expf(qs_s[d][t] - m) * inv;
#pragma unroll
        for (int e = 0; e < 16; e++) {
            float4 c4 = cs[d][e];
            acc[e].x = fmaf(c4.x, qv, acc[e].x);
            acc[e].y = fmaf(c4.y, qv, acc[e].y);
            acc[e].z = fmaf(c4.z, qv, acc[e].z);
            acc[e].w = fmaf(c4.w, qv, acc[e].w);
        }
    }

    __half* op = attnT + ((size_t)b * L + n0 + t) * HIDDEN + h * DHEAD;
#pragma unroll
    for (int e = 0; e < 16; e++) {
        __half2 h0 = __floats2half2_rn(acc[e].x, acc[e].y);
        __half2 h1 = __floats2half2_rn(acc[e].z, acc[e].w);
        *(uint2*)&op[e * 4] = make_uint2(*(uint32_t*)&h0, *(uint32_t*)&h1);
    }
}

// ---------------------------------------------------------------------------
// Fused out-GEMM + bias + channel RMSNorm + residual.
// CTA: full M=512 x N=64 (K=512). 512 threads, 16 warps of 32x64.
// 3-stage cp.async ring. Epilogue: per-column ||o||, out = o*scale*g_out + x.
// ---------------------------------------------------------------------------
#define OA_BYTES (512 * H_LD * 2)
#define OB_BYTES (64 * H_LD * 2)
#define OSTG_BYTES (OA_BYTES + OB_BYTES)
#define OSTAGES 3
#define OUT_SMEM (OSTAGES * OSTG_BYTES)

__global__ __launch_bounds__(512) void gemm_out_fused(
    const __half* __restrict__ A, const __half* __restrict__ Bb,
    const float* __restrict__ bias, const float* __restrict__ gout,
    const float* __restrict__ x, float* __restrict__ out) {
    __shared__ float colsum[64];
    uint32_t sbase = (uint32_t)__cvta_generic_to_shared(sgm_h);

    const int tid = threadIdx.x;
    const int lane = tid & 31;
    const int warp = tid >> 5;     // 0..15 = m block
    const int gid = lane >> 2;
    const int t4 = lane & 3;
    const int t8 = lane >> 3;
    const int r8 = lane & 7;
    const int bz = blockIdx.y;
    const int l0 = blockIdx.x * 64;

    const __half* Bp = Bb + ((size_t)bz * L + l0) * HIDDEN;

    float acc[2][8][4];
#pragma unroll
    for (int mi = 0; mi < 2; mi++)
#pragma unroll
        for (int ni = 0; ni < 8; ni++)
#pragma unroll
            for (int r = 0; r < 4; r++) acc[mi][ni][r] = 0.f;

    auto load_stage = [&](int kt) {
        uint32_t sA = sbase + (kt % OSTAGES) * OSTG_BYTES;
        uint32_t sB = sA + OA_BYTES;
        int k0 = kt * 32;
#pragma unroll
        for (int i = 0; i < 4; i++) {
            int c = tid + i * 512;
            int row = c >> 2, kc = (c & 3) * 8;
            cp_async16(sA + (row * H_LD + kc) * 2, A + (size_t)row * HIDDEN + k0 + kc);
        }
        if (tid < 256) {
            int row = tid >> 2, kc = (tid & 3) * 8;
            cp_async16(sB + (row * H_LD + kc) * 2, Bp + (size_t)row * HIDDEN + k0 + kc);
        }
    };

    const int ktiles = HIDDEN >> 5; // 16
#pragma unroll
    for (int s = 0; s < OSTAGES - 1; s++) {
        load_stage(s);
        cp_commit();
    }
    cp_wait<OSTAGES - 2>();
    __syncthreads();

    for (int kt = 0; kt < ktiles; kt++) {
        uint32_t abase = sbase + (kt % OSTAGES) * OSTG_BYTES;
        uint32_t bbase = abase + OA_BYTES;
#pragma unroll
        for (int kk = 0; kk < 2; kk++) {
            const int kbh = kk * 16;
            uint32_t af[2][4], bf[8][2];
#pragma unroll
            for (int mi = 0; mi < 2; mi++) {
                int row = warp * 32 + mi * 16 + r8 + (t8 & 1) * 8;
                int col = kbh + (t8 >> 1) * 8;
                ldsm_x4(af[mi], abase + (row * H_LD + col) * 2);
            }
#pragma unroll
            for (int np = 0; np < 4; np++) {
                int row = np * 16 + r8 + (t8 >> 1) * 8;
                int col = kbh + (t8 & 1) * 8;
                uint32_t r4[4];
                ldsm_x4(r4, bbase + (row * H_LD + col) * 2);
                bf[np * 2][0] = r4[0]; bf[np * 2][1] = r4[1];
                bf[np * 2 + 1][0] = r4[2]; bf[np * 2 + 1][1] = r4[3];
            }
#pragma unroll
            for (int mi = 0; mi < 2; mi++)
#pragma unroll
                for (int ni = 0; ni < 8; ni++)
                    mma_f16(acc[mi][ni], af[mi], bf[ni]);
        }
        int nt = kt + OSTAGES - 1;
        if (nt < ktiles) {
            load_stage(nt);
            cp_commit();
            cp_wait<OSTAGES - 2>();
        } else {
            cp_wait<0>();
        }
        __syncthreads();
    }

    // --- fused epilogue ---
    float bvs[2][2];
#pragma unroll
    for (int mi = 0; mi < 2; mi++) {
        int r0 = warp * 32 + mi * 16 + gid;
        bvs[mi][0] = bias[r0];
        bvs[mi][1] = bias[r0 + 8];
    }
    if (tid < 64) colsum[tid] = 0.f;
    __syncthreads();

#pragma unroll
    for (int ni = 0; ni < 8; ni++) {
#pragma unroll
        for (int c01 = 0; c01 < 2; c01++) {
            float part = 0.f;
#pragma unroll
            for (int mi = 0; mi < 2; mi++) {
                float v0 = acc[mi][ni][c01] + bvs[mi][0];
                float v1 = acc[mi][ni][2 + c01] + bvs[mi][1];
                acc[mi][ni][c01] = v0;
                acc[mi][ni][2 + c01] = v1;
                part += v0 * v0 + v1 * v1;
            }
            part += __shfl_xor_sync(0xFFFFFFFFu, part, 4);
            part += __shfl_xor_sync(0xFFFFFFFFu, part, 8);
            part += __shfl_xor_sync(0xFFFFFFFFu, part, 16);
            if (gid == 0) atomicAdd(&colsum[ni * 8 + t4 * 2 + c01], part);
        }
    }
    __syncthreads();

    float scl[8][2];
#pragma unroll
    for (int ni = 0; ni < 8; ni++) {
        int col = ni * 8 + t4 * 2;
        scl[ni][0] = SQRT_C / fmaxf(sqrtf(colsum[col]), 1e-12f);
        scl[ni][1] = SQRT_C / fmaxf(sqrtf(colsum[col + 1]), 1e-12f);
    }

#pragma unroll
    for (int mi = 0; mi < 2; mi++) {
        int r0 = warp * 32 + mi * 16 + gid;
        float g0 = gout[r0], g1 = gout[r0 + 8];
        const float* xr0 = x + ((size_t)bz * C + r0) * L + l0;
        const float* xr1 = x + ((size_t)bz * C + r0 + 8) * L + l0;
        float* or0 = out + ((size_t)bz * C + r0) * L + l0;
        float* or1 = out + ((size_t)bz * C + r0 + 8) * L + l0;
#pragma unroll
        for (int ni = 0; ni < 8; ni++) {
            int col = ni * 8 + t4 * 2;
            float2 xv0 = *(const float2*)&xr0[col];
            float2 xv1 = *(const float2*)&xr1[col];
            float2 v0 = make_float2(acc[mi][ni][0] * scl[ni][0] * g0 + xv0.x,
                                    acc[mi][ni][1] * scl[ni][1] * g0 + xv0.y);
            float2 v1 = make_float2(acc[mi][ni][2] * scl[ni][0] * g1 + xv1.x,
                                    acc[mi][ni][3] * scl[ni][1] * g1 + xv1.y);
            *(float2*)&or0[col] = v0;
            *(float2*)&or1[col] = v1;
        }
    }
}

// ---------------------------------------------------------------------------
extern "C" void kernel_launch(void* const* d_in, const int* in_sizes, int n_in,
                              void* d_out, int out_size) {
    const float* x     = (const float*)d_in[0];
    const float* g_in  = (const float*)d_in[1];
    const float* w_qkv = (const float*)d_in[2];
    const float* w_out = (const float*)d_in[3];
    const float* b_out = (const float*)d_in[4];
    const float* g_out = (const float*)d_in[5];
    float* out = (float*)d_out;

    __half *w2h, *wouth, *xhT, *qkvh, *attnT;
    float *ctxp, *ctx;
    cudaGetSymbolAddress((void**)&w2h, g_w2h);
    cudaGetSymbolAddress((void**)&wouth, g_wouth);
    cudaGetSymbolAddress((void**)&xhT, g_xhT);
    cudaGetSymbolAddress((void**)&qkvh, g_qkvh);
    cudaGetSymbolAddress((void**)&ctxp, g_ctxp);
    cudaGetSymbolAddress((void**)&ctx, g_ctx);
    cudaGetSymbolAddress((void**)&attnT, g_attnT);

    cudaFuncSetAttribute(normxpose_kernel, cudaFuncAttributeMaxDynamicSharedMemorySize,
                         NX_SMEM);
    cudaFuncSetAttribute(gemm_qkv, cudaFuncAttributeMaxDynamicSharedMemorySize,
                         GEMM_SMEM);
    cudaFuncSetAttribute(gemm_out_fused, cudaFuncAttributeMaxDynamicSharedMemorySize,
                         OUT_SMEM);

    // 0. weight conversions
    convert_wqkv_kernel<<<(QKV_CH * C) / 256, 256>>>(w_qkv, g_in, w2h);
    convert_wout_kernel<<<(C * HIDDEN) / 256, 256>>>(w_out, wouth);

    // 1. fused rmsnorm scale + transpose -> xhT fp16
    normxpose_kernel<<<dim3(L / 32, B), 256, NX_SMEM>>>(x, xhT);

    // 2. qkv = w2h @ xn   (fp16 HMMA, 128x256 tiles)
    gemm_qkv<<<dim3(L / 256, QKV_CH / 128, B), 256, GEMM_SMEM>>>(
        w2h, xhT, qkvh, C, L, (size_t)L * C, (size_t)QKV_CH * L);

    // 3. k softmax over L (fp16 in/out)
    ksoftmax_kernel<<<B * HIDDEN, 256>>>(qkvh);

    // 4. context per (b,h)
    ctx_part_kernel<<<dim3(B * HEADS, NCHUNK), 256>>>(qkvh, ctxp);
    ctx_reduce_kernel<<<(B * HEADS * DHEAD * DHEAD) / 256, 256>>>(ctxp, ctx);

    // 5. attnT fp16
    attn_apply_kernel<<<dim3(L / 128, B * HEADS), 128>>>(qkvh, ctx, attnT);

    // 6. out = rmsnorm(wouth @ attn + b_out)*g_out + x   (fused, 3-stage)
    gemm_out_fused<<<dim3(L / 64, B), 512, OUT_SMEM>>>(
        wouth, attnT, b_out, g_out, x, out);
}

// round 10
// speedup vs baseline: 4.8864x; 1.2523x over previous
#include <cuda_runtime.h>
#include <cuda_fp16.h>
#include <math.h>
#include <stdint.h>

// Problem constants
#define B 8
#define C 512
#define L 4096
#define HEADS 8
#define DHEAD 64
#define HIDDEN 512           // HEADS*DHEAD
#define QKV_CH 1536          // 3*HIDDEN
#define SQRT_C 22.627416998f // sqrt(512)
#define ATTN_SCALE 0.125f    // 64^-0.5
#define NCHUNK 8             // ctx split factor over L

// Scratch buffers
__device__ __half g_w2h[(size_t)QKV_CH * C];        // w_qkv * g_in, fp16
__device__ __half g_wouth[(size_t)C * HIDDEN];
__device__ __half g_xhT[(size_t)B * L * C];         // (x*s)^T fp16 [b][l][c]
__device__ __half g_qkvh[(size_t)B * QKV_CH * L];   // 96 MB fp16 [b][ch][l]
__device__ float  g_ctxp[(size_t)NCHUNK * B * HEADS * DHEAD * DHEAD];
__device__ float  g_ctx[(size_t)B * HEADS * DHEAD * DHEAD];
__device__ __half g_attnT[(size_t)B * L * HIDDEN];  // fp16 [b][l][e]

// ---------------------------------------------------------------------------
// PTX helpers
// ---------------------------------------------------------------------------
__device__ __forceinline__ void cp_async16(uint32_t dst, const void* src) {
    asm volatile("cp.async.cg.shared.global [%0], [%1], 16;" :: "r"(dst), "l"(src));
}
__device__ __forceinline__ void cp_commit() {
    asm volatile("cp.async.commit_group;");
}
template <int N>
__device__ __forceinline__ void cp_wait() {
    asm volatile("cp.async.wait_group %0;" :: "n"(N));
}
__device__ __forceinline__ void ldsm_x4(uint32_t r[4], uint32_t addr) {
    asm volatile("ldmatrix.sync.aligned.m8n8.x4.shared.b16 {%0,%1,%2,%3}, [%4];"
                 : "=r"(r[0]), "=r"(r[1]), "=r"(r[2]), "=r"(r[3]) : "r"(addr));
}
__device__ __forceinline__ void mma_f16(float d[4], const uint32_t a[4],
                                        const uint32_t b[2]) {
    asm volatile(
        "mma.sync.aligned.m16n8k16.row.col.f32.f16.f16.f32 "
        "{%0,%1,%2,%3}, {%4,%5,%6,%7}, {%8,%9}, {%0,%1,%2,%3};"
        : "+f"(d[0]), "+f"(d[1]), "+f"(d[2]), "+f"(d[3])
        : "r"(a[0]), "r"(a[1]), "r"(a[2]), "r"(a[3]),
          "r"(b[0]), "r"(b[1]));
}

// ---------------------------------------------------------------------------
// Weight conversions
// ---------------------------------------------------------------------------
__global__ void convert_wqkv_kernel(const float* __restrict__ w,
                                    const float* __restrict__ g,
                                    __half* __restrict__ w2h) {
    int i = blockIdx.x * 256 + threadIdx.x;
    w2h[i] = __float2half(w[i] * g[i & (C - 1)]);
}
__global__ void convert_wout_kernel(const float* __restrict__ w,
                                    __half* __restrict__ wh) {
    int i = blockIdx.x * 256 + threadIdx.x;
    wh[i] = __float2half(w[i]);
}

// ---------------------------------------------------------------------------
// Fused rmsnorm-scale + transpose: xhT[b][l][c] = fp16(x[b][c][l] * s[b,l])
// ---------------------------------------------------------------------------
#define NX_SMEM (512 * 33 * 4)
extern __shared__ float nx_sm[];
__global__ __launch_bounds__(256) void normxpose_kernel(const float* __restrict__ x,
                                                        __half* __restrict__ xhT) {
    float* t = nx_sm;               // t[c*33 + l]
    __shared__ float sc[32];
    int b = blockIdx.y;
    int l0 = blockIdx.x * 32;
    int tid = threadIdx.x;
    const float* xp = x + ((size_t)b * C) * L + l0;
#pragma unroll
    for (int i = 0; i < 64; i++) {
        int flat = i * 256 + tid;
        int c = flat >> 5, l = flat & 31;
        t[c * 33 + l] = xp[(size_t)c * L + l];
    }
    __syncthreads();
    int warp = tid >> 5, lane = tid & 31;
#pragma unroll
    for (int li = 0; li < 4; li++) {
        int l = warp * 4 + li;
        float ss = 0.f;
#pragma unroll
        for (int ci = 0; ci < 16; ci++) {
            float v = t[(ci * 32 + lane) * 33 + l];
            ss += v * v;
        }
#pragma unroll
        for (int off = 16; off > 0; off >>= 1)
            ss += __shfl_xor_sync(0xFFFFFFFFu, ss, off);
        if (lane == 0) sc[l] = SQRT_C / fmaxf(sqrtf(ss), 1e-12f);
    }
    __syncthreads();
    __half* op = xhT + ((size_t)b * L + l0) * C;
#pragma unroll
    for (int i = 0; i < 64; i++) {
        int flat = i * 256 + tid;
        int l = flat >> 9, c = flat & 511;
        op[(size_t)l * C + c] = __float2half(t[c * 33 + l] * sc[l]);
    }
}

// ---------------------------------------------------------------------------
// QKV GEMM (R7 shape): 128x128x32, 8 warps (2x4) of 64x32, 3-stage cp.async.
// ---------------------------------------------------------------------------
#define H_LD 40
#define H_TILEB (128 * H_LD * 2)
#define STAGES 3
#define GEMM_SMEM (STAGES * 2 * H_TILEB)

extern __shared__ __half sgm_h[];

__device__ __forceinline__ void qkv_load_tile(uint32_t sa, uint32_t sb, int stage,
                                              const __half* Ap, const __half* Bp,
                                              int k0, int K, int tid) {
#pragma unroll
    for (int i = 0; i < 2; i++) {
        int c = tid + i * 256;
        int row = c >> 2, kc = (c & 3) * 8;
        cp_async16(sa + stage * H_TILEB + (row * H_LD + kc) * 2,
                   Ap + (size_t)row * K + k0 + kc);
    }
#pragma unroll
    for (int i = 0; i < 2; i++) {
        int c = tid + i * 256;
        int row = c >> 2, kc = (c & 3) * 8;
        cp_async16(sb + stage * H_TILEB + (row * H_LD + kc) * 2,
                   Bp + (size_t)row * K + k0 + kc);
    }
}

__global__ __launch_bounds__(256) void gemm_qkv(
    const __half* __restrict__ A, const __half* __restrict__ Bb,
    __half* __restrict__ Cb, int K, int ldc, size_t strideB, size_t strideC) {
    uint32_t sa = (uint32_t)__cvta_generic_to_shared(sgm_h);
    uint32_t sb = sa + STAGES * H_TILEB;

    const int tid = threadIdx.x;
    const int lane = tid & 31;
    const int warp = tid >> 5;
    const int gid = lane >> 2;
    const int t4 = lane & 3;
    const int wm = warp >> 2;
    const int wn = warp & 3;
    const int t8 = lane >> 3;
    const int r8 = lane & 7;

    const __half* Ap = A + (size_t)blockIdx.y * 128 * K;
    const __half* Bp = Bb + (size_t)blockIdx.z * strideB + (size_t)blockIdx.x * 128 * K;
    __half* Cp = Cb + (size_t)blockIdx.z * strideC +
                 (size_t)blockIdx.y * 128 * ldc + (size_t)blockIdx.x * 128;

    float acc[4][4][4];
#pragma unroll
    for (int mi = 0; mi < 4; mi++)
#pragma unroll
        for (int ni = 0; ni < 4; ni++)
#pragma unroll
            for (int r = 0; r < 4; r++) acc[mi][ni][r] = 0.f;

    const int ktiles = K >> 5;
#pragma unroll
    for (int s = 0; s < STAGES - 1; s++) {
        qkv_load_tile(sa, sb, s, Ap, Bp, s * 32, K, tid);
        cp_commit();
    }
    cp_wait<STAGES - 2>();
    __syncthreads();

    for (int kt = 0; kt < ktiles; kt++) {
        uint32_t abase = sa + (kt % STAGES) * H_TILEB;
        uint32_t bbase = sb + (kt % STAGES) * H_TILEB;
#pragma unroll
        for (int kk = 0; kk < 2; kk++) {
            const int kbh = kk * 16;
            uint32_t af[4][4], bf[4][2];
#pragma unroll
            for (int mi = 0; mi < 4; mi++) {
                int row = wm * 64 + mi * 16 + r8 + (t8 & 1) * 8;
                int col = kbh + (t8 >> 1) * 8;
                ldsm_x4(af[mi], abase + (row * H_LD + col) * 2);
            }
#pragma unroll
            for (int np = 0; np < 2; np++) {
                int row = wn * 32 + np * 16 + r8 + (t8 >> 1) * 8;
                int col = kbh + (t8 & 1) * 8;
                uint32_t r4[4];
                ldsm_x4(r4, bbase + (row * H_LD + col) * 2);
                bf[np * 2][0] = r4[0]; bf[np * 2][1] = r4[1];
                bf[np * 2 + 1][0] = r4[2]; bf[np * 2 + 1][1] = r4[3];
            }
#pragma unroll
            for (int mi = 0; mi < 4; mi++)
#pragma unroll
                for (int ni = 0; ni < 4; ni++)
                    mma_f16(acc[mi][ni], af[mi], bf[ni]);
        }
        int nt = kt + STAGES - 1;
        if (nt < ktiles) {
            qkv_load_tile(sa, sb, nt % STAGES, Ap, Bp, nt * 32, K, tid);
            cp_commit();
            cp_wait<STAGES - 2>();
        } else {
            cp_wait<0>();
        }
        __syncthreads();
    }

#pragma unroll
    for (int mi = 0; mi < 4; mi++) {
        const int r0 = wm * 64 + mi * 16 + gid;
#pragma unroll
        for (int ni = 0; ni < 4; ni++) {
            const int col = wn * 32 + ni * 8 + t4 * 2;
            __half2 h0 = __floats2half2_rn(acc[mi][ni][0], acc[mi][ni][1]);
            __half2 h1 = __floats2half2_rn(acc[mi][ni][2], acc[mi][ni][3]);
            *(__half2*)&Cp[(size_t)r0 * ldc + col] = h0;
            *(__half2*)&Cp[(size_t)(r0 + 8) * ldc + col] = h1;
        }
    }
}

// ---------------------------------------------------------------------------
// k softmax over L, fp16 in/out (math fp32)
// ---------------------------------------------------------------------------
__global__ void ksoftmax_kernel(__half* __restrict__ qkvh) {
    int row = blockIdx.x;
    int b = row >> 9;
    int ch = row & (HIDDEN - 1);
    __half2* p = (__half2*)(qkvh + ((size_t)b * QKV_CH + HIDDEN + ch) * L);
    int tid = threadIdx.x;
    float2 v[8];
    float m = -INFINITY;
#pragma unroll
    for (int i = 0; i < 8; i++) {
        v[i] = __half22float2(p[tid + i * 256]);
        m = fmaxf(m, fmaxf(v[i].x, v[i].y));
    }
    __shared__ float red[256];
    red[tid] = m;
    __syncthreads();
    for (int s = 128; s > 0; s >>= 1) {
        if (tid < s) red[tid] = fmaxf(red[tid], red[tid + s]);
        __syncthreads();
    }
    m = red[0];
    __syncthreads();
    float sum = 0.f;
#pragma unroll
    for (int i = 0; i < 8; i++) {
        v[i].x = expf(v[i].x - m);
        v[i].y = expf(v[i].y - m);
        sum += v[i].x + v[i].y;
    }
    red[tid] = sum;
    __syncthreads();
    for (int s = 128; s > 0; s >>= 1) {
        if (tid < s) red[tid] += red[tid + s];
        __syncthreads();
    }
    float inv = 1.f / red[0];
#pragma unroll
    for (int i = 0; i < 8; i++)
        p[tid + i * 256] = __floats2half2_rn(v[i].x * inv, v[i].y * inv);
}

// ---------------------------------------------------------------------------
// ctx partial via HMMA: ctxp[chunk][bh] = k_sm[64, 512chunk] @ v[64, 512chunk]^T
// grid (bh=64, chunk=8), 128 threads (4 warps, warp = 16 d-rows x 64 e-cols).
// 3-stage cp.async, ldmatrix fragments.
// ---------------------------------------------------------------------------
#define CTX_LD 40
#define CTX_TILEB (64 * CTX_LD * 2)   // 5120 bytes

__global__ __launch_bounds__(128) void ctx_part_mma(const __half* __restrict__ qkvh,
                                                    float* __restrict__ ctxp) {
    __shared__ __half csk[3 * 64 * CTX_LD];
    __shared__ __half csv[3 * 64 * CTX_LD];
    uint32_t ska = (uint32_t)__cvta_generic_to_shared(csk);
    uint32_t skv = (uint32_t)__cvta_generic_to_shared(csv);

    int bh = blockIdx.x;
    int chunk = blockIdx.y;
    int b = bh >> 3, h = bh & 7;
    const __half* kp = qkvh + ((size_t)b * QKV_CH + HIDDEN + h * DHEAD) * L;
    const __half* vp = qkvh + ((size_t)b * QKV_CH + 2 * HIDDEN + h * DHEAD) * L;
    const int lbeg = chunk * (L / NCHUNK);   // 512-wide chunk

    const int tid = threadIdx.x;
    const int lane = tid & 31;
    const int warp = tid >> 5;
    const int gid = lane >> 2;
    const int t4 = lane & 3;
    const int t8 = lane >> 3;
    const int r8 = lane & 7;

    auto load_stage = [&](int stage, int kt) {
        int l0 = lbeg + kt * 32;
#pragma unroll
        for (int i = 0; i < 2; i++) {
            int flat = i * 128 + tid;
            int row = flat >> 2, kc = (flat & 3) * 8;
            cp_async16(ska + stage * CTX_TILEB + (row * CTX_LD + kc) * 2,
                       kp + (size_t)row * L + l0 + kc);
            cp_async16(skv + stage * CTX_TILEB + (row * CTX_LD + kc) * 2,
                       vp + (size_t)row * L + l0 + kc);
        }
    };

    float acc[8][4];
#pragma unroll
    for (int ni = 0; ni < 8; ni++)
#pragma unroll
        for (int r = 0; r < 4; r++) acc[ni][r] = 0.f;

    const int ktiles = (L / NCHUNK) >> 5;   // 16
#pragma unroll
    for (int s = 0; s < 2; s++) {
        load_stage(s, s);
        cp_commit();
    }
    cp_wait<1>();
    __syncthreads();

    for (int kt = 0; kt < ktiles; kt++) {
        uint32_t abase = ska + (kt % 3) * CTX_TILEB;
        uint32_t bbase = skv + (kt % 3) * CTX_TILEB;
#pragma unroll
        for (int kk = 0; kk < 2; kk++) {
            const int kbh = kk * 16;
            uint32_t af[4], bf[8][2];
            {
                int row = warp * 16 + r8 + (t8 & 1) * 8;
                int col = kbh + (t8 >> 1) * 8;
                ldsm_x4(af, abase + (row * CTX_LD + col) * 2);
            }
#pragma unroll
            for (int np = 0; np < 4; np++) {
                int row = np * 16 + r8 + (t8 >> 1) * 8;
                int col = kbh + (t8 & 1) * 8;
                uint32_t r4[4];
                ldsm_x4(r4, bbase + (row * CTX_LD + col) * 2);
                bf[np * 2][0] = r4[0]; bf[np * 2][1] = r4[1];
                bf[np * 2 + 1][0] = r4[2]; bf[np * 2 + 1][1] = r4[3];
            }
#pragma unroll
            for (int ni = 0; ni < 8; ni++)
                mma_f16(acc[ni], af, bf[ni]);
        }
        int nt = kt + 2;
        if (nt < ktiles) {
            load_stage(nt % 3, nt);
            cp_commit();
            cp_wait<1>();
        } else {
            cp_wait<0>();
        }
        __syncthreads();
    }

    float* cp = ctxp + ((size_t)chunk * (B * HEADS) + bh) * (DHEAD * DHEAD);
    int d = warp * 16 + gid;
#pragma unroll
    for (int ni = 0; ni < 8; ni++) {
        int col = ni * 8 + t4 * 2;
        *(float2*)&cp[d * DHEAD + col] = make_float2(acc[ni][0], acc[ni][1]);
        *(float2*)&cp[(d + 8) * DHEAD + col] = make_float2(acc[ni][2], acc[ni][3]);
    }
}

__global__ void ctx_reduce_kernel(const float* __restrict__ ctxp,
                                  float* __restrict__ ctx) {
    int i = blockIdx.x * 256 + threadIdx.x;
    float s = 0.f;
#pragma unroll
    for (int c = 0; c < NCHUNK; c++)
        s += ctxp[(size_t)c * (B * HEADS * DHEAD * DHEAD) + i];
    ctx[i] = s;
}

// ---------------------------------------------------------------------------
// q-softmax + ctx apply -> attnT[b][l][e] fp16.  One-pass: accumulate with raw
// exp(q), scale once by ATTN_SCALE/sum at the end (softmax is linear here).
// ---------------------------------------------------------------------------
__global__ __launch_bounds__(128) void attn_apply_kernel(const __half* __restrict__ qkvh,
                                                         const float* __restrict__ ctx,
                                                         __half* __restrict__ attnT) {
    int n0 = blockIdx.x * 128;
    int bh = blockIdx.y;
    int b = bh >> 3, h = bh & 7;

    __shared__ float4 cs[64][16];
    __shared__ float qs_s[64][128];
    const float4* cp4 = reinterpret_cast<const float4*>(ctx + (size_t)bh * DHEAD * DHEAD);
    for (int idx = threadIdx.x; idx < 64 * 16; idx += 128)
        cs[idx >> 4][idx & 15] = cp4[idx];

    const __half* qp = qkvh + ((size_t)b * QKV_CH + h * DHEAD) * L + n0;
    for (int idx = threadIdx.x; idx < 64 * 64; idx += 128) {
        int d = idx >> 6, c2 = (idx & 63) * 2;
        float2 qf = __half22float2(*(const __half2*)&qp[(size_t)d * L + c2]);
        qs_s[d][c2] = qf.x;
        qs_s[d][c2 + 1] = qf.y;
    }
    __syncthreads();

    int t = threadIdx.x;
    float sum = 0.f;
    float4 acc[16];
#pragma unroll
    for (int e = 0; e < 16; e++) acc[e] = make_float4(0.f, 0.f, 0.f, 0.f);

#pragma unroll 4
    for (int d = 0; d < DHEAD; d++) {
        float qv = expf(qs_s[d][t]);
        sum += qv;
#pragma unroll
        for (int e = 0; e < 16; e++) {
            float4 c4 = cs[d][e];
            acc[e].x = fmaf(c4.x, qv, acc[e].x);
            acc[e].y = fmaf(c4.y, qv, acc[e].y);
            acc[e].z = fmaf(c4.z, qv, acc[e].z);
            acc[e].w = fmaf(c4.w, qv, acc[e].w);
        }
    }
    float inv = ATTN_SCALE / sum;

    __half* op = attnT + ((size_t)b * L + n0 + t) * HIDDEN + h * DHEAD;
#pragma unroll
    for (int e = 0; e < 16; e++) {
        __half2 h0 = __floats2half2_rn(acc[e].x * inv, acc[e].y * inv);
        __half2 h1 = __floats2half2_rn(acc[e].z * inv, acc[e].w * inv);
        *(uint2*)&op[e * 4] = make_uint2(*(uint32_t*)&h0, *(uint32_t*)&h1);
    }
}

// ---------------------------------------------------------------------------
// Fused out-GEMM + bias + channel RMSNorm + residual.
// CTA: full M=512 x N=64 (K=512), 512 threads, 16 warps of 32x64.
// 3-stage cp.async; x rows 0..255 prefetched into smem during mainloop.
// ---------------------------------------------------------------------------
#define OA_BYTES (512 * H_LD * 2)        // 40960
#define OB_BYTES (64 * H_LD * 2)         // 5120
#define OSTG_BYTES (OA_BYTES + OB_BYTES) // 46080
#define OSTAGES 3
#define XS_OFF (OSTAGES * OSTG_BYTES)    // 138240
#define XS_LDF 68                        // floats per x smem row (272B, 16B aligned)
#define OUT_SMEM (XS_OFF + 256 * XS_LDF * 4)  // 138240 + 69632 = 207872

__global__ __launch_bounds__(512) void gemm_out_fused(
    const __half* __restrict__ A, const __half* __restrict__ Bb,
    const float* __restrict__ bias, const float* __restrict__ gout,
    const float* __restrict__ x, float* __restrict__ out) {
    __shared__ float colsum[64];
    uint32_t sbase = (uint32_t)__cvta_generic_to_shared(sgm_h);
    float* xs = (float*)((char*)sgm_h + XS_OFF);

    const int tid = threadIdx.x;
    const int lane = tid & 31;
    const int warp = tid >> 5;
    const int gid = lane >> 2;
    const int t4 = lane & 3;
    const int t8 = lane >> 3;
    const int r8 = lane & 7;
    const int bz = blockIdx.y;
    const int l0 = blockIdx.x * 64;

    const __half* Bp = Bb + ((size_t)bz * L + l0) * HIDDEN;

    float acc[2][8][4];
#pragma unroll
    for (int mi = 0; mi < 2; mi++)
#pragma unroll
        for (int ni = 0; ni < 8; ni++)
#pragma unroll
            for (int r = 0; r < 4; r++) acc[mi][ni][r] = 0.f;

    auto load_stage = [&](int kt) {
        uint32_t sA = sbase + (kt % OSTAGES) * OSTG_BYTES;
        uint32_t sB = sA + OA_BYTES;
        int k0 = kt * 32;
#pragma unroll
        for (int i = 0; i < 4; i++) {
            int c = tid + i * 512;
            int row = c >> 2, kc = (c & 3) * 8;
            cp_async16(sA + (row * H_LD + kc) * 2, A + (size_t)row * HIDDEN + k0 + kc);
        }
        if (tid < 256) {
            int row = tid >> 2, kc = (tid & 3) * 8;
            cp_async16(sB + (row * H_LD + kc) * 2, Bp + (size_t)row * HIDDEN + k0 + kc);
        }
    };
    // x prefetch: rows 0..255, chunk c = 256 cp16 ops (threads tid<256)
    auto load_xchunk = [&](int c) {
        if (tid < 256) {
            int flat = c * 256 + tid;
            int row = flat >> 4, seg = flat & 15;
            cp_async16(sbase + XS_OFF + row * (XS_LDF * 4) + seg * 16,
                       x + ((size_t)bz * C + row) * L + l0 + seg * 4);
        }
    };

    const int ktiles = HIDDEN >> 5; // 16
#pragma unroll
    for (int s = 0; s < OSTAGES - 1; s++) {
        load_stage(s);
        load_xchunk(s);
        cp_commit();
    }
    cp_wait<OSTAGES - 2>();
    __syncthreads();

    for (int kt = 0; kt < ktiles; kt++) {
        uint32_t abase = sbase + (kt % OSTAGES) * OSTG_BYTES;
        uint32_t bbase = abase + OA_BYTES;
#pragma unroll
        for (int kk = 0; kk < 2; kk++) {
            const int kbh = kk * 16;
            uint32_t af[2][4], bf[8][2];
#pragma unroll
            for (int mi = 0; mi < 2; mi++) {
                int row = warp * 32 + mi * 16 + r8 + (t8 & 1) * 8;
                int col = kbh + (t8 >> 1) * 8;
                ldsm_x4(af[mi], abase + (row * H_LD + col) * 2);
            }
#pragma unroll
            for (int np = 0; np < 4; np++) {
                int row = np * 16 + r8 + (t8 >> 1) * 8;
                int col = kbh + (t8 & 1) * 8;
                uint32_t r4[4];
                ldsm_x4(r4, bbase + (row * H_LD + col) * 2);
                bf[np * 2][0] = r4[0]; bf[np * 2][1] = r4[1];
                bf[np * 2 + 1][0] = r4[2]; bf[np * 2 + 1][1] = r4[3];
            }
#pragma unroll
            for (int mi = 0; mi < 2; mi++)
#pragma unroll
                for (int ni = 0; ni < 8; ni++)
                    mma_f16(acc[mi][ni], af[mi], bf[ni]);
        }
        int nt = kt + OSTAGES - 1;
        if (nt < ktiles) {
            load_stage(nt);
            load_xchunk(nt);
            cp_commit();
            cp_wait<OSTAGES - 2>();
        } else {
            cp_wait<0>();
        }
        __syncthreads();
    }

    // --- fused epilogue ---
    float bvs[2][2];
#pragma unroll
    for (int mi = 0; mi < 2; mi++) {
        int r0 = warp * 32 + mi * 16 + gid;
        bvs[mi][0] = bias[r0];
        bvs[mi][1] = bias[r0 + 8];
    }
    if (tid < 64) colsum[tid] = 0.f;
    __syncthreads();

#pragma unroll
    for (int ni = 0; ni < 8; ni++) {
#pragma unroll
        for (int c01 = 0; c01 < 2; c01++) {
            float part = 0.f;
#pragma unroll
            for (int mi = 0; mi < 2; mi++) {
                float v0 = acc[mi][ni][c01] + bvs[mi][0];
                float v1 = acc[mi][ni][2 + c01] + bvs[mi][1];
                acc[mi][ni][c01] = v0;
                acc[mi][ni][2 + c01] = v1;
                part += v0 * v0 + v1 * v1;
            }
            part += __shfl_xor_sync(0xFFFFFFFFu, part, 4);
            part += __shfl_xor_sync(0xFFFFFFFFu, part, 8);
            part += __shfl_xor_sync(0xFFFFFFFFu, part, 16);
            if (gid == 0) atomicAdd(&colsum[ni * 8 + t4 * 2 + c01], part);
        }
    }
    __syncthreads();

    float scl[8][2];
#pragma unroll
    for (int ni = 0; ni < 8; ni++) {
        int col = ni * 8 + t4 * 2;
        scl[ni][0] = SQRT_C / fmaxf(sqrtf(colsum[col]), 1e-12f);
        scl[ni][1] = SQRT_C / fmaxf(sqrtf(colsum[col + 1]), 1e-12f);
    }

#pragma unroll
    for (int mi = 0; mi < 2; mi++) {
        int r0 = warp * 32 + mi * 16 + gid;
        float g0 = gout[r0], g1 = gout[r0 + 8];
        const float* xr0;
        const float* xr1;
        if (r0 + 8 < 256) {
            xr0 = xs + r0 * XS_LDF;
            xr1 = xs + (r0 + 8) * XS_LDF;
        } else {
            xr0 = x + ((size_t)bz * C + r0) * L + l0;
            xr1 = x + ((size_t)bz * C + r0 + 8) * L + l0;
        }
        float* or0 = out + ((size_t)bz * C + r0) * L + l0;
        float* or1 = out + ((size_t)bz * C + r0 + 8) * L + l0;
#pragma unroll
        for (int ni = 0; ni < 8; ni++) {
            int col = ni * 8 + t4 * 2;
            float2 xv0 = *(const float2*)&xr0[col];
            float2 xv1 = *(const float2*)&xr1[col];
            float2 v0 = make_float2(acc[mi][ni][0] * scl[ni][0] * g0 + xv0.x,
                                    acc[mi][ni][1] * scl[ni][1] * g0 + xv0.y);
            float2 v1 = make_float2(acc[mi][ni][2] * scl[ni][0] * g1 + xv1.x,
                                    acc[mi][ni][3] * scl[ni][1] * g1 + xv1.y);
            *(float2*)&or0[col] = v0;
            *(float2*)&or1[col] = v1;
        }
    }
}

// ---------------------------------------------------------------------------
extern "C" void kernel_launch(void* const* d_in, const int* in_sizes, int n_in,
                              void* d_out, int out_size) {
    const float* x     = (const float*)d_in[0];
    const float* g_in  = (const float*)d_in[1];
    const float* w_qkv = (const float*)d_in[2];
    const float* w_out = (const float*)d_in[3];
    const float* b_out = (const float*)d_in[4];
    const float* g_out = (const float*)d_in[5];
    float* out = (float*)d_out;

    __half *w2h, *wouth, *xhT, *qkvh, *attnT;
    float *ctxp, *ctx;
    cudaGetSymbolAddress((void**)&w2h, g_w2h);
    cudaGetSymbolAddress((void**)&wouth, g_wouth);
    cudaGetSymbolAddress((void**)&xhT, g_xhT);
    cudaGetSymbolAddress((void**)&qkvh, g_qkvh);
    cudaGetSymbolAddress((void**)&ctxp, g_ctxp);
    cudaGetSymbolAddress((void**)&ctx, g_ctx);
    cudaGetSymbolAddress((void**)&attnT, g_attnT);

    cudaFuncSetAttribute(normxpose_kernel, cudaFuncAttributeMaxDynamicSharedMemorySize,
                         NX_SMEM);
    cudaFuncSetAttribute(gemm_qkv, cudaFuncAttributeMaxDynamicSharedMemorySize,
                         GEMM_SMEM);
    cudaFuncSetAttribute(gemm_out_fused, cudaFuncAttributeMaxDynamicSharedMemorySize,
                         OUT_SMEM);

    // 0. weight conversions
    convert_wqkv_kernel<<<(QKV_CH * C) / 256, 256>>>(w_qkv, g_in, w2h);
    convert_wout_kernel<<<(C * HIDDEN) / 256, 256>>>(w_out, wouth);

    // 1. fused rmsnorm scale + transpose -> xhT fp16
    normxpose_kernel<<<dim3(L / 32, B), 256, NX_SMEM>>>(x, xhT);

    // 2. qkv = w2h @ xn   (fp16 HMMA, 128x128 tiles)
    gemm_qkv<<<dim3(L / 128, QKV_CH / 128, B), 256, GEMM_SMEM>>>(
        w2h, xhT, qkvh, C, L, (size_t)L * C, (size_t)QKV_CH * L);

    // 3. k softmax over L (fp16 in/out)
    ksoftmax_kernel<<<B * HIDDEN, 256>>>(qkvh);

    // 4. context per (b,h) via HMMA, then reduce over 8 chunks
    ctx_part_mma<<<dim3(B * HEADS, NCHUNK), 128>>>(qkvh, ctxp);
    ctx_reduce_kernel<<<(B * HEADS * DHEAD * DHEAD) / 256, 256>>>(ctxp, ctx);

    // 5. attnT fp16 (one-pass softmax apply)
    attn_apply_kernel<<<dim3(L / 128, B * HEADS), 128>>>(qkvh, ctx, attnT);

    // 6. out = rmsnorm(wouth @ attn + b_out)*g_out + x  (fused, x prefetch)
    gemm_out_fused<<<dim3(L / 64, B), 512, OUT_SMEM>>>(
        wouth, attnT, b_out, g_out, x, out);
}

// round 11
// speedup vs baseline: 6.2656x; 1.2823x over previous
#include <cuda_runtime.h>
#include <cuda_fp16.h>
#include <math.h>
#include <stdint.h>

// Problem constants
#define B 8
#define C 512
#define L 4096
#define HEADS 8
#define DHEAD 64
#define HIDDEN 512           // HEADS*DHEAD
#define QKV_CH 1536          // 3*HIDDEN
#define SQRT_C 22.627416998f // sqrt(512)
#define ATTN_SCALE 0.125f    // 64^-0.5
#define NCHUNK 8             // ctx split factor over L
#define BH (B * HEADS)

// Scratch buffers
__device__ __half g_w2h[(size_t)QKV_CH * C];        // w_qkv * g_in, fp16
__device__ __half g_wouth[(size_t)C * HIDDEN];
__device__ __half g_xhT[(size_t)B * L * C];         // (x*s)^T fp16 [b][l][c]
__device__ __half g_qkvh[(size_t)B * QKV_CH * L];   // fp16 [b][ch][l]; k rows hold exp(k)
__device__ __half g_expqT[(size_t)BH * L * DHEAD];  // 32 MB exp(q) [bh][l][d]
__device__ float  g_qsum[(size_t)BH * L];           // per-(bh,l) sum of exp(q) over d
__device__ float  g_ksum[(size_t)B * HIDDEN];       // per-(b,kch) sum of exp(k) over l
__device__ float  g_ctxp[(size_t)NCHUNK * BH * DHEAD * DHEAD];
__device__ __half g_ctxh[(size_t)BH * DHEAD * DHEAD]; // ctx^T/ksum fp16 [bh][e][d]
__device__ __half g_attnT[(size_t)B * L * HIDDEN];  // fp16 [b][l][e]

// ---------------------------------------------------------------------------
// PTX helpers
// ---------------------------------------------------------------------------
__device__ __forceinline__ void cp_async16(uint32_t dst, const void* src) {
    asm volatile("cp.async.cg.shared.global [%0], [%1], 16;" :: "r"(dst), "l"(src));
}
__device__ __forceinline__ void cp_commit() {
    asm volatile("cp.async.commit_group;");
}
template <int N>
__device__ __forceinline__ void cp_wait() {
    asm volatile("cp.async.wait_group %0;" :: "n"(N));
}
__device__ __forceinline__ void ldsm_x4(uint32_t r[4], uint32_t addr) {
    asm volatile("ldmatrix.sync.aligned.m8n8.x4.shared.b16 {%0,%1,%2,%3}, [%4];"
                 : "=r"(r[0]), "=r"(r[1]), "=r"(r[2]), "=r"(r[3]) : "r"(addr));
}
__device__ __forceinline__ void mma_f16(float d[4], const uint32_t a[4],
                                        const uint32_t b[2]) {
    asm volatile(
        "mma.sync.aligned.m16n8k16.row.col.f32.f16.f16.f32 "
        "{%0,%1,%2,%3}, {%4,%5,%6,%7}, {%8,%9}, {%0,%1,%2,%3};"
        : "+f"(d[0]), "+f"(d[1]), "+f"(d[2]), "+f"(d[3])
        : "r"(a[0]), "r"(a[1]), "r"(a[2]), "r"(a[3]),
          "r"(b[0]), "r"(b[1]));
}

// ---------------------------------------------------------------------------
// Weight conversions + ksum zero
// ---------------------------------------------------------------------------
__global__ void convert_wqkv_kernel(const float* __restrict__ w,
                                    const float* __restrict__ g,
                                    __half* __restrict__ w2h) {
    int i = blockIdx.x * 256 + threadIdx.x;
    w2h[i] = __float2half(w[i] * g[i & (C - 1)]);
}
__global__ void convert_wout_kernel(const float* __restrict__ w,
                                    __half* __restrict__ wh) {
    int i = blockIdx.x * 256 + threadIdx.x;
    wh[i] = __float2half(w[i]);
}
__global__ void zero_ksum_kernel(float* __restrict__ ksum) {
    ksum[blockIdx.x * 256 + threadIdx.x] = 0.f;
}

// ---------------------------------------------------------------------------
// Fused rmsnorm-scale + transpose: xhT[b][l][c] = fp16(x[b][c][l] * s[b,l])
// ---------------------------------------------------------------------------
#define NX_SMEM (512 * 33 * 4)
extern __shared__ float nx_sm[];
__global__ __launch_bounds__(256) void normxpose_kernel(const float* __restrict__ x,
                                                        __half* __restrict__ xhT) {
    float* t = nx_sm;               // t[c*33 + l]
    __shared__ float sc[32];
    int b = blockIdx.y;
    int l0 = blockIdx.x * 32;
    int tid = threadIdx.x;
    const float* xp = x + ((size_t)b * C) * L + l0;
#pragma unroll
    for (int i = 0; i < 64; i++) {
        int flat = i * 256 + tid;
        int c = flat >> 5, l = flat & 31;
        t[c * 33 + l] = xp[(size_t)c * L + l];
    }
    __syncthreads();
    int warp = tid >> 5, lane = tid & 31;
#pragma unroll
    for (int li = 0; li < 4; li++) {
        int l = warp * 4 + li;
        float ss = 0.f;
#pragma unroll
        for (int ci = 0; ci < 16; ci++) {
            float v = t[(ci * 32 + lane) * 33 + l];
            ss += v * v;
        }
#pragma unroll
        for (int off = 16; off > 0; off >>= 1)
            ss += __shfl_xor_sync(0xFFFFFFFFu, ss, off);
        if (lane == 0) sc[l] = SQRT_C / fmaxf(sqrtf(ss), 1e-12f);
    }
    __syncthreads();
    __half* op = xhT + ((size_t)b * L + l0) * C;
#pragma unroll
    for (int i = 0; i < 64; i++) {
        int flat = i * 256 + tid;
        int l = flat >> 9, c = flat & 511;
        op[(size_t)l * C + c] = __float2half(t[c * 33 + l] * sc[l]);
    }
}

// ---------------------------------------------------------------------------
// QKV GEMM: 128x128x32, 8 warps (2x4) of 64x32, 3-stage cp.async.
// Region-specialized epilogue (by 0-3: q -> exp -> expqT + qsum;
// by 4-7: k -> exp in place + ksum atomics; by 8-11: v -> plain).
// ---------------------------------------------------------------------------
#define H_LD 40
#define H_TILEB (128 * H_LD * 2)
#define STAGES 3
#define GEMM_SMEM (STAGES * 2 * H_TILEB)

extern __shared__ __half sgm_h[];

__device__ __forceinline__ void qkv_load_tile(uint32_t sa, uint32_t sb, int stage,
                                              const __half* Ap, const __half* Bp,
                                              int k0, int K, int tid) {
#pragma unroll
    for (int i = 0; i < 2; i++) {
        int c = tid + i * 256;
        int row = c >> 2, kc = (c & 3) * 8;
        cp_async16(sa + stage * H_TILEB + (row * H_LD + kc) * 2,
                   Ap + (size_t)row * K + k0 + kc);
    }
#pragma unroll
    for (int i = 0; i < 2; i++) {
        int c = tid + i * 256;
        int row = c >> 2, kc = (c & 3) * 8;
        cp_async16(sb + stage * H_TILEB + (row * H_LD + kc) * 2,
                   Bp + (size_t)row * K + k0 + kc);
    }
}

__global__ __launch_bounds__(256) void gemm_qkv(
    const __half* __restrict__ A, const __half* __restrict__ Bb,
    __half* __restrict__ Cb, __half* __restrict__ expqT,
    float* __restrict__ qsum, float* __restrict__ ksum,
    int K, int ldc, size_t strideB, size_t strideC) {
    uint32_t sa = (uint32_t)__cvta_generic_to_shared(sgm_h);
    uint32_t sb = sa + STAGES * H_TILEB;

    const int tid = threadIdx.x;
    const int lane = tid & 31;
    const int warp = tid >> 5;
    const int gid = lane >> 2;
    const int t4 = lane & 3;
    const int wm = warp >> 2;
    const int wn = warp & 3;
    const int t8 = lane >> 3;
    const int r8 = lane & 7;

    const __half* Ap = A + (size_t)blockIdx.y * 128 * K;
    const __half* Bp = Bb + (size_t)blockIdx.z * strideB + (size_t)blockIdx.x * 128 * K;
    __half* Cp = Cb + (size_t)blockIdx.z * strideC +
                 (size_t)blockIdx.y * 128 * ldc + (size_t)blockIdx.x * 128;

    float acc[4][4][4];
#pragma unroll
    for (int mi = 0; mi < 4; mi++)
#pragma unroll
        for (int ni = 0; ni < 4; ni++)
#pragma unroll
            for (int r = 0; r < 4; r++) acc[mi][ni][r] = 0.f;

    const int ktiles = K >> 5;
#pragma unroll
    for (int s = 0; s < STAGES - 1; s++) {
        qkv_load_tile(sa, sb, s, Ap, Bp, s * 32, K, tid);
        cp_commit();
    }
    cp_wait<STAGES - 2>();
    __syncthreads();

    for (int kt = 0; kt < ktiles; kt++) {
        uint32_t abase = sa + (kt % STAGES) * H_TILEB;
        uint32_t bbase = sb + (kt % STAGES) * H_TILEB;
#pragma unroll
        for (int kk = 0; kk < 2; kk++) {
            const int kbh = kk * 16;
            uint32_t af[4][4], bf[4][2];
#pragma unroll
            for (int mi = 0; mi < 4; mi++) {
                int row = wm * 64 + mi * 16 + r8 + (t8 & 1) * 8;
                int col = kbh + (t8 >> 1) * 8;
                ldsm_x4(af[mi], abase + (row * H_LD + col) * 2);
            }
#pragma unroll
            for (int np = 0; np < 2; np++) {
                int row = wn * 32 + np * 16 + r8 + (t8 >> 1) * 8;
                int col = kbh + (t8 & 1) * 8;
                uint32_t r4[4];
                ldsm_x4(r4, bbase + (row * H_LD + col) * 2);
                bf[np * 2][0] = r4[0]; bf[np * 2][1] = r4[1];
                bf[np * 2 + 1][0] = r4[2]; bf[np * 2 + 1][1] = r4[3];
            }
#pragma unroll
            for (int mi = 0; mi < 4; mi++)
#pragma unroll
                for (int ni = 0; ni < 4; ni++)
                    mma_f16(acc[mi][ni], af[mi], bf[ni]);
        }
        int nt = kt + STAGES - 1;
        if (nt < ktiles) {
            qkv_load_tile(sa, sb, nt % STAGES, Ap, Bp, nt * 32, K, tid);
            cp_commit();
            cp_wait<STAGES - 2>();
        } else {
            cp_wait<0>();
        }
        __syncthreads();
    }

    const int b = blockIdx.z;
    const int l0 = blockIdx.x * 128;
    const int region = blockIdx.y >> 2;

    if (region == 0) {
        // --- q: exp -> expqT[bh][l][d], per-(h,l) sums -> qsum ---
        const int h = (blockIdx.y << 1) + wm;
        __half* qtb = expqT + (((size_t)b * HEADS + h) * L + l0) * DHEAD;
        float cs0[4] = {0.f, 0.f, 0.f, 0.f};
        float cs1[4] = {0.f, 0.f, 0.f, 0.f};
#pragma unroll
        for (int mi = 0; mi < 4; mi++) {
            const int d0 = mi * 16 + gid;
#pragma unroll
            for (int ni = 0; ni < 4; ni++) {
                const int col = wn * 32 + ni * 8 + t4 * 2;
                float e0 = expf(acc[mi][ni][0]);
                float e1 = expf(acc[mi][ni][1]);
                float e2 = expf(acc[mi][ni][2]);
                float e3 = expf(acc[mi][ni][3]);
                __half* q0 = qtb + (size_t)col * DHEAD;
                __half* q1 = q0 + DHEAD;
                q0[d0] = __float2half(e0);
                q0[d0 + 8] = __float2half(e2);
                q1[d0] = __float2half(e1);
                q1[d0 + 8] = __float2half(e3);
                cs0[ni] += e0 + e2;
                cs1[ni] += e1 + e3;
            }
        }
#pragma unroll
        for (int ni = 0; ni < 4; ni++) {
            cs0[ni] += __shfl_xor_sync(0xFFFFFFFFu, cs0[ni], 4);
            cs0[ni] += __shfl_xor_sync(0xFFFFFFFFu, cs0[ni], 8);
            cs0[ni] += __shfl_xor_sync(0xFFFFFFFFu, cs0[ni], 16);
            cs1[ni] += __shfl_xor_sync(0xFFFFFFFFu, cs1[ni], 4);
            cs1[ni] += __shfl_xor_sync(0xFFFFFFFFu, cs1[ni], 8);
            cs1[ni] += __shfl_xor_sync(0xFFFFFFFFu, cs1[ni], 16);
            if (gid == 0) {
                const int col = wn * 32 + ni * 8 + t4 * 2;
                float* qs = qsum + ((size_t)b * HEADS + h) * L + l0 + col;
                qs[0] = cs0[ni];
                qs[1] = cs1[ni];
            }
        }
    } else if (region == 1) {
        // --- k: exp in place + per-row sums (atomic) ---
#pragma unroll
        for (int mi = 0; mi < 4; mi++) {
            const int r0 = wm * 64 + mi * 16 + gid;
            float rs0 = 0.f, rs1 = 0.f;
#pragma unroll
            for (int ni = 0; ni < 4; ni++) {
                const int col = wn * 32 + ni * 8 + t4 * 2;
                float e0 = expf(acc[mi][ni][0]);
                float e1 = expf(acc[mi][ni][1]);
                float e2 = expf(acc[mi][ni][2]);
                float e3 = expf(acc[mi][ni][3]);
                *(__half2*)&Cp[(size_t)r0 * ldc + col] = __floats2half2_rn(e0, e1);
                *(__half2*)&Cp[(size_t)(r0 + 8) * ldc + col] = __floats2half2_rn(e2, e3);
                rs0 += e0 + e1;
                rs1 += e2 + e3;
            }
            rs0 += __shfl_xor_sync(0xFFFFFFFFu, rs0, 1);
            rs0 += __shfl_xor_sync(0xFFFFFFFFu, rs0, 2);
            rs1 += __shfl_xor_sync(0xFFFFFFFFu, rs1, 1);
            rs1 += __shfl_xor_sync(0xFFFFFFFFu, rs1, 2);
            if (t4 == 0) {
                const int ch = (blockIdx.y - 4) * 128 + r0;
                atomicAdd(&ksum[(size_t)b * HIDDEN + ch], rs0);
                atomicAdd(&ksum[(size_t)b * HIDDEN + ch + 8], rs1);
            }
        }
    } else {
        // --- v: plain fp16 store ---
#pragma unroll
        for (int mi = 0; mi < 4; mi++) {
            const int r0 = wm * 64 + mi * 16 + gid;
#pragma unroll
            for (int ni = 0; ni < 4; ni++) {
                const int col = wn * 32 + ni * 8 + t4 * 2;
                *(__half2*)&Cp[(size_t)r0 * ldc + col] =
                    __floats2half2_rn(acc[mi][ni][0], acc[mi][ni][1]);
                *(__half2*)&Cp[(size_t)(r0 + 8) * ldc + col] =
                    __floats2half2_rn(acc[mi][ni][2], acc[mi][ni][3]);
            }
        }
    }
}

// ---------------------------------------------------------------------------
// ctx partial via HMMA: ctxp[chunk][bh] = expk[64, 512chunk] @ v[64, 512chunk]^T
// ---------------------------------------------------------------------------
#define CTX_LD 40
#define CTX_TILEB (64 * CTX_LD * 2)

__global__ __launch_bounds__(128) void ctx_part_mma(const __half* __restrict__ qkvh,
                                                    float* __restrict__ ctxp) {
    __shared__ __half csk[3 * 64 * CTX_LD];
    __shared__ __half csv[3 * 64 * CTX_LD];
    uint32_t ska = (uint32_t)__cvta_generic_to_shared(csk);
    uint32_t skv = (uint32_t)__cvta_generic_to_shared(csv);

    int bh = blockIdx.x;
    int chunk = blockIdx.y;
    int b = bh >> 3, h = bh & 7;
    const __half* kp = qkvh + ((size_t)b * QKV_CH + HIDDEN + h * DHEAD) * L;
    const __half* vp = qkvh + ((size_t)b * QKV_CH + 2 * HIDDEN + h * DHEAD) * L;
    const int lbeg = chunk * (L / NCHUNK);

    const int tid = threadIdx.x;
    const int lane = tid & 31;
    const int warp = tid >> 5;
    const int gid = lane >> 2;
    const int t4 = lane & 3;
    const int t8 = lane >> 3;
    const int r8 = lane & 7;

    auto load_stage = [&](int stage, int kt) {
        int l0 = lbeg + kt * 32;
#pragma unroll
        for (int i = 0; i < 2; i++) {
            int flat = i * 128 + tid;
            int row = flat >> 2, kc = (flat & 3) * 8;
            cp_async16(ska + stage * CTX_TILEB + (row * CTX_LD + kc) * 2,
                       kp + (size_t)row * L + l0 + kc);
            cp_async16(skv + stage * CTX_TILEB + (row * CTX_LD + kc) * 2,
                       vp + (size_t)row * L + l0 + kc);
        }
    };

    float acc[8][4];
#pragma unroll
    for (int ni = 0; ni < 8; ni++)
#pragma unroll
        for (int r = 0; r < 4; r++) acc[ni][r] = 0.f;

    const int ktiles = (L / NCHUNK) >> 5;
#pragma unroll
    for (int s = 0; s < 2; s++) {
        load_stage(s, s);
        cp_commit();
    }
    cp_wait<1>();
    __syncthreads();

    for (int kt = 0; kt < ktiles; kt++) {
        uint32_t abase = ska + (kt % 3) * CTX_TILEB;
        uint32_t bbase = skv + (kt % 3) * CTX_TILEB;
#pragma unroll
        for (int kk = 0; kk < 2; kk++) {
            const int kbh = kk * 16;
            uint32_t af[4], bf[8][2];
            {
                int row = warp * 16 + r8 + (t8 & 1) * 8;
                int col = kbh + (t8 >> 1) * 8;
                ldsm_x4(af, abase + (row * CTX_LD + col) * 2);
            }
#pragma unroll
            for (int np = 0; np < 4; np++) {
                int row = np * 16 + r8 + (t8 >> 1) * 8;
                int col = kbh + (t8 & 1) * 8;
                uint32_t r4[4];
                ldsm_x4(r4, bbase + (row * CTX_LD + col) * 2);
                bf[np * 2][0] = r4[0]; bf[np * 2][1] = r4[1];
                bf[np * 2 + 1][0] = r4[2]; bf[np * 2 + 1][1] = r4[3];
            }
#pragma unroll
            for (int ni = 0; ni < 8; ni++)
                mma_f16(acc[ni], af, bf[ni]);
        }
        int nt = kt + 2;
        if (nt < ktiles) {
            load_stage(nt % 3, nt);
            cp_commit();
            cp_wait<1>();
        } else {
            cp_wait<0>();
        }
        __syncthreads();
    }

    float* cp = ctxp + ((size_t)chunk * BH + bh) * (DHEAD * DHEAD);
    int d = warp * 16 + gid;
#pragma unroll
    for (int ni = 0; ni < 8; ni++) {
        int col = ni * 8 + t4 * 2;
        *(float2*)&cp[d * DHEAD + col] = make_float2(acc[ni][0], acc[ni][1]);
        *(float2*)&cp[(d + 8) * DHEAD + col] = make_float2(acc[ni][2], acc[ni][3]);
    }
}

// ---------------------------------------------------------------------------
// Reduce chunks + divide by ksum, emit ctxh fp16 transposed [bh][e][d]
// ---------------------------------------------------------------------------
__global__ void ctx_reduce_kernel(const float* __restrict__ ctxp,
                                  const float* __restrict__ ksum,
                                  __half* __restrict__ ctxh) {
    int i = blockIdx.x * 256 + threadIdx.x; // over BH*4096
    int bh = i >> 12;
    int rem = i & 4095;
    int d = rem >> 6, e = rem & 63;
    float s = 0.f;
#pragma unroll
    for (int c = 0; c < NCHUNK; c++)
        s += ctxp[(size_t)c * (BH * DHEAD * DHEAD) + i];
    int b = bh >> 3, h = bh & 7;
    float kv = ksum[(size_t)b * HIDDEN + h * DHEAD + d];
    ctxh[((size_t)bh << 12) + e * DHEAD + d] = __float2half(s / kv);
}

// ---------------------------------------------------------------------------
// attn via HMMA: attnT[l][h*64+e] = (scale/qsum[l]) * sum_d expq[l][d]*ctxh[e][d]
// CTA: 128 l x 64 e, K=64. 4 warps (2x2) of 64x32. Single-shot staging.
// ---------------------------------------------------------------------------
#define AQ_LD 72
__global__ __launch_bounds__(128) void attn_mma(const __half* __restrict__ expqT,
                                                const float* __restrict__ qsum,
                                                const __half* __restrict__ ctxh,
                                                __half* __restrict__ attnT) {
    __shared__ __half As[128 * AQ_LD];
    __shared__ __half Bs[64 * AQ_LD];
    uint32_t sa = (uint32_t)__cvta_generic_to_shared(As);
    uint32_t sb = (uint32_t)__cvta_generic_to_shared(Bs);

    const int l0 = blockIdx.x * 128;
    const int bh = blockIdx.y;
    const int b = bh >> 3, h = bh & 7;

    const int tid = threadIdx.x;
    const int lane = tid & 31;
    const int warp = tid >> 5;
    const int gid = lane >> 2;
    const int t4 = lane & 3;
    const int t8 = lane >> 3;
    const int r8 = lane & 7;
    const int wm = warp >> 1;  // 0..1
    const int wn = warp & 1;   // 0..1

    const __half* qp = expqT + ((size_t)bh * L + l0) * DHEAD;
    const __half* cp = ctxh + ((size_t)bh << 12);

    // stage A: 128 rows x 64 halfs (8 segs of 8)
#pragma unroll
    for (int i = 0; i < 8; i++) {
        int flat = i * 128 + tid;
        int row = flat >> 3, seg = flat & 7;
        cp_async16(sa + (row * AQ_LD + seg * 8) * 2, qp + (size_t)row * DHEAD + seg * 8);
    }
    // stage B: 64 rows x 64 halfs
#pragma unroll
    for (int i = 0; i < 4; i++) {
        int flat = i * 128 + tid;
        int row = flat >> 3, seg = flat & 7;
        cp_async16(sb + (row * AQ_LD + seg * 8) * 2, cp + (size_t)row * DHEAD + seg * 8);
    }
    cp_commit();
    cp_wait<0>();
    __syncthreads();

    float acc[4][4][4];
#pragma unroll
    for (int mi = 0; mi < 4; mi++)
#pragma unroll
        for (int ni = 0; ni < 4; ni++)
#pragma unroll
            for (int r = 0; r < 4; r++) acc[mi][ni][r] = 0.f;

#pragma unroll
    for (int kt = 0; kt < 4; kt++) {
        const int kbh = kt * 16;
        uint32_t af[4][4], bf[4][2];
#pragma unroll
        for (int mi = 0; mi < 4; mi++) {
            int row = wm * 64 + mi * 16 + r8 + (t8 & 1) * 8;
            int col = kbh + (t8 >> 1) * 8;
            ldsm_x4(af[mi], sa + (row * AQ_LD + col) * 2);
        }
#pragma unroll
        for (int np = 0; np < 2; np++) {
            int row = wn * 32 + np * 16 + r8 + (t8 >> 1) * 8;
            int col = kbh + (t8 & 1) * 8;
            uint32_t r4[4];
            ldsm_x4(r4, sb + (row * AQ_LD + col) * 2);
            bf[np * 2][0] = r4[0]; bf[np * 2][1] = r4[1];
            bf[np * 2 + 1][0] = r4[2]; bf[np * 2 + 1][1] = r4[3];
        }
#pragma unroll
        for (int mi = 0; mi < 4; mi++)
#pragma unroll
            for (int ni = 0; ni < 4; ni++)
                mma_f16(acc[mi][ni], af[mi], bf[ni]);
    }

    const float* qs = qsum + (size_t)bh * L + l0;
#pragma unroll
    for (int mi = 0; mi < 4; mi++) {
        const int r0 = wm * 64 + mi * 16 + gid;
        const float inv0 = ATTN_SCALE / qs[r0];
        const float inv1 = ATTN_SCALE / qs[r0 + 8];
        __half* o0 = attnT + ((size_t)b * L + l0 + r0) * HIDDEN + h * DHEAD;
        __half* o1 = attnT + ((size_t)b * L + l0 + r0 + 8) * HIDDEN + h * DHEAD;
#pragma unroll
        for (int ni = 0; ni < 4; ni++) {
            const int col = wn * 32 + ni * 8 + t4 * 2;
            *(__half2*)&o0[col] = __floats2half2_rn(acc[mi][ni][0] * inv0,
                                                    acc[mi][ni][1] * inv0);
            *(__half2*)&o1[col] = __floats2half2_rn(acc[mi][ni][2] * inv1,
                                                    acc[mi][ni][3] * inv1);
        }
    }
}

// ---------------------------------------------------------------------------
// Fused out-GEMM + bias + channel RMSNorm + residual (unchanged from R10).
// ---------------------------------------------------------------------------
#define OA_BYTES (512 * H_LD * 2)
#define OB_BYTES (64 * H_LD * 2)
#define OSTG_BYTES (OA_BYTES + OB_BYTES)
#define OSTAGES 3
#define XS_OFF (OSTAGES * OSTG_BYTES)
#define XS_LDF 68
#define OUT_SMEM (XS_OFF + 256 * XS_LDF * 4)

__global__ __launch_bounds__(512) void gemm_out_fused(
    const __half* __restrict__ A, const __half* __restrict__ Bb,
    const float* __restrict__ bias, const float* __restrict__ gout,
    const float* __restrict__ x, float* __restrict__ out) {
    __shared__ float colsum[64];
    uint32_t sbase = (uint32_t)__cvta_generic_to_shared(sgm_h);
    float* xs = (float*)((char*)sgm_h + XS_OFF);

    const int tid = threadIdx.x;
    const int lane = tid & 31;
    const int warp = tid >> 5;
    const int gid = lane >> 2;
    const int t4 = lane & 3;
    const int t8 = lane >> 3;
    const int r8 = lane & 7;
    const int bz = blockIdx.y;
    const int l0 = blockIdx.x * 64;

    const __half* Bp = Bb + ((size_t)bz * L + l0) * HIDDEN;

    float acc[2][8][4];
#pragma unroll
    for (int mi = 0; mi < 2; mi++)
#pragma unroll
        for (int ni = 0; ni < 8; ni++)
#pragma unroll
            for (int r = 0; r < 4; r++) acc[mi][ni][r] = 0.f;

    auto load_stage = [&](int kt) {
        uint32_t sA = sbase + (kt % OSTAGES) * OSTG_BYTES;
        uint32_t sB = sA + OA_BYTES;
        int k0 = kt * 32;
#pragma unroll
        for (int i = 0; i < 4; i++) {
            int c = tid + i * 512;
            int row = c >> 2, kc = (c & 3) * 8;
            cp_async16(sA + (row * H_LD + kc) * 2, A + (size_t)row * HIDDEN + k0 + kc);
        }
        if (tid < 256) {
            int row = tid >> 2, kc = (tid & 3) * 8;
            cp_async16(sB + (row * H_LD + kc) * 2, Bp + (size_t)row * HIDDEN + k0 + kc);
        }
    };
    auto load_xchunk = [&](int c) {
        if (tid < 256) {
            int flat = c * 256 + tid;
            int row = flat >> 4, seg = flat & 15;
            cp_async16(sbase + XS_OFF + row * (XS_LDF * 4) + seg * 16,
                       x + ((size_t)bz * C + row) * L + l0 + seg * 4);
        }
    };

    const int ktiles = HIDDEN >> 5;
#pragma unroll
    for (int s = 0; s < OSTAGES - 1; s++) {
        load_stage(s);
        load_xchunk(s);
        cp_commit();
    }
    cp_wait<OSTAGES - 2>();
    __syncthreads();

    for (int kt = 0; kt < ktiles; kt++) {
        uint32_t abase = sbase + (kt % OSTAGES) * OSTG_BYTES;
        uint32_t bbase = abase + OA_BYTES;
#pragma unroll
        for (int kk = 0; kk < 2; kk++) {
            const int kbh = kk * 16;
            uint32_t af[2][4], bf[8][2];
#pragma unroll
            for (int mi = 0; mi < 2; mi++) {
                int row = warp * 32 + mi * 16 + r8 + (t8 & 1) * 8;
                int col = kbh + (t8 >> 1) * 8;
                ldsm_x4(af[mi], abase + (row * H_LD + col) * 2);
            }
#pragma unroll
            for (int np = 0; np < 4; np++) {
                int row = np * 16 + r8 + (t8 >> 1) * 8;
                int col = kbh + (t8 & 1) * 8;
                uint32_t r4[4];
                ldsm_x4(r4, bbase + (row * H_LD + col) * 2);
                bf[np * 2][0] = r4[0]; bf[np * 2][1] = r4[1];
                bf[np * 2 + 1][0] = r4[2]; bf[np * 2 + 1][1] = r4[3];
            }
#pragma unroll
            for (int mi = 0; mi < 2; mi++)
#pragma unroll
                for (int ni = 0; ni < 8; ni++)
                    mma_f16(acc[mi][ni], af[mi], bf[ni]);
        }
        int nt = kt + OSTAGES - 1;
        if (nt < ktiles) {
            load_stage(nt);
            load_xchunk(nt);
            cp_commit();
            cp_wait<OSTAGES - 2>();
        } else {
            cp_wait<0>();
        }
        __syncthreads();
    }

    float bvs[2][2];
#pragma unroll
    for (int mi = 0; mi < 2; mi++) {
        int r0 = warp * 32 + mi * 16 + gid;
        bvs[mi][0] = bias[r0];
        bvs[mi][1] = bias[r0 + 8];
    }
    if (tid < 64) colsum[tid] = 0.f;
    __syncthreads();

#pragma unroll
    for (int ni = 0; ni < 8; ni++) {
#pragma unroll
        for (int c01 = 0; c01 < 2; c01++) {
            float part = 0.f;
#pragma unroll
            for (int mi = 0; mi < 2; mi++) {
                float v0 = acc[mi][ni][c01] + bvs[mi][0];
                float v1 = acc[mi][ni][2 + c01] + bvs[mi][1];
                acc[mi][ni][c01] = v0;
                acc[mi][ni][2 + c01] = v1;
                part += v0 * v0 + v1 * v1;
            }
            part += __shfl_xor_sync(0xFFFFFFFFu, part, 4);
            part += __shfl_xor_sync(0xFFFFFFFFu, part, 8);
            part += __shfl_xor_sync(0xFFFFFFFFu, part, 16);
            if (gid == 0) atomicAdd(&colsum[ni * 8 + t4 * 2 + c01], part);
        }
    }
    __syncthreads();

    float scl[8][2];
#pragma unroll
    for (int ni = 0; ni < 8; ni++) {
        int col = ni * 8 + t4 * 2;
        scl[ni][0] = SQRT_C / fmaxf(sqrtf(colsum[col]), 1e-12f);
        scl[ni][1] = SQRT_C / fmaxf(sqrtf(colsum[col + 1]), 1e-12f);
    }

#pragma unroll
    for (int mi = 0; mi < 2; mi++) {
        int r0 = warp * 32 + mi * 16 + gid;
        float g0 = gout[r0], g1 = gout[r0 + 8];
        const float* xr0;
        const float* xr1;
        if (r0 + 8 < 256) {
            xr0 = xs + r0 * XS_LDF;
            xr1 = xs + (r0 + 8) * XS_LDF;
        } else {
            xr0 = x + ((size_t)bz * C + r0) * L + l0;
            xr1 = x + ((size_t)bz * C + r0 + 8) * L + l0;
        }
        float* or0 = out + ((size_t)bz * C + r0) * L + l0;
        float* or1 = out + ((size_t)bz * C + r0 + 8) * L + l0;
#pragma unroll
        for (int ni = 0; ni < 8; ni++) {
            int col = ni * 8 + t4 * 2;
            float2 xv0 = *(const float2*)&xr0[col];
            float2 xv1 = *(const float2*)&xr1[col];
            float2 v0 = make_float2(acc[mi][ni][0] * scl[ni][0] * g0 + xv0.x,
                                    acc[mi][ni][1] * scl[ni][1] * g0 + xv0.y);
            float2 v1 = make_float2(acc[mi][ni][2] * scl[ni][0] * g1 + xv1.x,
                                    acc[mi][ni][3] * scl[ni][1] * g1 + xv1.y);
            *(float2*)&or0[col] = v0;
            *(float2*)&or1[col] = v1;
        }
    }
}

// ---------------------------------------------------------------------------
extern "C" void kernel_launch(void* const* d_in, const int* in_sizes, int n_in,
                              void* d_out, int out_size) {
    const float* x     = (const float*)d_in[0];
    const float* g_in  = (const float*)d_in[1];
    const float* w_qkv = (const float*)d_in[2];
    const float* w_out = (const float*)d_in[3];
    const float* b_out = (const float*)d_in[4];
    const float* g_out = (const float*)d_in[5];
    float* out = (float*)d_out;

    __half *w2h, *wouth, *xhT, *qkvh, *expqT, *ctxh, *attnT;
    float *qsum, *ksum, *ctxp;
    cudaGetSymbolAddress((void**)&w2h, g_w2h);
    cudaGetSymbolAddress((void**)&wouth, g_wouth);
    cudaGetSymbolAddress((void**)&xhT, g_xhT);
    cudaGetSymbolAddress((void**)&qkvh, g_qkvh);
    cudaGetSymbolAddress((void**)&expqT, g_expqT);
    cudaGetSymbolAddress((void**)&qsum, g_qsum);
    cudaGetSymbolAddress((void**)&ksum, g_ksum);
    cudaGetSymbolAddress((void**)&ctxp, g_ctxp);
    cudaGetSymbolAddress((void**)&ctxh, g_ctxh);
    cudaGetSymbolAddress((void**)&attnT, g_attnT);

    cudaFuncSetAttribute(normxpose_kernel, cudaFuncAttributeMaxDynamicSharedMemorySize,
                         NX_SMEM);
    cudaFuncSetAttribute(gemm_qkv, cudaFuncAttributeMaxDynamicSharedMemorySize,
                         GEMM_SMEM);
    cudaFuncSetAttribute(gemm_out_fused, cudaFuncAttributeMaxDynamicSharedMemorySize,
                         OUT_SMEM);

    // 0. weight conversions + ksum zero
    convert_wqkv_kernel<<<(QKV_CH * C) / 256, 256>>>(w_qkv, g_in, w2h);
    convert_wout_kernel<<<(C * HIDDEN) / 256, 256>>>(w_out, wouth);
    zero_ksum_kernel<<<(B * HIDDEN) / 256, 256>>>(ksum);

    // 1. fused rmsnorm scale + transpose -> xhT fp16
    normxpose_kernel<<<dim3(L / 32, B), 256, NX_SMEM>>>(x, xhT);

    // 2. qkv GEMM with fused exp epilogues (q->expqT+qsum, k->exp+ksum, v plain)
    gemm_qkv<<<dim3(L / 128, QKV_CH / 128, B), 256, GEMM_SMEM>>>(
        w2h, xhT, qkvh, expqT, qsum, ksum, C, L,
        (size_t)L * C, (size_t)QKV_CH * L);

    // 3. context partials via HMMA (reads exp'd k), reduce + /ksum -> ctxh
    ctx_part_mma<<<dim3(BH, NCHUNK), 128>>>(qkvh, ctxp);
    ctx_reduce_kernel<<<(BH * DHEAD * DHEAD) / 256, 256>>>(ctxp, ksum, ctxh);

    // 4. attn via HMMA -> attnT
    attn_mma<<<dim3(L / 128, BH), 128>>>(expqT, qsum, ctxh, attnT);

    // 5. out = rmsnorm(wouth @ attn + b_out)*g_out + x
    gemm_out_fused<<<dim3(L / 64, B), 512, OUT_SMEM>>>(
        wouth, attnT, b_out, g_out, x, out);
}